// round 6
// baseline (speedup 1.0000x reference)
#include <cuda_runtime.h>
#include <cuda_bf16.h>
#include <cstdint>

#define B_  4
#define C_  2304
#define N_  2304
#define E_  2304
#define HW  48
#define PW  50
#define NH_ 4
#define K2  20736
#define E2  4608

// GEMM tiling: CTA 256x128x32, 8 warps, warp tile 64x64
#define BM 256
#define BN 128
#define BK 32
#define TSA 80                       // padded A row bytes (32 bf16 = 64B data)
#define A_TILE (BM * TSA)            // 20480
#define B_TILE (BN * TSA)            // 10240
#define OFF_AL A_TILE
#define OFF_BH (2 * A_TILE)
#define OFF_BL (2 * A_TILE + B_TILE)
#define STAGE_BYTES (2 * A_TILE + 2 * B_TILE)   // 61440
#define NSTAGE 3
#define DSMEM_REQ (NSTAGE * STAGE_BYTES)        // 184320

// ---------------- PTX helpers ----------------
__device__ __forceinline__ uint32_t smem_u32(const void* p) {
    uint32_t a;
    asm("{ .reg .u64 t; cvta.to.shared.u64 t, %1; cvt.u32.u64 %0, t; }" : "=r"(a) : "l"(p));
    return a;
}
__device__ __forceinline__ void cp16(uint32_t dst, const void* src) {
    asm volatile("cp.async.cg.shared.global [%0], [%1], 16;" :: "r"(dst), "l"(src));
}
__device__ __forceinline__ void cp_commit() { asm volatile("cp.async.commit_group;"); }
template<int NN>
__device__ __forceinline__ void cp_wait() { asm volatile("cp.async.wait_group %0;" :: "n"(NN)); }

__device__ __forceinline__ void ldm4(uint32_t& r0, uint32_t& r1, uint32_t& r2, uint32_t& r3, uint32_t a) {
    asm volatile("ldmatrix.sync.aligned.m8n8.x4.shared.b16 {%0,%1,%2,%3}, [%4];"
                 : "=r"(r0), "=r"(r1), "=r"(r2), "=r"(r3) : "r"(a));
}
__device__ __forceinline__ void mma16816(float* d, uint32_t a0, uint32_t a1, uint32_t a2, uint32_t a3,
                                         uint32_t b0, uint32_t b1) {
    asm volatile("mma.sync.aligned.m16n8k16.row.col.f32.bf16.bf16.f32 "
                 "{%0,%1,%2,%3}, {%4,%5,%6,%7}, {%8,%9}, {%0,%1,%2,%3};"
                 : "+f"(d[0]), "+f"(d[1]), "+f"(d[2]), "+f"(d[3])
                 : "r"(a0), "r"(a1), "r"(a2), "r"(a3), "r"(b0), "r"(b1));
}

__device__ __forceinline__ void split1(float v, __nv_bfloat16& h, __nv_bfloat16& l) {
    h = __float2bfloat16(v);
    l = __float2bfloat16(v - __bfloat162float(h));
}
__device__ __forceinline__ uint32_t pk2(__nv_bfloat16 a, __nv_bfloat16 b) {
    __nv_bfloat162 t(a, b);
    return *reinterpret_cast<uint32_t*>(&t);
}

// ---------------- scratch arenas ----------------
constexpr size_t SZ_EN = (size_t)B_ * E_ * N_;
constexpr size_t SZ_W  = (size_t)E_ * E_;
constexpr size_t F_HP = 0, F_DOWN = 23040000;
constexpr size_t F_QK = F_DOWN + SZ_EN, F_AO = F_QK + SZ_EN, F_H1 = F_AO + SZ_EN;
constexpr size_t F_FF = F_H1 + SZ_EN;
constexpr size_t F_TOT = F_FF + SZ_EN;

constexpr size_t H_IMH = 0, H_IML = H_IMH + (size_t)B_ * N_ * K2;
constexpr size_t H_W2H = H_IML + (size_t)B_ * N_ * K2, H_W2L = H_W2H + (size_t)C_ * K2;
constexpr size_t H_QWH = H_W2L + (size_t)C_ * K2, H_QWL = H_QWH + SZ_W;
constexpr size_t H_KWH = H_QWL + SZ_W, H_KWL = H_KWH + SZ_W;
constexpr size_t H_VWH = H_KWL + SZ_W, H_VWL = H_VWH + SZ_W;
constexpr size_t H_W1TH = H_VWL + SZ_W, H_W1TL = H_W1TH + 2 * SZ_W;
constexpr size_t H_W2TH = H_W1TL + 2 * SZ_W, H_W2TL = H_W2TH + 2 * SZ_W;
constexpr size_t H_DTH = H_W2TL + 2 * SZ_W, H_DTL = H_DTH + SZ_EN;
constexpr size_t H_VTH = H_DTL + SZ_EN, H_VTL = H_VTH + SZ_EN;
constexpr size_t H_QH = H_VTL + SZ_EN, H_QL = H_QH + SZ_EN;
constexpr size_t H_KH = H_QL + SZ_EN, H_KL = H_KH + SZ_EN;
constexpr size_t H_ATH = H_KL + SZ_EN, H_ATL = H_ATH + SZ_EN;
constexpr size_t H_H1H = H_ATL + SZ_EN, H_H1L = H_H1H + SZ_EN;
constexpr size_t H_MIDH = H_H1L + SZ_EN, H_MIDL = H_MIDH + 2 * SZ_EN;
constexpr size_t H_TOT = H_MIDL + 2 * SZ_EN;

__device__ __align__(256) float         g_f32[F_TOT];
__device__ __align__(256) __nv_bfloat16 g_b16[H_TOT];

// ---------------- mma.sync GEMM: D[m][n] = sum_k A[m,k]*B[n,k] (3xbf16 split) ----------------
// EPI: 0 none, 1 +b1[row], 2 +b1[col]+relu, 3 +b1[col], 4 conv(+b1[r]+b2[r]+b3[r]*b4[z*N_+n], relu)
// OUTB: 0 -> fp32 C; 1 -> bf16 split pair (Oh, Ol)
template<int EPI, int OUTB>
__global__ void __launch_bounds__(256, 1) mm_gemm(
    const __nv_bfloat16* __restrict__ Ah, const __nv_bfloat16* __restrict__ Al,
    const __nv_bfloat16* __restrict__ Bh, const __nv_bfloat16* __restrict__ Bl,
    float* __restrict__ C,
    __nv_bfloat16* __restrict__ Oh, __nv_bfloat16* __restrict__ Ol,
    const float* __restrict__ b1, const float* __restrict__ b2,
    const float* __restrict__ b3, const float* __restrict__ b4,
    int M, int N, int K, int tilesM, int tilesN,
    long long sA, long long sB, long long sC)
{
    extern __shared__ char smem[];
    const uint32_t sb = smem_u32(smem);
    const int tid = threadIdx.x;
    const int wid = tid >> 5, lane = tid & 31;
    const int wm = wid >> 1, wn = wid & 1;          // warp grid 4 (m) x 2 (n)
    const int z = blockIdx.z;

    // GROUP_M raster for L2 reuse
    int bid = blockIdx.x;
    const int GROUP = 8;
    int npg = GROUP * tilesN;
    int grp = bid / npg, rem = bid - grp * npg;
    int gs = tilesM - grp * GROUP; if (gs > GROUP) gs = GROUP;
    int mt = grp * GROUP + rem % gs;
    int nt = rem / gs;
    const int row0 = mt * BM, col0 = nt * BN;

    Ah += (size_t)z * sA; Al += (size_t)z * sA;
    Bh += (size_t)z * sB; Bl += (size_t)z * sB;

    // cp.async mapping: A: thread t -> row t, 4x16B; B: row t>>1, 2x16B at (t&1)*32
    const int arow = tid;
    const int brow = tid >> 1;
    const int bbyte = (tid & 1) * 32;

    auto prefetch = [&](int slab, int st) {
        const int k0 = slab * BK;
        const uint32_t base = sb + st * STAGE_BYTES;
        const char* sAh = (const char*)(Ah + (size_t)(row0 + arow) * K + k0);
        const char* sAl = (const char*)(Al + (size_t)(row0 + arow) * K + k0);
        const uint32_t da = base + (uint32_t)arow * TSA;
        #pragma unroll
        for (int i = 0; i < 4; i++) {
            cp16(da + i * 16, sAh + i * 16);
            cp16(da + OFF_AL + i * 16, sAl + i * 16);
        }
        const char* sBh = (const char*)(Bh + (size_t)(col0 + brow) * K + k0) + bbyte;
        const char* sBl = (const char*)(Bl + (size_t)(col0 + brow) * K + k0) + bbyte;
        const uint32_t db = base + OFF_BH + (uint32_t)brow * TSA + bbyte;
        cp16(db, sBh);      cp16(db + 16, sBh + 16);
        cp16(db + B_TILE, sBl); cp16(db + B_TILE + 16, sBl + 16);
        cp_commit();
    };

    float acc[4][8][4];
    #pragma unroll
    for (int a = 0; a < 4; a++)
        #pragma unroll
        for (int b = 0; b < 8; b++)
            #pragma unroll
            for (int c = 0; c < 4; c++) acc[a][b][c] = 0.f;

    const int S = K / BK;
    prefetch(0, 0);
    prefetch(1, 1);
    cp_wait<1>();
    __syncthreads();

    const uint32_t a_row = (uint32_t)(wm * 64 + (lane & 15));
    const uint32_t a_kh  = (uint32_t)(lane >> 4) * 16;
    const uint32_t b_row = (uint32_t)(wn * 64 + (lane & 7) + ((lane >> 4) & 1) * 8);
    const uint32_t b_kh  = (uint32_t)((lane >> 3) & 1) * 16;

    for (int i = 0; i < S; i++) {
        const uint32_t st = sb + (i % NSTAGE) * STAGE_BYTES;
        const uint32_t aH = st + a_row * TSA + a_kh;
        const uint32_t bH = st + OFF_BH + b_row * TSA + b_kh;

        #pragma unroll
        for (int ks = 0; ks < 2; ks++) {
            const uint32_t ko = ks * 32;
            uint32_t ah[4][4], al[4][4], bh[4][4], bl[4][4];
            #pragma unroll
            for (int mf = 0; mf < 4; mf++) {
                uint32_t adr = aH + ko + (uint32_t)mf * 16 * TSA;
                ldm4(ah[mf][0], ah[mf][1], ah[mf][2], ah[mf][3], adr);
                ldm4(al[mf][0], al[mf][1], al[mf][2], al[mf][3], adr + OFF_AL);
            }
            #pragma unroll
            for (int p = 0; p < 4; p++) {
                uint32_t adr = bH + ko + (uint32_t)p * 16 * TSA;
                ldm4(bh[p][0], bh[p][1], bh[p][2], bh[p][3], adr);
                ldm4(bl[p][0], bl[p][1], bl[p][2], bl[p][3], adr + B_TILE);
            }
            #pragma unroll
            for (int mf = 0; mf < 4; mf++)
                #pragma unroll
                for (int nf = 0; nf < 8; nf++) {
                    const int p = nf >> 1, q = (nf & 1) * 2;
                    uint32_t h0 = bh[p][q], h1 = bh[p][q + 1];
                    uint32_t l0 = bl[p][q], l1 = bl[p][q + 1];
                    mma16816(acc[mf][nf], ah[mf][0], ah[mf][1], ah[mf][2], ah[mf][3], h0, h1);
                    mma16816(acc[mf][nf], ah[mf][0], ah[mf][1], ah[mf][2], ah[mf][3], l0, l1);
                    mma16816(acc[mf][nf], al[mf][0], al[mf][1], al[mf][2], al[mf][3], h0, h1);
                }
        }
        if (i + 2 < S) prefetch(i + 2, (i + 2) % NSTAGE);
        if (i + 1 < S) cp_wait<1>(); else cp_wait<0>();
        __syncthreads();
    }

    // epilogue
    #pragma unroll
    for (int mf = 0; mf < 4; mf++) {
        #pragma unroll
        for (int h = 0; h < 2; h++) {
            const int r = row0 + wm * 64 + mf * 16 + (lane >> 2) + h * 8;
            float rbias = 0.f, iw = 0.f;
            if (EPI == 1) rbias = b1[r];
            if (EPI == 4) { rbias = b1[r] + b2[r]; iw = b3[r]; }
            const float* xrow = (EPI == 4) ? (b4 + (size_t)z * N_) : nullptr;
            #pragma unroll
            for (int nf = 0; nf < 8; nf++) {
                const int cidx = col0 + wn * 64 + nf * 8 + (lane & 3) * 2;
                float2 o;
                o.x = acc[mf][nf][h * 2 + 0];
                o.y = acc[mf][nf][h * 2 + 1];
                if (EPI == 1) { o.x += rbias; o.y += rbias; }
                if (EPI == 2 || EPI == 3) {
                    float2 bc = *(const float2*)(b1 + cidx);
                    o.x += bc.x; o.y += bc.y;
                }
                if (EPI == 4) {
                    float2 xv = *(const float2*)(xrow + cidx);
                    o.x += rbias + iw * xv.x; o.y += rbias + iw * xv.y;
                }
                if (EPI == 2 || EPI == 4) { o.x = fmaxf(o.x, 0.f); o.y = fmaxf(o.y, 0.f); }
                if (OUTB == 0) {
                    *(float2*)(C + (size_t)z * sC + (size_t)r * N + cidx) = o;
                } else {
                    __nv_bfloat16 hx, lx, hy, ly;
                    split1(o.x, hx, lx); split1(o.y, hy, ly);
                    size_t off = (size_t)z * sC + (size_t)r * N + cidx;
                    *(uint32_t*)(Oh + off) = pk2(hx, hy);
                    *(uint32_t*)(Ol + off) = pk2(lx, ly);
                }
            }
        }
    }
}

// ---------------- conv1 (3x3, 1->C) + ReLU, zero-padded ----------------
__global__ void conv1_relu_pad(const float* __restrict__ x, const float* __restrict__ w,
                               const float* __restrict__ bia, float* __restrict__ hp) {
    int idx = blockIdx.x * 256 + threadIdx.x;
    int b = idx / (C_ * PW * PW);
    int rem = idx - b * (C_ * PW * PW);
    int c = rem / (PW * PW);
    int p = rem - c * (PW * PW);
    int yy = p / PW, xx = p - yy * PW;
    float out = 0.f;
    if (yy >= 1 && yy <= HW && xx >= 1 && xx <= HW) {
        int y = yy - 1, x0 = xx - 1;
        float acc = bia[c];
        const float* xb = x + b * HW * HW;
        #pragma unroll
        for (int ky = 0; ky < 3; ky++) {
            int iy = y + ky - 1;
            if (iy < 0 || iy >= HW) continue;
            #pragma unroll
            for (int kx = 0; kx < 3; kx++) {
                int ix = x0 + kx - 1;
                if (ix < 0 || ix >= HW) continue;
                acc += w[c * 9 + ky * 3 + kx] * xb[iy * HW + ix];
            }
        }
        out = fmaxf(acc, 0.f);
    }
    hp[idx] = out;
}

// ---------------- im2col^T + split ----------------
__global__ void im2col_gen(const float* __restrict__ hp,
                           __nv_bfloat16* __restrict__ bh, __nv_bfloat16* __restrict__ bl) {
    __shared__ float s[64][33];
    int t = threadIdx.x;
    int ic0 = blockIdx.x * 64, n0 = blockIdx.y * 32;
    int zo = blockIdx.z, z = zo / 9, off = zo - z * 9;
    int ky = off / 3, kx = off - ky * 3;
    const float* hpz = hp + (size_t)z * C_ * (PW * PW);
    #pragma unroll
    for (int p = 0; p < 2; p++) {
        int icl = p * 32 + (t >> 3);
        int nl = (t & 7) * 4;
        const float* base = hpz + (size_t)(ic0 + icl) * (PW * PW) + ky * PW + kx;
        #pragma unroll
        for (int i = 0; i < 4; i++) {
            int n = n0 + nl + i;
            int y = n / HW, xx = n - y * HW;
            s[icl][nl + i] = base[y * PW + xx];
        }
    }
    __syncthreads();
    int n = t >> 3, icc = (t & 7) * 8;
    size_t o = (size_t)z * ((size_t)N_ * K2) + (size_t)(n0 + n) * K2 + (size_t)off * C_ + ic0 + icc;
    __nv_bfloat16 hh[8], ll[8];
    #pragma unroll
    for (int i = 0; i < 8; i++) split1(s[icc + i][n], hh[i], ll[i]);
    uint4 uh, ul;
    uh.x = pk2(hh[0], hh[1]); uh.y = pk2(hh[2], hh[3]); uh.z = pk2(hh[4], hh[5]); uh.w = pk2(hh[6], hh[7]);
    ul.x = pk2(ll[0], ll[1]); ul.y = pk2(ll[2], ll[3]); ul.z = pk2(ll[4], ll[5]); ul.w = pk2(ll[6], ll[7]);
    *(uint4*)(bh + o) = uh;
    *(uint4*)(bl + o) = ul;
}

// ---------------- W2 reorder+split: out[c][off*C+ic] = W2[c][ic*9+off] ----------------
__global__ void reorder_split_w2(const float* __restrict__ w2,
                                 __nv_bfloat16* __restrict__ oh, __nv_bfloat16* __restrict__ ol) {
    int id = blockIdx.x * 256 + threadIdx.x;
    int c = id / (9 * 288);
    int rem = id - c * (9 * 288);
    int off = rem / 288, icb = rem - off * 288;
    const float* src = w2 + (size_t)c * K2 + (size_t)icb * 72 + off;
    __nv_bfloat16 hh[8], ll[8];
    #pragma unroll
    for (int i = 0; i < 8; i++) split1(src[i * 9], hh[i], ll[i]);
    size_t o = (size_t)c * K2 + (size_t)off * C_ + (size_t)icb * 8;
    uint4 uh, ul;
    uh.x = pk2(hh[0], hh[1]); uh.y = pk2(hh[2], hh[3]); uh.z = pk2(hh[4], hh[5]); uh.w = pk2(hh[6], hh[7]);
    ul.x = pk2(ll[0], ll[1]); ul.y = pk2(ll[2], ll[3]); ul.z = pk2(ll[4], ll[5]); ul.w = pk2(ll[6], ll[7]);
    *(uint4*)(oh + o) = uh;
    *(uint4*)(ol + o) = ul;
}

// ---------------- plain split (weights) ----------------
__global__ void split_plain(const float* __restrict__ src,
                            __nv_bfloat16* __restrict__ oh, __nv_bfloat16* __restrict__ ol) {
    size_t i4 = (size_t)blockIdx.x * 256 + threadIdx.x;
    float4 v = *(const float4*)(src + i4 * 4);
    __nv_bfloat16 h0, h1, h2, h3, l0, l1, l2, l3;
    split1(v.x, h0, l0); split1(v.y, h1, l1); split1(v.z, h2, l2); split1(v.w, h3, l3);
    uint2 uh, ul;
    uh.x = pk2(h0, h1); uh.y = pk2(h2, h3);
    ul.x = pk2(l0, l1); ul.y = pk2(l2, l3);
    *(uint2*)(oh + i4 * 4) = uh;
    *(uint2*)(ol + i4 * 4) = ul;
}

// ---------------- transpose + split: in [z][R][Cc] -> out [z][Cc][R] ----------------
__global__ void transpose_split(const float* __restrict__ in,
                                __nv_bfloat16* __restrict__ oh, __nv_bfloat16* __restrict__ ol,
                                int R, int Cc) {
    __shared__ float s[64][33];
    int t = threadIdx.x;
    int c0 = blockIdx.x * 32, r0 = blockIdx.y * 64;
    size_t zb = (size_t)blockIdx.z * R * Cc;
    {
        int r = t >> 2, cl = (t & 3) * 8;
        const float* src = in + zb + (size_t)(r0 + r) * Cc + c0 + cl;
        float4 a = *(const float4*)src;
        float4 b = *(const float4*)(src + 4);
        s[r][cl + 0] = a.x; s[r][cl + 1] = a.y; s[r][cl + 2] = a.z; s[r][cl + 3] = a.w;
        s[r][cl + 4] = b.x; s[r][cl + 5] = b.y; s[r][cl + 6] = b.z; s[r][cl + 7] = b.w;
    }
    __syncthreads();
    int c = t >> 3, rl = (t & 7) * 8;
    __nv_bfloat16 hh[8], ll[8];
    #pragma unroll
    for (int i = 0; i < 8; i++) split1(s[rl + i][c], hh[i], ll[i]);
    size_t o = zb + (size_t)(c0 + c) * R + r0 + rl;
    uint4 uh, ul;
    uh.x = pk2(hh[0], hh[1]); uh.y = pk2(hh[2], hh[3]); uh.z = pk2(hh[4], hh[5]); uh.w = pk2(hh[6], hh[7]);
    ul.x = pk2(ll[0], ll[1]); ul.y = pk2(ll[2], ll[3]); ul.z = pk2(ll[4], ll[5]); ul.w = pk2(ll[6], ll[7]);
    *(uint4*)(oh + o) = uh;
    *(uint4*)(ol + o) = ul;
}

// ---------------- reductions ----------------
__device__ __forceinline__ float block_sum(float v, float* red) {
    int tid = threadIdx.x;
    red[tid] = v; __syncthreads();
    #pragma unroll
    for (int s = 128; s > 0; s >>= 1) { if (tid < s) red[tid] += red[tid + s]; __syncthreads(); }
    float r = red[0]; __syncthreads();
    return r;
}
__device__ __forceinline__ float block_max(float v, float* red) {
    int tid = threadIdx.x;
    red[tid] = v; __syncthreads();
    #pragma unroll
    for (int s = 128; s > 0; s >>= 1) { if (tid < s) red[tid] = fmaxf(red[tid], red[tid + s]); __syncthreads(); }
    float r = red[0]; __syncthreads();
    return r;
}

// ---------------- softmax with analytic rel-pos bias -> bf16 split output ----------------
__global__ void softmax_bias_split(const float* __restrict__ qk, const float* __restrict__ rel,
                                   __nv_bfloat16* __restrict__ oh, __nv_bfloat16* __restrict__ ol) {
    __shared__ float red[256];
    int row = blockIdx.x;
    int b = row / E_;
    int i = row - b * E_;
    int ci = i / HW, wi = i - ci * HW;
    const float* rp = qk + (size_t)row * E_;
    int tid = threadIdx.x;
    float v[9];
    float mx = -3.4e38f;
    #pragma unroll
    for (int r = 0; r < 9; r++) {
        int j = r * 256 + tid;
        int cj = j / HW, wj = j - cj * HW;
        int idx = (ci - cj + HW - 1) * (2 * HW - 1) + (wi - wj + HW - 1);
        v[r] = rp[j] * (1.0f / 48.0f) + rel[idx * NH_ + b];
        mx = fmaxf(mx, v[r]);
    }
    mx = block_max(mx, red);
    float s = 0.f;
    #pragma unroll
    for (int r = 0; r < 9; r++) { v[r] = __expf(v[r] - mx); s += v[r]; }
    s = block_sum(s, red);
    float inv = 1.f / s;
    #pragma unroll
    for (int r = 0; r < 9; r++) {
        int j = r * 256 + tid;
        __nv_bfloat16 h, l;
        split1(v[r] * inv, h, l);
        oh[(size_t)row * E_ + j] = h;
        ol[(size_t)row * E_ + j] = l;
    }
}

// ---------------- shuffle + residual + LN1 -> fp32 + bf16 split ----------------
__global__ void add_shuffle_ln(const float* __restrict__ ao, const float* __restrict__ down,
                               const float* __restrict__ g, const float* __restrict__ be,
                               float* __restrict__ h1,
                               __nv_bfloat16* __restrict__ oh, __nv_bfloat16* __restrict__ ol) {
    __shared__ float red[256];
    int m = blockIdx.x;
    int e = m >> 2, bs = m & 3;
    const float* ar = ao + ((size_t)bs * E_ + e) * N_;
    const float* dr = down + (size_t)m * N_;
    int tid = threadIdx.x;
    float v[9]; float s = 0.f;
    #pragma unroll
    for (int r = 0; r < 9; r++) { int j = r * 256 + tid; v[r] = ar[j] + dr[j]; s += v[r]; }
    float mean = block_sum(s, red) * (1.f / N_);
    float s2 = 0.f;
    #pragma unroll
    for (int r = 0; r < 9; r++) { float d = v[r] - mean; s2 += d * d; }
    float var = block_sum(s2, red) * (1.f / N_);
    float rstd = rsqrtf(var + 1e-5f);
    #pragma unroll
    for (int r = 0; r < 9; r++) {
        int j = r * 256 + tid;
        float o = (v[r] - mean) * rstd * g[j] + be[j];
        h1[(size_t)m * N_ + j] = o;
        __nv_bfloat16 h, l;
        split1(o, h, l);
        oh[(size_t)m * N_ + j] = h;
        ol[(size_t)m * N_ + j] = l;
    }
}

// ---------------- residual + LN2 ----------------
__global__ void add_ln(const float* __restrict__ f, const float* __restrict__ h1,
                       const float* __restrict__ g, const float* __restrict__ be,
                       float* __restrict__ out) {
    __shared__ float red[256];
    int m = blockIdx.x;
    const float* fr = f + (size_t)m * N_;
    const float* hr = h1 + (size_t)m * N_;
    int tid = threadIdx.x;
    float v[9]; float s = 0.f;
    #pragma unroll
    for (int r = 0; r < 9; r++) { int j = r * 256 + tid; v[r] = fr[j] + hr[j]; s += v[r]; }
    float mean = block_sum(s, red) * (1.f / N_);
    float s2 = 0.f;
    #pragma unroll
    for (int r = 0; r < 9; r++) { float d = v[r] - mean; s2 += d * d; }
    float var = block_sum(s2, red) * (1.f / N_);
    float rstd = rsqrtf(var + 1e-5f);
    #pragma unroll
    for (int r = 0; r < 9; r++) {
        int j = r * 256 + tid;
        out[(size_t)m * N_ + j] = (v[r] - mean) * rstd * g[j] + be[j];
    }
}

// ---------------- maxpool 2x2 ----------------
__global__ void maxpool_k(const float* __restrict__ out, float* __restrict__ p) {
    int idx = blockIdx.x * 256 + threadIdx.x;
    int bc = idx / (24 * 24);
    int r = idx - bc * 576;
    int y = r / 24, x = r - y * 24;
    const float* o = out + (size_t)bc * N_ + (2 * y) * HW + 2 * x;
    p[idx] = fmaxf(fmaxf(o[0], o[1]), fmaxf(o[HW], o[HW + 1]));
}

// ---------------- launcher ----------------
extern "C" void kernel_launch(void* const* d_in, const int* in_sizes, int n_in,
                              void* d_out, int out_size) {
    const float* x    = (const float*)d_in[0];
    const float* c1w  = (const float*)d_in[1];
    const float* c1b  = (const float*)d_in[2];
    const float* c2w  = (const float*)d_in[3];
    const float* c2b  = (const float*)d_in[4];
    const float* idw  = (const float*)d_in[5];
    const float* idb  = (const float*)d_in[6];
    const float* qw   = (const float*)d_in[7];
    const float* qb   = (const float*)d_in[8];
    const float* kw   = (const float*)d_in[9];
    const float* kb   = (const float*)d_in[10];
    const float* vw   = (const float*)d_in[11];
    const float* vb   = (const float*)d_in[12];
    const float* rel  = (const float*)d_in[13];
    const float* ln1g = (const float*)d_in[14];
    const float* ln1b = (const float*)d_in[15];
    const float* ln2g = (const float*)d_in[16];
    const float* ln2b = (const float*)d_in[17];
    const float* fw1  = (const float*)d_in[18];
    const float* fb1  = (const float*)d_in[19];
    const float* fw2  = (const float*)d_in[20];
    const float* fb2  = (const float*)d_in[21];

    float* outp = (float*)d_out;
    float* pool = outp + (size_t)B_ * C_ * N_;

    float* F; __nv_bfloat16* Hh;
    cudaGetSymbolAddress((void**)&F, g_f32);
    cudaGetSymbolAddress((void**)&Hh, g_b16);

    float* hp = F + F_HP;   float* down = F + F_DOWN;
    float* qk = F + F_QK;   float* ao   = F + F_AO;
    float* h1 = F + F_H1;   float* ff   = F + F_FF;

    cudaFuncSetAttribute(mm_gemm<4,0>, cudaFuncAttributeMaxDynamicSharedMemorySize, DSMEM_REQ);
    cudaFuncSetAttribute(mm_gemm<1,1>, cudaFuncAttributeMaxDynamicSharedMemorySize, DSMEM_REQ);
    cudaFuncSetAttribute(mm_gemm<3,1>, cudaFuncAttributeMaxDynamicSharedMemorySize, DSMEM_REQ);
    cudaFuncSetAttribute(mm_gemm<0,0>, cudaFuncAttributeMaxDynamicSharedMemorySize, DSMEM_REQ);
    cudaFuncSetAttribute(mm_gemm<2,1>, cudaFuncAttributeMaxDynamicSharedMemorySize, DSMEM_REQ);
    cudaFuncSetAttribute(mm_gemm<3,0>, cudaFuncAttributeMaxDynamicSharedMemorySize, DSMEM_REQ);

    const long long EN = (long long)E_ * N_;
    const long long NK2 = (long long)N_ * K2;

    // weight prep
    reorder_split_w2<<<23328, 256>>>(c2w, Hh + H_W2H, Hh + H_W2L);
    split_plain<<<5184, 256>>>(qw, Hh + H_QWH, Hh + H_QWL);
    split_plain<<<5184, 256>>>(kw, Hh + H_KWH, Hh + H_KWL);
    split_plain<<<5184, 256>>>(vw, Hh + H_VWH, Hh + H_VWL);
    transpose_split<<<dim3(144, 36, 1), 256>>>(fw1, Hh + H_W1TH, Hh + H_W1TL, E_, E2);
    transpose_split<<<dim3(72, 72, 1), 256>>>(fw2, Hh + H_W2TH, Hh + H_W2TL, E2, E_);

    // conv block
    conv1_relu_pad<<<90000, 256>>>(x, c1w, c1b, hp);
    im2col_gen<<<dim3(36, 72, 36), 256>>>(hp, Hh + H_IMH, Hh + H_IML);
    mm_gemm<4,0><<<dim3(162, 1, 4), 256, DSMEM_REQ>>>(
        Hh + H_W2H, Hh + H_W2L, Hh + H_IMH, Hh + H_IML, down, nullptr, nullptr,
        c2b, idb, idw, x, C_, N_, K2, 9, 18, 0, NK2, EN);

    // qkv (q, k direct bf16; v computed pre-transposed as vT = DT . vw, bf16)
    transpose_split<<<dim3(72, 36, 4), 256>>>(down, Hh + H_DTH, Hh + H_DTL, C_, N_);
    mm_gemm<1,1><<<dim3(162, 1, 4), 256, DSMEM_REQ>>>(
        Hh + H_QWH, Hh + H_QWL, Hh + H_DTH, Hh + H_DTL, nullptr, Hh + H_QH, Hh + H_QL,
        qb, nullptr, nullptr, nullptr, E_, N_, C_, 9, 18, 0, EN, EN);
    mm_gemm<1,1><<<dim3(162, 1, 4), 256, DSMEM_REQ>>>(
        Hh + H_KWH, Hh + H_KWL, Hh + H_DTH, Hh + H_DTL, nullptr, Hh + H_KH, Hh + H_KL,
        kb, nullptr, nullptr, nullptr, E_, N_, C_, 9, 18, 0, EN, EN);
    mm_gemm<3,1><<<dim3(162, 1, 4), 256, DSMEM_REQ>>>(
        Hh + H_DTH, Hh + H_DTL, Hh + H_VWH, Hh + H_VWL, nullptr, Hh + H_VTH, Hh + H_VTL,
        vb, nullptr, nullptr, nullptr, N_, E_, C_, 9, 18, EN, 0, EN);

    // attention
    mm_gemm<0,0><<<dim3(162, 1, 4), 256, DSMEM_REQ>>>(
        Hh + H_QH, Hh + H_QL, Hh + H_KH, Hh + H_KL, qk, nullptr, nullptr,
        nullptr, nullptr, nullptr, nullptr, E_, E_, N_, 9, 18, EN, EN, EN);
    softmax_bias_split<<<B_ * E_, 256>>>(qk, rel, Hh + H_ATH, Hh + H_ATL);
    mm_gemm<0,0><<<dim3(162, 1, 4), 256, DSMEM_REQ>>>(
        Hh + H_ATH, Hh + H_ATL, Hh + H_VTH, Hh + H_VTL, ao, nullptr, nullptr,
        nullptr, nullptr, nullptr, nullptr, E_, N_, E_, 9, 18, EN, EN, EN);
    add_shuffle_ln<<<B_ * C_, 256>>>(ao, down, ln1g, ln1b, h1, Hh + H_H1H, Hh + H_H1L);

    // FFN
    mm_gemm<2,1><<<dim3(1296, 1, 1), 256, DSMEM_REQ>>>(
        Hh + H_H1H, Hh + H_H1L, Hh + H_W1TH, Hh + H_W1TL, nullptr, Hh + H_MIDH, Hh + H_MIDL,
        fb1, nullptr, nullptr, nullptr, B_ * N_, E2, E_, 36, 36, 0, 0, 0);
    mm_gemm<3,0><<<dim3(648, 1, 1), 256, DSMEM_REQ>>>(
        Hh + H_MIDH, Hh + H_MIDL, Hh + H_W2TH, Hh + H_W2TL, ff, nullptr, nullptr,
        fb2, nullptr, nullptr, nullptr, B_ * N_, E_, E2, 36, 18, 0, 0, 0);
    add_ln<<<B_ * C_, 256>>>(ff, h1, ln2g, ln2b, outp);
    maxpool_k<<<20736, 256>>>(outp, pool);
}

// round 7
// speedup vs baseline: 1.1434x; 1.1434x over previous
#include <cuda_runtime.h>
#include <cuda_bf16.h>
#include <cstdint>

#define B_  4
#define C_  2304
#define N_  2304
#define E_  2304
#define HW  48
#define PW  50
#define NH_ 4
#define K2  20736
#define E2  4608

// GEMM tiling (R5 geometry): CTA 128x128x32, 8 warps (2m x 4n), warp tile 64x32
#define BM 128
#define BN 128
#define BK 32
#define TSTRIDE 40                      // padded row stride in bf16 (80 B)
#define TILE_BYTES (BM * TSTRIDE * 2)   // 10240
#define STAGE_BYTES (4 * TILE_BYTES)    // 40960: Ah, Al, Bh, Bl
#define NSTAGE 3
#define DSMEM_REQ (NSTAGE * STAGE_BYTES)

// ---------------- PTX helpers ----------------
__device__ __forceinline__ uint32_t smem_u32(const void* p) {
    uint32_t a;
    asm("{ .reg .u64 t; cvta.to.shared.u64 t, %1; cvt.u32.u64 %0, t; }" : "=r"(a) : "l"(p));
    return a;
}
__device__ __forceinline__ void cp16(uint32_t dst, const void* src) {
    asm volatile("cp.async.cg.shared.global [%0], [%1], 16;" :: "r"(dst), "l"(src));
}
__device__ __forceinline__ void cp_commit() { asm volatile("cp.async.commit_group;"); }
template<int NN>
__device__ __forceinline__ void cp_wait() { asm volatile("cp.async.wait_group %0;" :: "n"(NN)); }

__device__ __forceinline__ void ldm4(uint32_t& r0, uint32_t& r1, uint32_t& r2, uint32_t& r3, uint32_t a) {
    asm volatile("ldmatrix.sync.aligned.m8n8.x4.shared.b16 {%0,%1,%2,%3}, [%4];"
                 : "=r"(r0), "=r"(r1), "=r"(r2), "=r"(r3) : "r"(a));
}
__device__ __forceinline__ void mma16816(float* d, uint32_t a0, uint32_t a1, uint32_t a2, uint32_t a3,
                                         uint32_t b0, uint32_t b1) {
    asm volatile("mma.sync.aligned.m16n8k16.row.col.f32.bf16.bf16.f32 "
                 "{%0,%1,%2,%3}, {%4,%5,%6,%7}, {%8,%9}, {%0,%1,%2,%3};"
                 : "+f"(d[0]), "+f"(d[1]), "+f"(d[2]), "+f"(d[3])
                 : "r"(a0), "r"(a1), "r"(a2), "r"(a3), "r"(b0), "r"(b1));
}

__device__ __forceinline__ void split1(float v, __nv_bfloat16& h, __nv_bfloat16& l) {
    h = __float2bfloat16(v);
    l = __float2bfloat16(v - __bfloat162float(h));
}
__device__ __forceinline__ uint32_t pk2(__nv_bfloat16 a, __nv_bfloat16 b) {
    __nv_bfloat162 t(a, b);
    return *reinterpret_cast<uint32_t*>(&t);
}

// ---------------- scratch arenas ----------------
constexpr size_t SZ_EN = (size_t)B_ * E_ * N_;
constexpr size_t SZ_W  = (size_t)E_ * E_;
constexpr size_t F_HP = 0, F_DOWN = 23040000;
constexpr size_t F_QK = F_DOWN + SZ_EN, F_AO = F_QK + SZ_EN, F_H1 = F_AO + SZ_EN;
constexpr size_t F_FF = F_H1 + SZ_EN;
constexpr size_t F_TOT = F_FF + SZ_EN;

constexpr size_t H_IMH = 0, H_IML = H_IMH + (size_t)B_ * N_ * K2;
constexpr size_t H_W2H = H_IML + (size_t)B_ * N_ * K2, H_W2L = H_W2H + (size_t)C_ * K2;
constexpr size_t H_QWH = H_W2L + (size_t)C_ * K2, H_QWL = H_QWH + SZ_W;
constexpr size_t H_KWH = H_QWL + SZ_W, H_KWL = H_KWH + SZ_W;
constexpr size_t H_VWH = H_KWL + SZ_W, H_VWL = H_VWH + SZ_W;
constexpr size_t H_W1TH = H_VWL + SZ_W, H_W1TL = H_W1TH + 2 * SZ_W;
constexpr size_t H_W2TH = H_W1TL + 2 * SZ_W, H_W2TL = H_W2TH + 2 * SZ_W;
constexpr size_t H_DTH = H_W2TL + 2 * SZ_W, H_DTL = H_DTH + SZ_EN;
constexpr size_t H_VTH = H_DTL + SZ_EN, H_VTL = H_VTH + SZ_EN;
constexpr size_t H_QH = H_VTL + SZ_EN, H_QL = H_QH + SZ_EN;
constexpr size_t H_KH = H_QL + SZ_EN, H_KL = H_KH + SZ_EN;
constexpr size_t H_ATH = H_KL + SZ_EN, H_ATL = H_ATH + SZ_EN;
constexpr size_t H_H1H = H_ATL + SZ_EN, H_H1L = H_H1H + SZ_EN;
constexpr size_t H_MIDH = H_H1L + SZ_EN, H_MIDL = H_MIDH + 2 * SZ_EN;
constexpr size_t H_TOT = H_MIDL + 2 * SZ_EN;

__device__ __align__(256) float         g_f32[F_TOT];
__device__ __align__(256) __nv_bfloat16 g_b16[H_TOT];

// ---------------- mma.sync GEMM: D[m][n] = sum_k A[m,k]*B[n,k] (3xbf16 split) ----------------
// EPI: 0 none, 1 +b1[row], 2 +b1[col]+relu, 3 +b1[col], 4 conv(+b1[r]+b2[r]+b3[r]*b4[z*N_+n], relu)
// OUTB: 0 -> fp32 C; 1 -> bf16 split pair (Oh, Ol)
template<int EPI, int OUTB>
__global__ void __launch_bounds__(256, 1) mm_gemm(
    const __nv_bfloat16* __restrict__ Ah, const __nv_bfloat16* __restrict__ Al,
    const __nv_bfloat16* __restrict__ Bh, const __nv_bfloat16* __restrict__ Bl,
    float* __restrict__ C,
    __nv_bfloat16* __restrict__ Oh, __nv_bfloat16* __restrict__ Ol,
    const float* __restrict__ b1, const float* __restrict__ b2,
    const float* __restrict__ b3, const float* __restrict__ b4,
    int M, int N, int K, int tilesM, int tilesN,
    long long sA, long long sB, long long sC)
{
    extern __shared__ char smem[];
    const uint32_t sb = smem_u32(smem);
    const int tid = threadIdx.x;
    const int wid = tid >> 5, lane = tid & 31;
    const int wm = wid >> 2, wn = wid & 3;          // warp grid 2 (m) x 4 (n)
    const int z = blockIdx.z;

    // GROUP_M raster for L2 reuse
    int bid = blockIdx.x;
    const int GROUP = 8;
    int npg = GROUP * tilesN;
    int grp = bid / npg, rem = bid - grp * npg;
    int gs = tilesM - grp * GROUP; if (gs > GROUP) gs = GROUP;
    int mt = grp * GROUP + rem % gs;
    int nt = rem / gs;
    const int row0 = mt * BM, col0 = nt * BN;

    Ah += (size_t)z * sA; Al += (size_t)z * sA;
    Bh += (size_t)z * sB; Bl += (size_t)z * sB;

    // cp.async mapping: thread t -> row t>>1, two 16B chunks at (t&1)*32 bytes
    const int crow = tid >> 1;
    const int cbyte = (tid & 1) * 32;
    const uint32_t dst_off = (uint32_t)crow * (TSTRIDE * 2) + cbyte;

    auto prefetch = [&](int slab, int st) {
        const int k0 = slab * BK;
        uint32_t base = sb + st * STAGE_BYTES + dst_off;
        const char* srcA_h = (const char*)(Ah + (size_t)(row0 + crow) * K + k0) + cbyte;
        const char* srcA_l = (const char*)(Al + (size_t)(row0 + crow) * K + k0) + cbyte;
        const char* srcB_h = (const char*)(Bh + (size_t)(col0 + crow) * K + k0) + cbyte;
        const char* srcB_l = (const char*)(Bl + (size_t)(col0 + crow) * K + k0) + cbyte;
        cp16(base,                   srcA_h);      cp16(base + 16,                   srcA_h + 16);
        cp16(base + TILE_BYTES,      srcA_l);      cp16(base + TILE_BYTES + 16,      srcA_l + 16);
        cp16(base + 2 * TILE_BYTES,  srcB_h);      cp16(base + 2 * TILE_BYTES + 16,  srcB_h + 16);
        cp16(base + 3 * TILE_BYTES,  srcB_l);      cp16(base + 3 * TILE_BYTES + 16,  srcB_l + 16);
        cp_commit();
    };

    float acc[4][4][4];
    #pragma unroll
    for (int a = 0; a < 4; a++)
        #pragma unroll
        for (int b = 0; b < 4; b++)
            #pragma unroll
            for (int c = 0; c < 4; c++) acc[a][b][c] = 0.f;

    const int S = K / BK;
    prefetch(0, 0);
    prefetch(1, 1);
    cp_wait<1>();
    __syncthreads();

    const uint32_t a_row = (uint32_t)(wm * 64 + (lane & 15));
    const uint32_t a_kh  = (uint32_t)(lane >> 4) * 16;
    const uint32_t b_row = (uint32_t)(wn * 32 + (lane & 7) + ((lane >> 4) & 1) * 8);
    const uint32_t b_kh  = (uint32_t)((lane >> 3) & 1) * 16;

    for (int i = 0; i < S; i++) {
        const uint32_t st = sb + (i % NSTAGE) * STAGE_BYTES;
        const uint32_t aH = st + a_row * (TSTRIDE * 2) + a_kh;
        const uint32_t bH = st + 2 * TILE_BYTES + b_row * (TSTRIDE * 2) + b_kh;

        #pragma unroll
        for (int ks = 0; ks < 2; ks++) {
            const uint32_t ko = ks * 32;
            uint32_t ah[4][4], al[4][4], bh[2][4], bl[2][4];
            #pragma unroll
            for (int mf = 0; mf < 4; mf++) {
                uint32_t adr = aH + ko + (uint32_t)mf * 16 * (TSTRIDE * 2);
                ldm4(ah[mf][0], ah[mf][1], ah[mf][2], ah[mf][3], adr);
                ldm4(al[mf][0], al[mf][1], al[mf][2], al[mf][3], adr + TILE_BYTES);
            }
            #pragma unroll
            for (int p = 0; p < 2; p++) {
                uint32_t adr = bH + ko + (uint32_t)p * 16 * (TSTRIDE * 2);
                ldm4(bh[p][0], bh[p][1], bh[p][2], bh[p][3], adr);
                ldm4(bl[p][0], bl[p][1], bl[p][2], bl[p][3], adr + TILE_BYTES);
            }
            #pragma unroll
            for (int mf = 0; mf < 4; mf++)
                #pragma unroll
                for (int nf = 0; nf < 4; nf++) {
                    uint32_t h0 = bh[nf >> 1][(nf & 1) * 2], h1 = bh[nf >> 1][(nf & 1) * 2 + 1];
                    uint32_t l0 = bl[nf >> 1][(nf & 1) * 2], l1 = bl[nf >> 1][(nf & 1) * 2 + 1];
                    mma16816(acc[mf][nf], ah[mf][0], ah[mf][1], ah[mf][2], ah[mf][3], h0, h1);
                    mma16816(acc[mf][nf], ah[mf][0], ah[mf][1], ah[mf][2], ah[mf][3], l0, l1);
                    mma16816(acc[mf][nf], al[mf][0], al[mf][1], al[mf][2], al[mf][3], h0, h1);
                }
        }
        if (i + 2 < S) prefetch(i + 2, (i + 2) % NSTAGE);
        if (i + 1 < S) cp_wait<1>(); else cp_wait<0>();
        __syncthreads();
    }

    // epilogue
    #pragma unroll
    for (int mf = 0; mf < 4; mf++) {
        #pragma unroll
        for (int h = 0; h < 2; h++) {
            const int r = row0 + wm * 64 + mf * 16 + (lane >> 2) + h * 8;
            float rbias = 0.f, iw = 0.f;
            if (EPI == 1) rbias = b1[r];
            if (EPI == 4) { rbias = b1[r] + b2[r]; iw = b3[r]; }
            const float* xrow = (EPI == 4) ? (b4 + (size_t)z * N_) : nullptr;
            #pragma unroll
            for (int nf = 0; nf < 4; nf++) {
                const int cidx = col0 + wn * 32 + nf * 8 + (lane & 3) * 2;
                float2 o;
                o.x = acc[mf][nf][h * 2 + 0];
                o.y = acc[mf][nf][h * 2 + 1];
                if (EPI == 1) { o.x += rbias; o.y += rbias; }
                if (EPI == 2 || EPI == 3) {
                    float2 bc = *(const float2*)(b1 + cidx);
                    o.x += bc.x; o.y += bc.y;
                }
                if (EPI == 4) {
                    float2 xv = *(const float2*)(xrow + cidx);
                    o.x += rbias + iw * xv.x; o.y += rbias + iw * xv.y;
                }
                if (EPI == 2 || EPI == 4) { o.x = fmaxf(o.x, 0.f); o.y = fmaxf(o.y, 0.f); }
                if (OUTB == 0) {
                    *(float2*)(C + (size_t)z * sC + (size_t)r * N + cidx) = o;
                } else {
                    __nv_bfloat16 hx, lx, hy, ly;
                    split1(o.x, hx, lx); split1(o.y, hy, ly);
                    size_t off = (size_t)z * sC + (size_t)r * N + cidx;
                    *(uint32_t*)(Oh + off) = pk2(hx, hy);
                    *(uint32_t*)(Ol + off) = pk2(lx, ly);
                }
            }
        }
    }
}

// ---------------- conv1 (3x3, 1->C) + ReLU, zero-padded ----------------
__global__ void conv1_relu_pad(const float* __restrict__ x, const float* __restrict__ w,
                               const float* __restrict__ bia, float* __restrict__ hp) {
    int idx = blockIdx.x * 256 + threadIdx.x;
    int b = idx / (C_ * PW * PW);
    int rem = idx - b * (C_ * PW * PW);
    int c = rem / (PW * PW);
    int p = rem - c * (PW * PW);
    int yy = p / PW, xx = p - yy * PW;
    float out = 0.f;
    if (yy >= 1 && yy <= HW && xx >= 1 && xx <= HW) {
        int y = yy - 1, x0 = xx - 1;
        float acc = bia[c];
        const float* xb = x + b * HW * HW;
        #pragma unroll
        for (int ky = 0; ky < 3; ky++) {
            int iy = y + ky - 1;
            if (iy < 0 || iy >= HW) continue;
            #pragma unroll
            for (int kx = 0; kx < 3; kx++) {
                int ix = x0 + kx - 1;
                if (ix < 0 || ix >= HW) continue;
                acc += w[c * 9 + ky * 3 + kx] * xb[iy * HW + ix];
            }
        }
        out = fmaxf(acc, 0.f);
    }
    hp[idx] = out;
}

// ---------------- im2col^T + split ----------------
__global__ void im2col_gen(const float* __restrict__ hp,
                           __nv_bfloat16* __restrict__ bh, __nv_bfloat16* __restrict__ bl) {
    __shared__ float s[64][33];
    int t = threadIdx.x;
    int ic0 = blockIdx.x * 64, n0 = blockIdx.y * 32;
    int zo = blockIdx.z, z = zo / 9, off = zo - z * 9;
    int ky = off / 3, kx = off - ky * 3;
    const float* hpz = hp + (size_t)z * C_ * (PW * PW);
    #pragma unroll
    for (int p = 0; p < 2; p++) {
        int icl = p * 32 + (t >> 3);
        int nl = (t & 7) * 4;
        const float* base = hpz + (size_t)(ic0 + icl) * (PW * PW) + ky * PW + kx;
        #pragma unroll
        for (int i = 0; i < 4; i++) {
            int n = n0 + nl + i;
            int y = n / HW, xx = n - y * HW;
            s[icl][nl + i] = base[y * PW + xx];
        }
    }
    __syncthreads();
    int n = t >> 3, icc = (t & 7) * 8;
    size_t o = (size_t)z * ((size_t)N_ * K2) + (size_t)(n0 + n) * K2 + (size_t)off * C_ + ic0 + icc;
    __nv_bfloat16 hh[8], ll[8];
    #pragma unroll
    for (int i = 0; i < 8; i++) split1(s[icc + i][n], hh[i], ll[i]);
    uint4 uh, ul;
    uh.x = pk2(hh[0], hh[1]); uh.y = pk2(hh[2], hh[3]); uh.z = pk2(hh[4], hh[5]); uh.w = pk2(hh[6], hh[7]);
    ul.x = pk2(ll[0], ll[1]); ul.y = pk2(ll[2], ll[3]); ul.z = pk2(ll[4], ll[5]); ul.w = pk2(ll[6], ll[7]);
    *(uint4*)(bh + o) = uh;
    *(uint4*)(bl + o) = ul;
}

// ---------------- W2 reorder+split: out[c][off*C+ic] = W2[c][ic*9+off] ----------------
__global__ void reorder_split_w2(const float* __restrict__ w2,
                                 __nv_bfloat16* __restrict__ oh, __nv_bfloat16* __restrict__ ol) {
    int id = blockIdx.x * 256 + threadIdx.x;
    int c = id / (9 * 288);
    int rem = id - c * (9 * 288);
    int off = rem / 288, icb = rem - off * 288;
    const float* src = w2 + (size_t)c * K2 + (size_t)icb * 72 + off;
    __nv_bfloat16 hh[8], ll[8];
    #pragma unroll
    for (int i = 0; i < 8; i++) split1(src[i * 9], hh[i], ll[i]);
    size_t o = (size_t)c * K2 + (size_t)off * C_ + (size_t)icb * 8;
    uint4 uh, ul;
    uh.x = pk2(hh[0], hh[1]); uh.y = pk2(hh[2], hh[3]); uh.z = pk2(hh[4], hh[5]); uh.w = pk2(hh[6], hh[7]);
    ul.x = pk2(ll[0], ll[1]); ul.y = pk2(ll[2], ll[3]); ul.z = pk2(ll[4], ll[5]); ul.w = pk2(ll[6], ll[7]);
    *(uint4*)(oh + o) = uh;
    *(uint4*)(ol + o) = ul;
}

// ---------------- plain split (weights) ----------------
__global__ void split_plain(const float* __restrict__ src,
                            __nv_bfloat16* __restrict__ oh, __nv_bfloat16* __restrict__ ol) {
    size_t i4 = (size_t)blockIdx.x * 256 + threadIdx.x;
    float4 v = *(const float4*)(src + i4 * 4);
    __nv_bfloat16 h0, h1, h2, h3, l0, l1, l2, l3;
    split1(v.x, h0, l0); split1(v.y, h1, l1); split1(v.z, h2, l2); split1(v.w, h3, l3);
    uint2 uh, ul;
    uh.x = pk2(h0, h1); uh.y = pk2(h2, h3);
    ul.x = pk2(l0, l1); ul.y = pk2(l2, l3);
    *(uint2*)(oh + i4 * 4) = uh;
    *(uint2*)(ol + i4 * 4) = ul;
}

// ---------------- transpose + split: in [z][R][Cc] -> out [z][Cc][R] ----------------
__global__ void transpose_split(const float* __restrict__ in,
                                __nv_bfloat16* __restrict__ oh, __nv_bfloat16* __restrict__ ol,
                                int R, int Cc) {
    __shared__ float s[64][33];
    int t = threadIdx.x;
    int c0 = blockIdx.x * 32, r0 = blockIdx.y * 64;
    size_t zb = (size_t)blockIdx.z * R * Cc;
    {
        int r = t >> 2, cl = (t & 3) * 8;
        const float* src = in + zb + (size_t)(r0 + r) * Cc + c0 + cl;
        float4 a = *(const float4*)src;
        float4 b = *(const float4*)(src + 4);
        s[r][cl + 0] = a.x; s[r][cl + 1] = a.y; s[r][cl + 2] = a.z; s[r][cl + 3] = a.w;
        s[r][cl + 4] = b.x; s[r][cl + 5] = b.y; s[r][cl + 6] = b.z; s[r][cl + 7] = b.w;
    }
    __syncthreads();
    int c = t >> 3, rl = (t & 7) * 8;
    __nv_bfloat16 hh[8], ll[8];
    #pragma unroll
    for (int i = 0; i < 8; i++) split1(s[rl + i][c], hh[i], ll[i]);
    size_t o = zb + (size_t)(c0 + c) * R + r0 + rl;
    uint4 uh, ul;
    uh.x = pk2(hh[0], hh[1]); uh.y = pk2(hh[2], hh[3]); uh.z = pk2(hh[4], hh[5]); uh.w = pk2(hh[6], hh[7]);
    ul.x = pk2(ll[0], ll[1]); ul.y = pk2(ll[2], ll[3]); ul.z = pk2(ll[4], ll[5]); ul.w = pk2(ll[6], ll[7]);
    *(uint4*)(oh + o) = uh;
    *(uint4*)(ol + o) = ul;
}

// ---------------- reductions ----------------
__device__ __forceinline__ float block_sum(float v, float* red) {
    int tid = threadIdx.x;
    red[tid] = v; __syncthreads();
    #pragma unroll
    for (int s = 128; s > 0; s >>= 1) { if (tid < s) red[tid] += red[tid + s]; __syncthreads(); }
    float r = red[0]; __syncthreads();
    return r;
}
__device__ __forceinline__ float block_max(float v, float* red) {
    int tid = threadIdx.x;
    red[tid] = v; __syncthreads();
    #pragma unroll
    for (int s = 128; s > 0; s >>= 1) { if (tid < s) red[tid] = fmaxf(red[tid], red[tid + s]); __syncthreads(); }
    float r = red[0]; __syncthreads();
    return r;
}

// ---------------- softmax with analytic rel-pos bias -> bf16 split output ----------------
__global__ void softmax_bias_split(const float* __restrict__ qk, const float* __restrict__ rel,
                                   __nv_bfloat16* __restrict__ oh, __nv_bfloat16* __restrict__ ol) {
    __shared__ float red[256];
    int row = blockIdx.x;
    int b = row / E_;
    int i = row - b * E_;
    int ci = i / HW, wi = i - ci * HW;
    const float* rp = qk + (size_t)row * E_;
    int tid = threadIdx.x;
    float v[9];
    float mx = -3.4e38f;
    #pragma unroll
    for (int r = 0; r < 9; r++) {
        int j = r * 256 + tid;
        int cj = j / HW, wj = j - cj * HW;
        int idx = (ci - cj + HW - 1) * (2 * HW - 1) + (wi - wj + HW - 1);
        v[r] = rp[j] * (1.0f / 48.0f) + rel[idx * NH_ + b];
        mx = fmaxf(mx, v[r]);
    }
    mx = block_max(mx, red);
    float s = 0.f;
    #pragma unroll
    for (int r = 0; r < 9; r++) { v[r] = __expf(v[r] - mx); s += v[r]; }
    s = block_sum(s, red);
    float inv = 1.f / s;
    #pragma unroll
    for (int r = 0; r < 9; r++) {
        int j = r * 256 + tid;
        __nv_bfloat16 h, l;
        split1(v[r] * inv, h, l);
        oh[(size_t)row * E_ + j] = h;
        ol[(size_t)row * E_ + j] = l;
    }
}

// ---------------- shuffle + residual + LN1 -> fp32 + bf16 split ----------------
__global__ void add_shuffle_ln(const float* __restrict__ ao, const float* __restrict__ down,
                               const float* __restrict__ g, const float* __restrict__ be,
                               float* __restrict__ h1,
                               __nv_bfloat16* __restrict__ oh, __nv_bfloat16* __restrict__ ol) {
    __shared__ float red[256];
    int m = blockIdx.x;
    int e = m >> 2, bs = m & 3;
    const float* ar = ao + ((size_t)bs * E_ + e) * N_;
    const float* dr = down + (size_t)m * N_;
    int tid = threadIdx.x;
    float v[9]; float s = 0.f;
    #pragma unroll
    for (int r = 0; r < 9; r++) { int j = r * 256 + tid; v[r] = ar[j] + dr[j]; s += v[r]; }
    float mean = block_sum(s, red) * (1.f / N_);
    float s2 = 0.f;
    #pragma unroll
    for (int r = 0; r < 9; r++) { float d = v[r] - mean; s2 += d * d; }
    float var = block_sum(s2, red) * (1.f / N_);
    float rstd = rsqrtf(var + 1e-5f);
    #pragma unroll
    for (int r = 0; r < 9; r++) {
        int j = r * 256 + tid;
        float o = (v[r] - mean) * rstd * g[j] + be[j];
        h1[(size_t)m * N_ + j] = o;
        __nv_bfloat16 h, l;
        split1(o, h, l);
        oh[(size_t)m * N_ + j] = h;
        ol[(size_t)m * N_ + j] = l;
    }
}

// ---------------- residual + LN2 ----------------
__global__ void add_ln(const float* __restrict__ f, const float* __restrict__ h1,
                       const float* __restrict__ g, const float* __restrict__ be,
                       float* __restrict__ out) {
    __shared__ float red[256];
    int m = blockIdx.x;
    const float* fr = f + (size_t)m * N_;
    const float* hr = h1 + (size_t)m * N_;
    int tid = threadIdx.x;
    float v[9]; float s = 0.f;
    #pragma unroll
    for (int r = 0; r < 9; r++) { int j = r * 256 + tid; v[r] = fr[j] + hr[j]; s += v[r]; }
    float mean = block_sum(s, red) * (1.f / N_);
    float s2 = 0.f;
    #pragma unroll
    for (int r = 0; r < 9; r++) { float d = v[r] - mean; s2 += d * d; }
    float var = block_sum(s2, red) * (1.f / N_);
    float rstd = rsqrtf(var + 1e-5f);
    #pragma unroll
    for (int r = 0; r < 9; r++) {
        int j = r * 256 + tid;
        out[(size_t)m * N_ + j] = (v[r] - mean) * rstd * g[j] + be[j];
    }
}

// ---------------- maxpool 2x2 ----------------
__global__ void maxpool_k(const float* __restrict__ out, float* __restrict__ p) {
    int idx = blockIdx.x * 256 + threadIdx.x;
    int bc = idx / (24 * 24);
    int r = idx - bc * 576;
    int y = r / 24, x = r - y * 24;
    const float* o = out + (size_t)bc * N_ + (2 * y) * HW + 2 * x;
    p[idx] = fmaxf(fmaxf(o[0], o[1]), fmaxf(o[HW], o[HW + 1]));
}

// ---------------- launcher ----------------
extern "C" void kernel_launch(void* const* d_in, const int* in_sizes, int n_in,
                              void* d_out, int out_size) {
    const float* x    = (const float*)d_in[0];
    const float* c1w  = (const float*)d_in[1];
    const float* c1b  = (const float*)d_in[2];
    const float* c2w  = (const float*)d_in[3];
    const float* c2b  = (const float*)d_in[4];
    const float* idw  = (const float*)d_in[5];
    const float* idb  = (const float*)d_in[6];
    const float* qw   = (const float*)d_in[7];
    const float* qb   = (const float*)d_in[8];
    const float* kw   = (const float*)d_in[9];
    const float* kb   = (const float*)d_in[10];
    const float* vw   = (const float*)d_in[11];
    const float* vb   = (const float*)d_in[12];
    const float* rel  = (const float*)d_in[13];
    const float* ln1g = (const float*)d_in[14];
    const float* ln1b = (const float*)d_in[15];
    const float* ln2g = (const float*)d_in[16];
    const float* ln2b = (const float*)d_in[17];
    const float* fw1  = (const float*)d_in[18];
    const float* fb1  = (const float*)d_in[19];
    const float* fw2  = (const float*)d_in[20];
    const float* fb2  = (const float*)d_in[21];

    float* outp = (float*)d_out;
    float* pool = outp + (size_t)B_ * C_ * N_;

    float* F; __nv_bfloat16* Hh;
    cudaGetSymbolAddress((void**)&F, g_f32);
    cudaGetSymbolAddress((void**)&Hh, g_b16);

    float* hp = F + F_HP;   float* down = F + F_DOWN;
    float* qk = F + F_QK;   float* ao   = F + F_AO;
    float* h1 = F + F_H1;   float* ff   = F + F_FF;

    cudaFuncSetAttribute(mm_gemm<4,0>, cudaFuncAttributeMaxDynamicSharedMemorySize, DSMEM_REQ);
    cudaFuncSetAttribute(mm_gemm<1,1>, cudaFuncAttributeMaxDynamicSharedMemorySize, DSMEM_REQ);
    cudaFuncSetAttribute(mm_gemm<3,1>, cudaFuncAttributeMaxDynamicSharedMemorySize, DSMEM_REQ);
    cudaFuncSetAttribute(mm_gemm<0,0>, cudaFuncAttributeMaxDynamicSharedMemorySize, DSMEM_REQ);
    cudaFuncSetAttribute(mm_gemm<2,1>, cudaFuncAttributeMaxDynamicSharedMemorySize, DSMEM_REQ);
    cudaFuncSetAttribute(mm_gemm<3,0>, cudaFuncAttributeMaxDynamicSharedMemorySize, DSMEM_REQ);

    const long long EN = (long long)E_ * N_;
    const long long NK2 = (long long)N_ * K2;

    // weight prep
    reorder_split_w2<<<23328, 256>>>(c2w, Hh + H_W2H, Hh + H_W2L);
    split_plain<<<5184, 256>>>(qw, Hh + H_QWH, Hh + H_QWL);
    split_plain<<<5184, 256>>>(kw, Hh + H_KWH, Hh + H_KWL);
    split_plain<<<5184, 256>>>(vw, Hh + H_VWH, Hh + H_VWL);
    transpose_split<<<dim3(144, 36, 1), 256>>>(fw1, Hh + H_W1TH, Hh + H_W1TL, E_, E2);
    transpose_split<<<dim3(72, 72, 1), 256>>>(fw2, Hh + H_W2TH, Hh + H_W2TL, E2, E_);

    // conv block
    conv1_relu_pad<<<90000, 256>>>(x, c1w, c1b, hp);
    im2col_gen<<<dim3(36, 72, 36), 256>>>(hp, Hh + H_IMH, Hh + H_IML);
    mm_gemm<4,0><<<dim3(324, 1, 4), 256, DSMEM_REQ>>>(
        Hh + H_W2H, Hh + H_W2L, Hh + H_IMH, Hh + H_IML, down, nullptr, nullptr,
        c2b, idb, idw, x, C_, N_, K2, 18, 18, 0, NK2, EN);

    // qkv (q, k direct bf16; v computed pre-transposed as vT = DT . vw)
    transpose_split<<<dim3(72, 36, 4), 256>>>(down, Hh + H_DTH, Hh + H_DTL, C_, N_);
    mm_gemm<1,1><<<dim3(324, 1, 4), 256, DSMEM_REQ>>>(
        Hh + H_QWH, Hh + H_QWL, Hh + H_DTH, Hh + H_DTL, nullptr, Hh + H_QH, Hh + H_QL,
        qb, nullptr, nullptr, nullptr, E_, N_, C_, 18, 18, 0, EN, EN);
    mm_gemm<1,1><<<dim3(324, 1, 4), 256, DSMEM_REQ>>>(
        Hh + H_KWH, Hh + H_KWL, Hh + H_DTH, Hh + H_DTL, nullptr, Hh + H_KH, Hh + H_KL,
        kb, nullptr, nullptr, nullptr, E_, N_, C_, 18, 18, 0, EN, EN);
    mm_gemm<3,1><<<dim3(324, 1, 4), 256, DSMEM_REQ>>>(
        Hh + H_DTH, Hh + H_DTL, Hh + H_VWH, Hh + H_VWL, nullptr, Hh + H_VTH, Hh + H_VTL,
        vb, nullptr, nullptr, nullptr, N_, E_, C_, 18, 18, EN, 0, EN);

    // attention
    mm_gemm<0,0><<<dim3(324, 1, 4), 256, DSMEM_REQ>>>(
        Hh + H_QH, Hh + H_QL, Hh + H_KH, Hh + H_KL, qk, nullptr, nullptr,
        nullptr, nullptr, nullptr, nullptr, E_, E_, N_, 18, 18, EN, EN, EN);
    softmax_bias_split<<<B_ * E_, 256>>>(qk, rel, Hh + H_ATH, Hh + H_ATL);
    mm_gemm<0,0><<<dim3(324, 1, 4), 256, DSMEM_REQ>>>(
        Hh + H_ATH, Hh + H_ATL, Hh + H_VTH, Hh + H_VTL, ao, nullptr, nullptr,
        nullptr, nullptr, nullptr, nullptr, E_, N_, E_, 18, 18, EN, EN, EN);
    add_shuffle_ln<<<B_ * C_, 256>>>(ao, down, ln1g, ln1b, h1, Hh + H_H1H, Hh + H_H1L);

    // FFN
    mm_gemm<2,1><<<dim3(2592, 1, 1), 256, DSMEM_REQ>>>(
        Hh + H_H1H, Hh + H_H1L, Hh + H_W1TH, Hh + H_W1TL, nullptr, Hh + H_MIDH, Hh + H_MIDL,
        fb1, nullptr, nullptr, nullptr, B_ * N_, E2, E_, 72, 36, 0, 0, 0);
    mm_gemm<3,0><<<dim3(1296, 1, 1), 256, DSMEM_REQ>>>(
        Hh + H_MIDH, Hh + H_MIDL, Hh + H_W2TH, Hh + H_W2TL, ff, nullptr, nullptr,
        fb2, nullptr, nullptr, nullptr, B_ * N_, E_, E2, 72, 18, 0, 0, 0);
    add_ln<<<B_ * C_, 256>>>(ff, h1, ln2g, ln2b, outp);
    maxpool_k<<<20736, 256>>>(outp, pool);
}

// round 8
// speedup vs baseline: 1.4515x; 1.2695x over previous
#include <cuda_runtime.h>
#include <cuda_bf16.h>
#include <cuda_fp16.h>
#include <cstdint>

#define B_  4
#define C_  2304
#define N_  2304
#define E_  2304
#define HW  48
#define PW  50
#define NH_ 4
#define K2  20736
#define E2  4608

// GEMM tiling: CTA 128x128x32, 8 warps (2m x 4n), warp tile 64x32
#define BM 128
#define BN 128
#define BK 32
#define TSTRIDE 40
#define TILE_BYTES (BM * TSTRIDE * 2)   // 10240
#define NSTAGE 3

// ---------------- PTX helpers ----------------
__device__ __forceinline__ uint32_t smem_u32(const void* p) {
    uint32_t a;
    asm("{ .reg .u64 t; cvta.to.shared.u64 t, %1; cvt.u32.u64 %0, t; }" : "=r"(a) : "l"(p));
    return a;
}
__device__ __forceinline__ void cp16(uint32_t dst, const void* src) {
    asm volatile("cp.async.cg.shared.global [%0], [%1], 16;" :: "r"(dst), "l"(src));
}
__device__ __forceinline__ void cp_commit() { asm volatile("cp.async.commit_group;"); }
template<int NN>
__device__ __forceinline__ void cp_wait() { asm volatile("cp.async.wait_group %0;" :: "n"(NN)); }

__device__ __forceinline__ void ldm4(uint32_t& r0, uint32_t& r1, uint32_t& r2, uint32_t& r3, uint32_t a) {
    asm volatile("ldmatrix.sync.aligned.m8n8.x4.shared.b16 {%0,%1,%2,%3}, [%4];"
                 : "=r"(r0), "=r"(r1), "=r"(r2), "=r"(r3) : "r"(a));
}
__device__ __forceinline__ void mma_bf16(float* d, uint32_t a0, uint32_t a1, uint32_t a2, uint32_t a3,
                                         uint32_t b0, uint32_t b1) {
    asm volatile("mma.sync.aligned.m16n8k16.row.col.f32.bf16.bf16.f32 "
                 "{%0,%1,%2,%3}, {%4,%5,%6,%7}, {%8,%9}, {%0,%1,%2,%3};"
                 : "+f"(d[0]), "+f"(d[1]), "+f"(d[2]), "+f"(d[3])
                 : "r"(a0), "r"(a1), "r"(a2), "r"(a3), "r"(b0), "r"(b1));
}
__device__ __forceinline__ void mma_f16(float* d, uint32_t a0, uint32_t a1, uint32_t a2, uint32_t a3,
                                        uint32_t b0, uint32_t b1) {
    asm volatile("mma.sync.aligned.m16n8k16.row.col.f32.f16.f16.f32 "
                 "{%0,%1,%2,%3}, {%4,%5,%6,%7}, {%8,%9}, {%0,%1,%2,%3};"
                 : "+f"(d[0]), "+f"(d[1]), "+f"(d[2]), "+f"(d[3])
                 : "r"(a0), "r"(a1), "r"(a2), "r"(a3), "r"(b0), "r"(b1));
}
template<int DT>
__device__ __forceinline__ void mma_any(float* d, uint32_t a0, uint32_t a1, uint32_t a2, uint32_t a3,
                                        uint32_t b0, uint32_t b1) {
    if (DT == 0) mma_bf16(d, a0, a1, a2, a3, b0, b1);
    else         mma_f16 (d, a0, a1, a2, a3, b0, b1);
}

__device__ __forceinline__ void split1(float v, __nv_bfloat16& h, __nv_bfloat16& l) {
    h = __float2bfloat16(v);
    l = __float2bfloat16(v - __bfloat162float(h));
}
__device__ __forceinline__ uint32_t pk2(__nv_bfloat16 a, __nv_bfloat16 b) {
    __nv_bfloat162 t(a, b);
    return *reinterpret_cast<uint32_t*>(&t);
}
__device__ __forceinline__ void split1h(float v, __half& h, __half& l) {
    h = __float2half(v);
    l = __float2half(v - __half2float(h));
}
__device__ __forceinline__ uint32_t pk2h(__half a, __half b) {
    __half2 t(a, b);
    return *reinterpret_cast<uint32_t*>(&t);
}

// ---------------- scratch arenas ----------------
constexpr size_t SZ_EN = (size_t)B_ * E_ * N_;
constexpr size_t SZ_W  = (size_t)E_ * E_;
constexpr size_t F_HP = 0, F_DOWN = 23040000;
constexpr size_t F_QK = F_DOWN + SZ_EN, F_AO = F_QK + SZ_EN, F_H1 = F_AO + SZ_EN;
constexpr size_t F_FF = F_H1 + SZ_EN;
constexpr size_t F_TOT = F_FF + SZ_EN;

constexpr size_t H_IM  = 0;
constexpr size_t H_W2H = H_IM + (size_t)B_ * N_ * K2;
constexpr size_t H_W2L = H_W2H + (size_t)C_ * K2;
constexpr size_t H_QWH = H_W2L + (size_t)C_ * K2, H_QWL = H_QWH + SZ_W;
constexpr size_t H_KWH = H_QWL + SZ_W, H_KWL = H_KWH + SZ_W;
constexpr size_t H_VWH = H_KWL + SZ_W, H_VWL = H_VWH + SZ_W;
constexpr size_t H_W1TH = H_VWL + SZ_W, H_W1TL = H_W1TH + 2 * SZ_W;
constexpr size_t H_W2TH = H_W1TL + 2 * SZ_W, H_W2TL = H_W2TH + 2 * SZ_W;
constexpr size_t H_DTH = H_W2TL + 2 * SZ_W, H_DTL = H_DTH + SZ_EN;
constexpr size_t H_VTH = H_DTL + SZ_EN, H_VTL = H_VTH + SZ_EN;
constexpr size_t H_QH = H_VTL + SZ_EN, H_QL = H_QH + SZ_EN;
constexpr size_t H_KH = H_QL + SZ_EN, H_KL = H_KH + SZ_EN;
constexpr size_t H_ATH = H_KL + SZ_EN, H_ATL = H_ATH + SZ_EN;
constexpr size_t H_H1F = H_ATL + SZ_EN;
constexpr size_t H_MID = H_H1F + SZ_EN;
constexpr size_t H_TOT = H_MID + 2 * SZ_EN;

__device__ __align__(256) float    g_f32[F_TOT];
__device__ __align__(256) uint16_t g_b16[H_TOT];

// ---------------- GEMM: D[m][n] = sum_k A[m,k]*B[n,k] ----------------
// MODE: 0 = 3-term (Ah,Al,Bh,Bl); 1 = 2-term A-split (Ah,Al,B in Bh); 2 = 2-term B-split (A in Ah, Bh,Bl)
// DT: 0 bf16, 1 f16
// EPI: 0 none, 1 +b1[row], 2 +b1[col]+relu, 3 +b1[col], 4 conv(+b1[r]+b2[r]+b3[r]*b4[z*N_+n], relu)
// OUTB: 0 fp32 C; 1 bf16 split pair (Oh,Ol); 2 fp16 single (Oh)
template<int MODE, int DT, int EPI, int OUTB>
__global__ void __launch_bounds__(256, 1) mm_gemm(
    const uint16_t* __restrict__ Ah, const uint16_t* __restrict__ Al,
    const uint16_t* __restrict__ Bh, const uint16_t* __restrict__ Bl,
    float* __restrict__ C,
    uint16_t* __restrict__ Oh, uint16_t* __restrict__ Ol,
    const float* __restrict__ b1, const float* __restrict__ b2,
    const float* __restrict__ b3, const float* __restrict__ b4,
    int M, int N, int K, int tilesM, int tilesN,
    long long sA, long long sB, long long sC)
{
    constexpr int NA = (MODE == 2) ? 1 : 2;
    constexpr int NB = (MODE == 1) ? 1 : 2;
    constexpr int STB = (NA + NB) * TILE_BYTES;

    extern __shared__ char smem[];
    const uint32_t sb = smem_u32(smem);
    const int tid = threadIdx.x;
    const int wid = tid >> 5, lane = tid & 31;
    const int wm = wid >> 2, wn = wid & 3;
    const int z = blockIdx.z;

    int bid = blockIdx.x;
    const int GROUP = 8;
    int npg = GROUP * tilesN;
    int grp = bid / npg, rem = bid - grp * npg;
    int gs = tilesM - grp * GROUP; if (gs > GROUP) gs = GROUP;
    int mt = grp * GROUP + rem % gs;
    int nt = rem / gs;
    const int row0 = mt * BM, col0 = nt * BN;

    Ah += (size_t)z * sA; if (NA == 2) Al += (size_t)z * sA;
    Bh += (size_t)z * sB; if (NB == 2) Bl += (size_t)z * sB;

    const int crow = tid >> 1;
    const int cbyte = (tid & 1) * 32;
    const uint32_t dst_off = (uint32_t)crow * (TSTRIDE * 2) + cbyte;

    auto prefetch = [&](int slab, int st) {
        const int k0 = slab * BK;
        uint32_t base = sb + st * STB + dst_off;
        const char* a0 = (const char*)(Ah + (size_t)(row0 + crow) * K + k0) + cbyte;
        cp16(base, a0); cp16(base + 16, a0 + 16);
        if (NA == 2) {
            const char* a1 = (const char*)(Al + (size_t)(row0 + crow) * K + k0) + cbyte;
            cp16(base + TILE_BYTES, a1); cp16(base + TILE_BYTES + 16, a1 + 16);
        }
        uint32_t bb = base + NA * TILE_BYTES;
        const char* b0 = (const char*)(Bh + (size_t)(col0 + crow) * K + k0) + cbyte;
        cp16(bb, b0); cp16(bb + 16, b0 + 16);
        if (NB == 2) {
            const char* b1p = (const char*)(Bl + (size_t)(col0 + crow) * K + k0) + cbyte;
            cp16(bb + TILE_BYTES, b1p); cp16(bb + TILE_BYTES + 16, b1p + 16);
        }
        cp_commit();
    };

    float acc[4][4][4];
    #pragma unroll
    for (int a = 0; a < 4; a++)
        #pragma unroll
        for (int b = 0; b < 4; b++)
            #pragma unroll
            for (int c = 0; c < 4; c++) acc[a][b][c] = 0.f;

    const int S = K / BK;
    prefetch(0, 0);
    prefetch(1, 1);
    cp_wait<1>();
    __syncthreads();

    const uint32_t a_row = (uint32_t)(wm * 64 + (lane & 15));
    const uint32_t a_kh  = (uint32_t)(lane >> 4) * 16;
    const uint32_t b_row = (uint32_t)(wn * 32 + (lane & 7) + ((lane >> 4) & 1) * 8);
    const uint32_t b_kh  = (uint32_t)((lane >> 3) & 1) * 16;

    for (int i = 0; i < S; i++) {
        const uint32_t st = sb + (i % NSTAGE) * STB;
        const uint32_t aH = st + a_row * (TSTRIDE * 2) + a_kh;
        const uint32_t bH = st + NA * TILE_BYTES + b_row * (TSTRIDE * 2) + b_kh;

        #pragma unroll
        for (int ks = 0; ks < 2; ks++) {
            const uint32_t ko = ks * 32;
            uint32_t ah[4][4], al[4][4], bh2[2][4], bl2[2][4];
            #pragma unroll
            for (int mf = 0; mf < 4; mf++) {
                uint32_t adr = aH + ko + (uint32_t)mf * 16 * (TSTRIDE * 2);
                ldm4(ah[mf][0], ah[mf][1], ah[mf][2], ah[mf][3], adr);
                if (NA == 2) ldm4(al[mf][0], al[mf][1], al[mf][2], al[mf][3], adr + TILE_BYTES);
            }
            #pragma unroll
            for (int p = 0; p < 2; p++) {
                uint32_t adr = bH + ko + (uint32_t)p * 16 * (TSTRIDE * 2);
                ldm4(bh2[p][0], bh2[p][1], bh2[p][2], bh2[p][3], adr);
                if (NB == 2) ldm4(bl2[p][0], bl2[p][1], bl2[p][2], bl2[p][3], adr + TILE_BYTES);
            }
            #pragma unroll
            for (int mf = 0; mf < 4; mf++)
                #pragma unroll
                for (int nf = 0; nf < 4; nf++) {
                    const int p = nf >> 1, q = (nf & 1) * 2;
                    uint32_t h0 = bh2[p][q], h1 = bh2[p][q + 1];
                    mma_any<DT>(acc[mf][nf], ah[mf][0], ah[mf][1], ah[mf][2], ah[mf][3], h0, h1);
                    if (MODE == 0) {
                        uint32_t l0 = bl2[p][q], l1 = bl2[p][q + 1];
                        mma_any<DT>(acc[mf][nf], ah[mf][0], ah[mf][1], ah[mf][2], ah[mf][3], l0, l1);
                        mma_any<DT>(acc[mf][nf], al[mf][0], al[mf][1], al[mf][2], al[mf][3], h0, h1);
                    } else if (MODE == 1) {
                        mma_any<DT>(acc[mf][nf], al[mf][0], al[mf][1], al[mf][2], al[mf][3], h0, h1);
                    } else {
                        uint32_t l0 = bl2[p][q], l1 = bl2[p][q + 1];
                        mma_any<DT>(acc[mf][nf], ah[mf][0], ah[mf][1], ah[mf][2], ah[mf][3], l0, l1);
                    }
                }
        }
        if (i + 2 < S) prefetch(i + 2, (i + 2) % NSTAGE);
        if (i + 1 < S) cp_wait<1>(); else cp_wait<0>();
        __syncthreads();
    }

    // epilogue
    #pragma unroll
    for (int mf = 0; mf < 4; mf++) {
        #pragma unroll
        for (int h = 0; h < 2; h++) {
            const int r = row0 + wm * 64 + mf * 16 + (lane >> 2) + h * 8;
            float rbias = 0.f, iw = 0.f;
            if (EPI == 1) rbias = b1[r];
            if (EPI == 4) { rbias = b1[r] + b2[r]; iw = b3[r]; }
            const float* xrow = (EPI == 4) ? (b4 + (size_t)z * N_) : nullptr;
            #pragma unroll
            for (int nf = 0; nf < 4; nf++) {
                const int cidx = col0 + wn * 32 + nf * 8 + (lane & 3) * 2;
                float2 o;
                o.x = acc[mf][nf][h * 2 + 0];
                o.y = acc[mf][nf][h * 2 + 1];
                if (EPI == 1) { o.x += rbias; o.y += rbias; }
                if (EPI == 2 || EPI == 3) {
                    float2 bc = *(const float2*)(b1 + cidx);
                    o.x += bc.x; o.y += bc.y;
                }
                if (EPI == 4) {
                    float2 xv = *(const float2*)(xrow + cidx);
                    o.x += rbias + iw * xv.x; o.y += rbias + iw * xv.y;
                }
                if (EPI == 2 || EPI == 4) { o.x = fmaxf(o.x, 0.f); o.y = fmaxf(o.y, 0.f); }
                size_t off = (size_t)z * sC + (size_t)r * N + cidx;
                if (OUTB == 0) {
                    *(float2*)(C + off) = o;
                } else if (OUTB == 1) {
                    __nv_bfloat16 hx, lx, hy, ly;
                    split1(o.x, hx, lx); split1(o.y, hy, ly);
                    *(uint32_t*)(Oh + off) = pk2(hx, hy);
                    *(uint32_t*)(Ol + off) = pk2(lx, ly);
                } else {
                    *(uint32_t*)(Oh + off) = pk2h(__float2half(o.x), __float2half(o.y));
                }
            }
        }
    }
}

// ---------------- conv1 (3x3, 1->C) + ReLU, zero-padded ----------------
__global__ void conv1_relu_pad(const float* __restrict__ x, const float* __restrict__ w,
                               const float* __restrict__ bia, float* __restrict__ hp) {
    int idx = blockIdx.x * 256 + threadIdx.x;
    int b = idx / (C_ * PW * PW);
    int rem = idx - b * (C_ * PW * PW);
    int c = rem / (PW * PW);
    int p = rem - c * (PW * PW);
    int yy = p / PW, xx = p - yy * PW;
    float out = 0.f;
    if (yy >= 1 && yy <= HW && xx >= 1 && xx <= HW) {
        int y = yy - 1, x0 = xx - 1;
        float acc = bia[c];
        const float* xb = x + b * HW * HW;
        #pragma unroll
        for (int ky = 0; ky < 3; ky++) {
            int iy = y + ky - 1;
            if (iy < 0 || iy >= HW) continue;
            #pragma unroll
            for (int kx = 0; kx < 3; kx++) {
                int ix = x0 + kx - 1;
                if (ix < 0 || ix >= HW) continue;
                acc += w[c * 9 + ky * 3 + kx] * xb[iy * HW + ix];
            }
        }
        out = fmaxf(acc, 0.f);
    }
    hp[idx] = out;
}

// ---------------- im2col^T, fp16 single ----------------
__global__ void im2col_f16(const float* __restrict__ hp, uint16_t* __restrict__ bb) {
    __shared__ float s[64][33];
    int t = threadIdx.x;
    int ic0 = blockIdx.x * 64, n0 = blockIdx.y * 32;
    int zo = blockIdx.z, z = zo / 9, off = zo - z * 9;
    int ky = off / 3, kx = off - ky * 3;
    const float* hpz = hp + (size_t)z * C_ * (PW * PW);
    #pragma unroll
    for (int p = 0; p < 2; p++) {
        int icl = p * 32 + (t >> 3);
        int nl = (t & 7) * 4;
        const float* base = hpz + (size_t)(ic0 + icl) * (PW * PW) + ky * PW + kx;
        #pragma unroll
        for (int i = 0; i < 4; i++) {
            int n = n0 + nl + i;
            int y = n / HW, xx = n - y * HW;
            s[icl][nl + i] = base[y * PW + xx];
        }
    }
    __syncthreads();
    int n = t >> 3, icc = (t & 7) * 8;
    size_t o = (size_t)z * ((size_t)N_ * K2) + (size_t)(n0 + n) * K2 + (size_t)off * C_ + ic0 + icc;
    uint4 u;
    u.x = pk2h(__float2half(s[icc + 0][n]), __float2half(s[icc + 1][n]));
    u.y = pk2h(__float2half(s[icc + 2][n]), __float2half(s[icc + 3][n]));
    u.z = pk2h(__float2half(s[icc + 4][n]), __float2half(s[icc + 5][n]));
    u.w = pk2h(__float2half(s[icc + 6][n]), __float2half(s[icc + 7][n]));
    *(uint4*)(bb + o) = u;
}

// ---------------- W2 reorder + fp16 split ----------------
__global__ void reorder_split_w2(const float* __restrict__ w2,
                                 uint16_t* __restrict__ oh, uint16_t* __restrict__ ol) {
    int id = blockIdx.x * 256 + threadIdx.x;
    int c = id / (9 * 288);
    int rem = id - c * (9 * 288);
    int off = rem / 288, icb = rem - off * 288;
    const float* src = w2 + (size_t)c * K2 + (size_t)icb * 72 + off;
    __half hh[8], ll[8];
    #pragma unroll
    for (int i = 0; i < 8; i++) split1h(src[i * 9], hh[i], ll[i]);
    size_t o = (size_t)c * K2 + (size_t)off * C_ + (size_t)icb * 8;
    uint4 uh, ul;
    uh.x = pk2h(hh[0], hh[1]); uh.y = pk2h(hh[2], hh[3]); uh.z = pk2h(hh[4], hh[5]); uh.w = pk2h(hh[6], hh[7]);
    ul.x = pk2h(ll[0], ll[1]); ul.y = pk2h(ll[2], ll[3]); ul.z = pk2h(ll[4], ll[5]); ul.w = pk2h(ll[6], ll[7]);
    *(uint4*)(oh + o) = uh;
    *(uint4*)(ol + o) = ul;
}

// ---------------- plain bf16 split (qkv weights) ----------------
__global__ void split_plain(const float* __restrict__ src,
                            uint16_t* __restrict__ oh, uint16_t* __restrict__ ol) {
    size_t i4 = (size_t)blockIdx.x * 256 + threadIdx.x;
    float4 v = *(const float4*)(src + i4 * 4);
    __nv_bfloat16 h0, h1, h2, h3, l0, l1, l2, l3;
    split1(v.x, h0, l0); split1(v.y, h1, l1); split1(v.z, h2, l2); split1(v.w, h3, l3);
    uint2 uh, ul;
    uh.x = pk2(h0, h1); uh.y = pk2(h2, h3);
    ul.x = pk2(l0, l1); ul.y = pk2(l2, l3);
    *(uint2*)(oh + i4 * 4) = uh;
    *(uint2*)(ol + i4 * 4) = ul;
}

// ---------------- transpose + bf16 split ----------------
__global__ void transpose_split(const float* __restrict__ in,
                                uint16_t* __restrict__ oh, uint16_t* __restrict__ ol,
                                int R, int Cc) {
    __shared__ float s[64][33];
    int t = threadIdx.x;
    int c0 = blockIdx.x * 32, r0 = blockIdx.y * 64;
    size_t zb = (size_t)blockIdx.z * R * Cc;
    {
        int r = t >> 2, cl = (t & 3) * 8;
        const float* src = in + zb + (size_t)(r0 + r) * Cc + c0 + cl;
        float4 a = *(const float4*)src;
        float4 b = *(const float4*)(src + 4);
        s[r][cl + 0] = a.x; s[r][cl + 1] = a.y; s[r][cl + 2] = a.z; s[r][cl + 3] = a.w;
        s[r][cl + 4] = b.x; s[r][cl + 5] = b.y; s[r][cl + 6] = b.z; s[r][cl + 7] = b.w;
    }
    __syncthreads();
    int c = t >> 3, rl = (t & 7) * 8;
    __nv_bfloat16 hh[8], ll[8];
    #pragma unroll
    for (int i = 0; i < 8; i++) split1(s[rl + i][c], hh[i], ll[i]);
    size_t o = zb + (size_t)(c0 + c) * R + r0 + rl;
    uint4 uh, ul;
    uh.x = pk2(hh[0], hh[1]); uh.y = pk2(hh[2], hh[3]); uh.z = pk2(hh[4], hh[5]); uh.w = pk2(hh[6], hh[7]);
    ul.x = pk2(ll[0], ll[1]); ul.y = pk2(ll[2], ll[3]); ul.z = pk2(ll[4], ll[5]); ul.w = pk2(ll[6], ll[7]);
    *(uint4*)(oh + o) = uh;
    *(uint4*)(ol + o) = ul;
}

// ---------------- transpose + fp16 split (FFN weights) ----------------
__global__ void transpose_split_f16(const float* __restrict__ in,
                                    uint16_t* __restrict__ oh, uint16_t* __restrict__ ol,
                                    int R, int Cc) {
    __shared__ float s[64][33];
    int t = threadIdx.x;
    int c0 = blockIdx.x * 32, r0 = blockIdx.y * 64;
    {
        int r = t >> 2, cl = (t & 3) * 8;
        const float* src = in + (size_t)(r0 + r) * Cc + c0 + cl;
        float4 a = *(const float4*)src;
        float4 b = *(const float4*)(src + 4);
        s[r][cl + 0] = a.x; s[r][cl + 1] = a.y; s[r][cl + 2] = a.z; s[r][cl + 3] = a.w;
        s[r][cl + 4] = b.x; s[r][cl + 5] = b.y; s[r][cl + 6] = b.z; s[r][cl + 7] = b.w;
    }
    __syncthreads();
    int c = t >> 3, rl = (t & 7) * 8;
    __half hh[8], ll[8];
    #pragma unroll
    for (int i = 0; i < 8; i++) split1h(s[rl + i][c], hh[i], ll[i]);
    size_t o = (size_t)(c0 + c) * R + r0 + rl;
    uint4 uh, ul;
    uh.x = pk2h(hh[0], hh[1]); uh.y = pk2h(hh[2], hh[3]); uh.z = pk2h(hh[4], hh[5]); uh.w = pk2h(hh[6], hh[7]);
    ul.x = pk2h(ll[0], ll[1]); ul.y = pk2h(ll[2], ll[3]); ul.z = pk2h(ll[4], ll[5]); ul.w = pk2h(ll[6], ll[7]);
    *(uint4*)(oh + o) = uh;
    *(uint4*)(ol + o) = ul;
}

// ---------------- reductions ----------------
__device__ __forceinline__ float block_sum(float v, float* red) {
    int tid = threadIdx.x;
    red[tid] = v; __syncthreads();
    #pragma unroll
    for (int s = 128; s > 0; s >>= 1) { if (tid < s) red[tid] += red[tid + s]; __syncthreads(); }
    float r = red[0]; __syncthreads();
    return r;
}
__device__ __forceinline__ float block_max(float v, float* red) {
    int tid = threadIdx.x;
    red[tid] = v; __syncthreads();
    #pragma unroll
    for (int s = 128; s > 0; s >>= 1) { if (tid < s) red[tid] = fmaxf(red[tid], red[tid + s]); __syncthreads(); }
    float r = red[0]; __syncthreads();
    return r;
}

// ---------------- softmax with analytic rel-pos bias -> bf16 split ----------------
__global__ void softmax_bias_split(const float* __restrict__ qk, const float* __restrict__ rel,
                                   uint16_t* __restrict__ oh, uint16_t* __restrict__ ol) {
    __shared__ float red[256];
    int row = blockIdx.x;
    int b = row / E_;
    int i = row - b * E_;
    int ci = i / HW, wi = i - ci * HW;
    const float* rp = qk + (size_t)row * E_;
    int tid = threadIdx.x;
    float v[9];
    float mx = -3.4e38f;
    #pragma unroll
    for (int r = 0; r < 9; r++) {
        int j = r * 256 + tid;
        int cj = j / HW, wj = j - cj * HW;
        int idx = (ci - cj + HW - 1) * (2 * HW - 1) + (wi - wj + HW - 1);
        v[r] = rp[j] * (1.0f / 48.0f) + rel[idx * NH_ + b];
        mx = fmaxf(mx, v[r]);
    }
    mx = block_max(mx, red);
    float s = 0.f;
    #pragma unroll
    for (int r = 0; r < 9; r++) { v[r] = __expf(v[r] - mx); s += v[r]; }
    s = block_sum(s, red);
    float inv = 1.f / s;
    #pragma unroll
    for (int r = 0; r < 9; r++) {
        int j = r * 256 + tid;
        __nv_bfloat16 h, l;
        split1(v[r] * inv, h, l);
        oh[(size_t)row * E_ + j] = *(uint16_t*)&h;
        ol[(size_t)row * E_ + j] = *(uint16_t*)&l;
    }
}

// ---------------- shuffle + residual + LN1 -> fp32 + fp16 single ----------------
__global__ void add_shuffle_ln(const float* __restrict__ ao, const float* __restrict__ down,
                               const float* __restrict__ g, const float* __restrict__ be,
                               float* __restrict__ h1, uint16_t* __restrict__ of16) {
    __shared__ float red[256];
    int m = blockIdx.x;
    int e = m >> 2, bs = m & 3;
    const float* ar = ao + ((size_t)bs * E_ + e) * N_;
    const float* dr = down + (size_t)m * N_;
    int tid = threadIdx.x;
    float v[9]; float s = 0.f;
    #pragma unroll
    for (int r = 0; r < 9; r++) { int j = r * 256 + tid; v[r] = ar[j] + dr[j]; s += v[r]; }
    float mean = block_sum(s, red) * (1.f / N_);
    float s2 = 0.f;
    #pragma unroll
    for (int r = 0; r < 9; r++) { float d = v[r] - mean; s2 += d * d; }
    float var = block_sum(s2, red) * (1.f / N_);
    float rstd = rsqrtf(var + 1e-5f);
    #pragma unroll
    for (int r = 0; r < 9; r++) {
        int j = r * 256 + tid;
        float o = (v[r] - mean) * rstd * g[j] + be[j];
        h1[(size_t)m * N_ + j] = o;
        __half hf = __float2half(o);
        of16[(size_t)m * N_ + j] = *(uint16_t*)&hf;
    }
}

// ---------------- residual + LN2 ----------------
__global__ void add_ln(const float* __restrict__ f, const float* __restrict__ h1,
                       const float* __restrict__ g, const float* __restrict__ be,
                       float* __restrict__ out) {
    __shared__ float red[256];
    int m = blockIdx.x;
    const float* fr = f + (size_t)m * N_;
    const float* hr = h1 + (size_t)m * N_;
    int tid = threadIdx.x;
    float v[9]; float s = 0.f;
    #pragma unroll
    for (int r = 0; r < 9; r++) { int j = r * 256 + tid; v[r] = fr[j] + hr[j]; s += v[r]; }
    float mean = block_sum(s, red) * (1.f / N_);
    float s2 = 0.f;
    #pragma unroll
    for (int r = 0; r < 9; r++) { float d = v[r] - mean; s2 += d * d; }
    float var = block_sum(s2, red) * (1.f / N_);
    float rstd = rsqrtf(var + 1e-5f);
    #pragma unroll
    for (int r = 0; r < 9; r++) {
        int j = r * 256 + tid;
        out[(size_t)m * N_ + j] = (v[r] - mean) * rstd * g[j] + be[j];
    }
}

// ---------------- maxpool 2x2 ----------------
__global__ void maxpool_k(const float* __restrict__ out, float* __restrict__ p) {
    int idx = blockIdx.x * 256 + threadIdx.x;
    int bc = idx / (24 * 24);
    int r = idx - bc * 576;
    int y = r / 24, x = r - y * 24;
    const float* o = out + (size_t)bc * N_ + (2 * y) * HW + 2 * x;
    p[idx] = fmaxf(fmaxf(o[0], o[1]), fmaxf(o[HW], o[HW + 1]));
}

// ---------------- launcher ----------------
extern "C" void kernel_launch(void* const* d_in, const int* in_sizes, int n_in,
                              void* d_out, int out_size) {
    const float* x    = (const float*)d_in[0];
    const float* c1w  = (const float*)d_in[1];
    const float* c1b  = (const float*)d_in[2];
    const float* c2w  = (const float*)d_in[3];
    const float* c2b  = (const float*)d_in[4];
    const float* idw  = (const float*)d_in[5];
    const float* idb  = (const float*)d_in[6];
    const float* qw   = (const float*)d_in[7];
    const float* qb   = (const float*)d_in[8];
    const float* kw   = (const float*)d_in[9];
    const float* kb   = (const float*)d_in[10];
    const float* vw   = (const float*)d_in[11];
    const float* vb   = (const float*)d_in[12];
    const float* rel  = (const float*)d_in[13];
    const float* ln1g = (const float*)d_in[14];
    const float* ln1b = (const float*)d_in[15];
    const float* ln2g = (const float*)d_in[16];
    const float* ln2b = (const float*)d_in[17];
    const float* fw1  = (const float*)d_in[18];
    const float* fb1  = (const float*)d_in[19];
    const float* fw2  = (const float*)d_in[20];
    const float* fb2  = (const float*)d_in[21];

    float* outp = (float*)d_out;
    float* pool = outp + (size_t)B_ * C_ * N_;

    float* F; uint16_t* Hh;
    cudaGetSymbolAddress((void**)&F, g_f32);
    cudaGetSymbolAddress((void**)&Hh, g_b16);

    float* hp = F + F_HP;   float* down = F + F_DOWN;
    float* qk = F + F_QK;   float* ao   = F + F_AO;
    float* h1 = F + F_H1;   float* ff   = F + F_FF;

    const int SM4 = NSTAGE * 4 * TILE_BYTES;
    const int SM3 = NSTAGE * 3 * TILE_BYTES;
    cudaFuncSetAttribute(mm_gemm<1,1,4,0>, cudaFuncAttributeMaxDynamicSharedMemorySize, SM3);
    cudaFuncSetAttribute(mm_gemm<0,0,1,1>, cudaFuncAttributeMaxDynamicSharedMemorySize, SM4);
    cudaFuncSetAttribute(mm_gemm<0,0,3,1>, cudaFuncAttributeMaxDynamicSharedMemorySize, SM4);
    cudaFuncSetAttribute(mm_gemm<0,0,0,0>, cudaFuncAttributeMaxDynamicSharedMemorySize, SM4);
    cudaFuncSetAttribute(mm_gemm<2,1,2,2>, cudaFuncAttributeMaxDynamicSharedMemorySize, SM3);
    cudaFuncSetAttribute(mm_gemm<2,1,3,0>, cudaFuncAttributeMaxDynamicSharedMemorySize, SM3);

    const long long EN = (long long)E_ * N_;
    const long long NK2 = (long long)N_ * K2;

    // weight prep
    reorder_split_w2<<<23328, 256>>>(c2w, Hh + H_W2H, Hh + H_W2L);
    split_plain<<<5184, 256>>>(qw, Hh + H_QWH, Hh + H_QWL);
    split_plain<<<5184, 256>>>(kw, Hh + H_KWH, Hh + H_KWL);
    split_plain<<<5184, 256>>>(vw, Hh + H_VWH, Hh + H_VWL);
    transpose_split_f16<<<dim3(144, 36, 1), 256>>>(fw1, Hh + H_W1TH, Hh + H_W1TL, E_, E2);
    transpose_split_f16<<<dim3(72, 72, 1), 256>>>(fw2, Hh + H_W2TH, Hh + H_W2TL, E2, E_);

    // conv block (2-term fp16: W2 split, im2col single)
    conv1_relu_pad<<<90000, 256>>>(x, c1w, c1b, hp);
    im2col_f16<<<dim3(36, 72, 36), 256>>>(hp, Hh + H_IM);
    mm_gemm<1,1,4,0><<<dim3(324, 1, 4), 256, SM3>>>(
        Hh + H_W2H, Hh + H_W2L, Hh + H_IM, nullptr, down, nullptr, nullptr,
        c2b, idb, idw, x, C_, N_, K2, 18, 18, 0, NK2, EN);

    // qkv (3-term bf16)
    transpose_split<<<dim3(72, 36, 4), 256>>>(down, Hh + H_DTH, Hh + H_DTL, C_, N_);
    mm_gemm<0,0,1,1><<<dim3(324, 1, 4), 256, SM4>>>(
        Hh + H_QWH, Hh + H_QWL, Hh + H_DTH, Hh + H_DTL, nullptr, Hh + H_QH, Hh + H_QL,
        qb, nullptr, nullptr, nullptr, E_, N_, C_, 18, 18, 0, EN, EN);
    mm_gemm<0,0,1,1><<<dim3(324, 1, 4), 256, SM4>>>(
        Hh + H_KWH, Hh + H_KWL, Hh + H_DTH, Hh + H_DTL, nullptr, Hh + H_KH, Hh + H_KL,
        kb, nullptr, nullptr, nullptr, E_, N_, C_, 18, 18, 0, EN, EN);
    mm_gemm<0,0,3,1><<<dim3(324, 1, 4), 256, SM4>>>(
        Hh + H_DTH, Hh + H_DTL, Hh + H_VWH, Hh + H_VWL, nullptr, Hh + H_VTH, Hh + H_VTL,
        vb, nullptr, nullptr, nullptr, N_, E_, C_, 18, 18, EN, 0, EN);

    // attention (3-term bf16)
    mm_gemm<0,0,0,0><<<dim3(324, 1, 4), 256, SM4>>>(
        Hh + H_QH, Hh + H_QL, Hh + H_KH, Hh + H_KL, qk, nullptr, nullptr,
        nullptr, nullptr, nullptr, nullptr, E_, E_, N_, 18, 18, EN, EN, EN);
    softmax_bias_split<<<B_ * E_, 256>>>(qk, rel, Hh + H_ATH, Hh + H_ATL);
    mm_gemm<0,0,0,0><<<dim3(324, 1, 4), 256, SM4>>>(
        Hh + H_ATH, Hh + H_ATL, Hh + H_VTH, Hh + H_VTL, ao, nullptr, nullptr,
        nullptr, nullptr, nullptr, nullptr, E_, N_, E_, 18, 18, EN, EN, EN);
    add_shuffle_ln<<<B_ * C_, 256>>>(ao, down, ln1g, ln1b, h1, Hh + H_H1F);

    // FFN (2-term fp16: activations single, weights split)
    mm_gemm<2,1,2,2><<<dim3(2592, 1, 1), 256, SM3>>>(
        Hh + H_H1F, nullptr, Hh + H_W1TH, Hh + H_W1TL, nullptr, Hh + H_MID, nullptr,
        fb1, nullptr, nullptr, nullptr, B_ * N_, E2, E_, 72, 36, 0, 0, 0);
    mm_gemm<2,1,3,0><<<dim3(1296, 1, 1), 256, SM3>>>(
        Hh + H_MID, nullptr, Hh + H_W2TH, Hh + H_W2TL, ff, nullptr, nullptr,
        fb2, nullptr, nullptr, nullptr, B_ * N_, E_, E2, 72, 18, 0, 0, 0);
    add_ln<<<B_ * C_, 256>>>(ff, h1, ln2g, ln2b, outp);
    maxpool_k<<<20736, 256>>>(outp, pool);
}

// round 12
// speedup vs baseline: 1.6185x; 1.1150x over previous
#include <cuda_runtime.h>
#include <cuda_bf16.h>
#include <cuda_fp16.h>
#include <cstdint>

#define B_  4
#define C_  2304
#define N_  2304
#define E_  2304
#define HW  48
#define PW  50
#define NH_ 4
#define K2  20736
#define E2  4608

// GEMM tiling: CTA 128x128x32, 8 warps (2m x 4n), warp tile 64x32
#define BM 128
#define BN 128
#define BK 32
#define TSTRIDE 40
#define TILE_BYTES (BM * TSTRIDE * 2)   // 10240
#define NSTAGE 3

// ---------------- PTX helpers ----------------
__device__ __forceinline__ uint32_t smem_u32(const void* p) {
    uint32_t a;
    asm("{ .reg .u64 t; cvta.to.shared.u64 t, %1; cvt.u32.u64 %0, t; }" : "=r"(a) : "l"(p));
    return a;
}
__device__ __forceinline__ void cp16(uint32_t dst, const void* src) {
    asm volatile("cp.async.cg.shared.global [%0], [%1], 16;" :: "r"(dst), "l"(src));
}
__device__ __forceinline__ void cp_commit() { asm volatile("cp.async.commit_group;"); }
template<int NN>
__device__ __forceinline__ void cp_wait() { asm volatile("cp.async.wait_group %0;" :: "n"(NN)); }

__device__ __forceinline__ void ldm4(uint32_t& r0, uint32_t& r1, uint32_t& r2, uint32_t& r3, uint32_t a) {
    asm volatile("ldmatrix.sync.aligned.m8n8.x4.shared.b16 {%0,%1,%2,%3}, [%4];"
                 : "=r"(r0), "=r"(r1), "=r"(r2), "=r"(r3) : "r"(a));
}
__device__ __forceinline__ void mma_bf16(float* d, uint32_t a0, uint32_t a1, uint32_t a2, uint32_t a3,
                                         uint32_t b0, uint32_t b1) {
    asm volatile("mma.sync.aligned.m16n8k16.row.col.f32.bf16.bf16.f32 "
                 "{%0,%1,%2,%3}, {%4,%5,%6,%7}, {%8,%9}, {%0,%1,%2,%3};"
                 : "+f"(d[0]), "+f"(d[1]), "+f"(d[2]), "+f"(d[3])
                 : "r"(a0), "r"(a1), "r"(a2), "r"(a3), "r"(b0), "r"(b1));
}
__device__ __forceinline__ void mma_f16(float* d, uint32_t a0, uint32_t a1, uint32_t a2, uint32_t a3,
                                        uint32_t b0, uint32_t b1) {
    asm volatile("mma.sync.aligned.m16n8k16.row.col.f32.f16.f16.f32 "
                 "{%0,%1,%2,%3}, {%4,%5,%6,%7}, {%8,%9}, {%0,%1,%2,%3};"
                 : "+f"(d[0]), "+f"(d[1]), "+f"(d[2]), "+f"(d[3])
                 : "r"(a0), "r"(a1), "r"(a2), "r"(a3), "r"(b0), "r"(b1));
}
template<int DT>
__device__ __forceinline__ void mma_any(float* d, uint32_t a0, uint32_t a1, uint32_t a2, uint32_t a3,
                                        uint32_t b0, uint32_t b1) {
    if (DT == 0) mma_bf16(d, a0, a1, a2, a3, b0, b1);
    else         mma_f16 (d, a0, a1, a2, a3, b0, b1);
}

__device__ __forceinline__ void split1(float v, __nv_bfloat16& h, __nv_bfloat16& l) {
    h = __float2bfloat16(v);
    l = __float2bfloat16(v - __bfloat162float(h));
}
__device__ __forceinline__ uint32_t pk2(__nv_bfloat16 a, __nv_bfloat16 b) {
    __nv_bfloat162 t(a, b);
    return *reinterpret_cast<uint32_t*>(&t);
}
__device__ __forceinline__ void split1h(float v, __half& h, __half& l) {
    h = __float2half(v);
    l = __float2half(v - __half2float(h));
}
__device__ __forceinline__ uint32_t pk2h(__half a, __half b) {
    __half2 t(a, b);
    return *reinterpret_cast<uint32_t*>(&t);
}

// ---------------- scratch arenas (uint16 units) ----------------
constexpr size_t SZ_EN = (size_t)B_ * E_ * N_;
constexpr size_t SZ_W  = (size_t)E_ * E_;
constexpr size_t F_HP = 0, F_DOWN = 23040000;
constexpr size_t F_QK = F_DOWN + SZ_EN, F_AO = F_QK + SZ_EN, F_H1 = F_AO + SZ_EN;
constexpr size_t F_FF = F_H1 + SZ_EN;
constexpr size_t F_TOT = F_FF + SZ_EN;

constexpr size_t H_IM  = 0;
constexpr size_t H_W2H = H_IM + (size_t)B_ * N_ * K2;
constexpr size_t H_W2L = H_W2H + (size_t)C_ * K2;
constexpr size_t H_QWH = H_W2L + (size_t)C_ * K2, H_QWL = H_QWH + SZ_W;
constexpr size_t H_KWH = H_QWL + SZ_W, H_KWL = H_KWH + SZ_W;
constexpr size_t H_VWH = H_KWL + SZ_W, H_VWL = H_VWH + SZ_W;
constexpr size_t H_W1TH = H_VWL + SZ_W, H_W1TL = H_W1TH + 2 * SZ_W;
constexpr size_t H_W2TH = H_W1TL + 2 * SZ_W, H_W2TL = H_W2TH + 2 * SZ_W;
constexpr size_t H_DT  = H_W2TL + 2 * SZ_W;                  // fp16 single down^T
constexpr size_t H_VT  = H_DT + SZ_EN;                       // fp16 single v^T
constexpr size_t H_QH  = H_VT + SZ_EN, H_QL = H_QH + SZ_EN;  // fp16 split q
constexpr size_t H_K   = H_QL + SZ_EN;                       // fp16 single k
constexpr size_t H_ATH = H_K + SZ_EN, H_ATL = H_ATH + SZ_EN; // fp16 split attn
constexpr size_t H_H1F = H_ATL + SZ_EN;                      // fp16 single h1
constexpr size_t H_MID = H_H1F + SZ_EN;                      // fp16 single mid
constexpr size_t H_TOT = H_MID + 2 * SZ_EN;

__device__ __align__(256) float    g_f32[F_TOT];
__device__ __align__(256) uint16_t g_b16[H_TOT];

// ---------------- GEMM: D[m][n] = sum_k A[m,k]*B[n,k] ----------------
// MODE: 0 = 3-term (Ah,Al,Bh,Bl); 1 = 2-term A-split (Ah,Al; B single in Bh); 2 = 2-term B-split (A single; Bh,Bl)
// DT: 0 bf16, 1 f16
// EPI: 0 none, 1 +b1[row], 2 +b1[col]+relu, 3 +b1[col], 4 conv(+b1[r]+b2[r]+b3[r]*b4[z*N_+n], relu)
// OUTB: 0 fp32 C; 1 bf16 split pair; 2 fp16 single (Oh); 3 fp16 split pair (Oh,Ol)
template<int MODE, int DT, int EPI, int OUTB>
__global__ void __launch_bounds__(256, 1) mm_gemm(
    const uint16_t* __restrict__ Ah, const uint16_t* __restrict__ Al,
    const uint16_t* __restrict__ Bh, const uint16_t* __restrict__ Bl,
    float* __restrict__ C,
    uint16_t* __restrict__ Oh, uint16_t* __restrict__ Ol,
    const float* __restrict__ b1, const float* __restrict__ b2,
    const float* __restrict__ b3, const float* __restrict__ b4,
    int M, int N, int K, int tilesM, int tilesN,
    long long sA, long long sB, long long sC)
{
    constexpr int NA = (MODE == 2) ? 1 : 2;
    constexpr int NB = (MODE == 1) ? 1 : 2;
    constexpr int STB = (NA + NB) * TILE_BYTES;

    extern __shared__ char smem[];
    const uint32_t sb = smem_u32(smem);
    const int tid = threadIdx.x;
    const int wid = tid >> 5, lane = tid & 31;
    const int wm = wid >> 2, wn = wid & 3;
    const int z = blockIdx.z;

    int bid = blockIdx.x;
    const int GROUP = 8;
    int npg = GROUP * tilesN;
    int grp = bid / npg, rem = bid - grp * npg;
    int gs = tilesM - grp * GROUP; if (gs > GROUP) gs = GROUP;
    int mt = grp * GROUP + rem % gs;
    int nt = rem / gs;
    const int row0 = mt * BM, col0 = nt * BN;

    Ah += (size_t)z * sA; if (NA == 2) Al += (size_t)z * sA;
    Bh += (size_t)z * sB; if (NB == 2) Bl += (size_t)z * sB;

    const int crow = tid >> 1;
    const int cbyte = (tid & 1) * 32;
    const uint32_t dst_off = (uint32_t)crow * (TSTRIDE * 2) + cbyte;

    auto prefetch = [&](int slab, int st) {
        const int k0 = slab * BK;
        uint32_t base = sb + st * STB + dst_off;
        const char* a0 = (const char*)(Ah + (size_t)(row0 + crow) * K + k0) + cbyte;
        cp16(base, a0); cp16(base + 16, a0 + 16);
        if (NA == 2) {
            const char* a1 = (const char*)(Al + (size_t)(row0 + crow) * K + k0) + cbyte;
            cp16(base + TILE_BYTES, a1); cp16(base + TILE_BYTES + 16, a1 + 16);
        }
        uint32_t bb = base + NA * TILE_BYTES;
        const char* b0 = (const char*)(Bh + (size_t)(col0 + crow) * K + k0) + cbyte;
        cp16(bb, b0); cp16(bb + 16, b0 + 16);
        if (NB == 2) {
            const char* b1p = (const char*)(Bl + (size_t)(col0 + crow) * K + k0) + cbyte;
            cp16(bb + TILE_BYTES, b1p); cp16(bb + TILE_BYTES + 16, b1p + 16);
        }
        cp_commit();
    };

    float acc[4][4][4];
    #pragma unroll
    for (int a = 0; a < 4; a++)
        #pragma unroll
        for (int b = 0; b < 4; b++)
            #pragma unroll
            for (int c = 0; c < 4; c++) acc[a][b][c] = 0.f;

    const int S = K / BK;
    prefetch(0, 0);
    prefetch(1, 1);
    cp_wait<1>();
    __syncthreads();

    const uint32_t a_row = (uint32_t)(wm * 64 + (lane & 15));
    const uint32_t a_kh  = (uint32_t)(lane >> 4) * 16;
    const uint32_t b_row = (uint32_t)(wn * 32 + (lane & 7) + ((lane >> 4) & 1) * 8);
    const uint32_t b_kh  = (uint32_t)((lane >> 3) & 1) * 16;

    for (int i = 0; i < S; i++) {
        const uint32_t st = sb + (i % NSTAGE) * STB;
        const uint32_t aH = st + a_row * (TSTRIDE * 2) + a_kh;
        const uint32_t bH = st + NA * TILE_BYTES + b_row * (TSTRIDE * 2) + b_kh;

        #pragma unroll
        for (int ks = 0; ks < 2; ks++) {
            const uint32_t ko = ks * 32;
            uint32_t ah[4][4], al[4][4], bh2[2][4], bl2[2][4];
            #pragma unroll
            for (int mf = 0; mf < 4; mf++) {
                uint32_t adr = aH + ko + (uint32_t)mf * 16 * (TSTRIDE * 2);
                ldm4(ah[mf][0], ah[mf][1], ah[mf][2], ah[mf][3], adr);
                if (NA == 2) ldm4(al[mf][0], al[mf][1], al[mf][2], al[mf][3], adr + TILE_BYTES);
            }
            #pragma unroll
            for (int p = 0; p < 2; p++) {
                uint32_t adr = bH + ko + (uint32_t)p * 16 * (TSTRIDE * 2);
                ldm4(bh2[p][0], bh2[p][1], bh2[p][2], bh2[p][3], adr);
                if (NB == 2) ldm4(bl2[p][0], bl2[p][1], bl2[p][2], bl2[p][3], adr + TILE_BYTES);
            }
            #pragma unroll
            for (int mf = 0; mf < 4; mf++)
                #pragma unroll
                for (int nf = 0; nf < 4; nf++) {
                    const int p = nf >> 1, q = (nf & 1) * 2;
                    uint32_t h0 = bh2[p][q], h1 = bh2[p][q + 1];
                    mma_any<DT>(acc[mf][nf], ah[mf][0], ah[mf][1], ah[mf][2], ah[mf][3], h0, h1);
                    if (MODE == 0) {
                        uint32_t l0 = bl2[p][q], l1 = bl2[p][q + 1];
                        mma_any<DT>(acc[mf][nf], ah[mf][0], ah[mf][1], ah[mf][2], ah[mf][3], l0, l1);
                        mma_any<DT>(acc[mf][nf], al[mf][0], al[mf][1], al[mf][2], al[mf][3], h0, h1);
                    } else if (MODE == 1) {
                        mma_any<DT>(acc[mf][nf], al[mf][0], al[mf][1], al[mf][2], al[mf][3], h0, h1);
                    } else {
                        uint32_t l0 = bl2[p][q], l1 = bl2[p][q + 1];
                        mma_any<DT>(acc[mf][nf], ah[mf][0], ah[mf][1], ah[mf][2], ah[mf][3], l0, l1);
                    }
                }
        }
        if (i + 2 < S) prefetch(i + 2, (i + 2) % NSTAGE);
        if (i + 1 < S) cp_wait<1>(); else cp_wait<0>();
        __syncthreads();
    }

    // epilogue
    #pragma unroll
    for (int mf = 0; mf < 4; mf++) {
        #pragma unroll
        for (int h = 0; h < 2; h++) {
            const int r = row0 + wm * 64 + mf * 16 + (lane >> 2) + h * 8;
            float rbias = 0.f, iw = 0.f;
            if (EPI == 1) rbias = b1[r];
            if (EPI == 4) { rbias = b1[r] + b2[r]; iw = b3[r]; }
            const float* xrow = (EPI == 4) ? (b4 + (size_t)z * N_) : nullptr;
            #pragma unroll
            for (int nf = 0; nf < 4; nf++) {
                const int cidx = col0 + wn * 32 + nf * 8 + (lane & 3) * 2;
                float2 o;
                o.x = acc[mf][nf][h * 2 + 0];
                o.y = acc[mf][nf][h * 2 + 1];
                if (EPI == 1) { o.x += rbias; o.y += rbias; }
                if (EPI == 2 || EPI == 3) {
                    float2 bc = *(const float2*)(b1 + cidx);
                    o.x += bc.x; o.y += bc.y;
                }
                if (EPI == 4) {
                    float2 xv = *(const float2*)(xrow + cidx);
                    o.x += rbias + iw * xv.x; o.y += rbias + iw * xv.y;
                }
                if (EPI == 2 || EPI == 4) { o.x = fmaxf(o.x, 0.f); o.y = fmaxf(o.y, 0.f); }
                size_t off = (size_t)z * sC + (size_t)r * N + cidx;
                if (OUTB == 0) {
                    *(float2*)(C + off) = o;
                } else if (OUTB == 1) {
                    __nv_bfloat16 hx, lx, hy, ly;
                    split1(o.x, hx, lx); split1(o.y, hy, ly);
                    *(uint32_t*)(Oh + off) = pk2(hx, hy);
                    *(uint32_t*)(Ol + off) = pk2(lx, ly);
                } else if (OUTB == 2) {
                    *(uint32_t*)(Oh + off) = pk2h(__float2half(o.x), __float2half(o.y));
                } else {
                    __half hx, lx, hy, ly;
                    split1h(o.x, hx, lx); split1h(o.y, hy, ly);
                    *(uint32_t*)(Oh + off) = pk2h(hx, hy);
                    *(uint32_t*)(Ol + off) = pk2h(lx, ly);
                }
            }
        }
    }
}

// ---------------- conv1 (3x3, 1->C) + ReLU, zero-padded ----------------
__global__ void conv1_relu_pad(const float* __restrict__ x, const float* __restrict__ w,
                               const float* __restrict__ bia, float* __restrict__ hp) {
    int idx = blockIdx.x * 256 + threadIdx.x;
    int b = idx / (C_ * PW * PW);
    int rem = idx - b * (C_ * PW * PW);
    int c = rem / (PW * PW);
    int p = rem - c * (PW * PW);
    int yy = p / PW, xx = p - yy * PW;
    float out = 0.f;
    if (yy >= 1 && yy <= HW && xx >= 1 && xx <= HW) {
        int y = yy - 1, x0 = xx - 1;
        float acc = bia[c];
        const float* xb = x + b * HW * HW;
        #pragma unroll
        for (int ky = 0; ky < 3; ky++) {
            int iy = y + ky - 1;
            if (iy < 0 || iy >= HW) continue;
            #pragma unroll
            for (int kx = 0; kx < 3; kx++) {
                int ix = x0 + kx - 1;
                if (ix < 0 || ix >= HW) continue;
                acc += w[c * 9 + ky * 3 + kx] * xb[iy * HW + ix];
            }
        }
        out = fmaxf(acc, 0.f);
    }
    hp[idx] = out;
}

// ---------------- im2col^T, fp16 single ----------------
__global__ void im2col_f16(const float* __restrict__ hp, uint16_t* __restrict__ bb) {
    __shared__ float s[64][33];
    int t = threadIdx.x;
    int ic0 = blockIdx.x * 64, n0 = blockIdx.y * 32;
    int zo = blockIdx.z, z = zo / 9, off = zo - z * 9;
    int ky = off / 3, kx = off - ky * 3;
    const float* hpz = hp + (size_t)z * C_ * (PW * PW);
    #pragma unroll
    for (int p = 0; p < 2; p++) {
        int icl = p * 32 + (t >> 3);
        int nl = (t & 7) * 4;
        const float* base = hpz + (size_t)(ic0 + icl) * (PW * PW) + ky * PW + kx;
        #pragma unroll
        for (int i = 0; i < 4; i++) {
            int n = n0 + nl + i;
            int y = n / HW, xx = n - y * HW;
            s[icl][nl + i] = base[y * PW + xx];
        }
    }
    __syncthreads();
    int n = t >> 3, icc = (t & 7) * 8;
    size_t o = (size_t)z * ((size_t)N_ * K2) + (size_t)(n0 + n) * K2 + (size_t)off * C_ + ic0 + icc;
    uint4 u;
    u.x = pk2h(__float2half(s[icc + 0][n]), __float2half(s[icc + 1][n]));
    u.y = pk2h(__float2half(s[icc + 2][n]), __float2half(s[icc + 3][n]));
    u.z = pk2h(__float2half(s[icc + 4][n]), __float2half(s[icc + 5][n]));
    u.w = pk2h(__float2half(s[icc + 6][n]), __float2half(s[icc + 7][n]));
    *(uint4*)(bb + o) = u;
}

// ---------------- W2 reorder + fp16 split ----------------
__global__ void reorder_split_w2(const float* __restrict__ w2,
                                 uint16_t* __restrict__ oh, uint16_t* __restrict__ ol) {
    int id = blockIdx.x * 256 + threadIdx.x;
    int c = id / (9 * 288);
    int rem = id - c * (9 * 288);
    int off = rem / 288, icb = rem - off * 288;
    const float* src = w2 + (size_t)c * K2 + (size_t)icb * 72 + off;
    __half hh[8], ll[8];
    #pragma unroll
    for (int i = 0; i < 8; i++) split1h(src[i * 9], hh[i], ll[i]);
    size_t o = (size_t)c * K2 + (size_t)off * C_ + (size_t)icb * 8;
    uint4 uh, ul;
    uh.x = pk2h(hh[0], hh[1]); uh.y = pk2h(hh[2], hh[3]); uh.z = pk2h(hh[4], hh[5]); uh.w = pk2h(hh[6], hh[7]);
    ul.x = pk2h(ll[0], ll[1]); ul.y = pk2h(ll[2], ll[3]); ul.z = pk2h(ll[4], ll[5]); ul.w = pk2h(ll[6], ll[7]);
    *(uint4*)(oh + o) = uh;
    *(uint4*)(ol + o) = ul;
}

// ---------------- plain fp16 split (qkv weights) ----------------
__global__ void split_plain_f16(const float* __restrict__ src,
                                uint16_t* __restrict__ oh, uint16_t* __restrict__ ol) {
    size_t i4 = (size_t)blockIdx.x * 256 + threadIdx.x;
    float4 v = *(const float4*)(src + i4 * 4);
    __half h0, h1, h2, h3, l0, l1, l2, l3;
    split1h(v.x, h0, l0); split1h(v.y, h1, l1); split1h(v.z, h2, l2); split1h(v.w, h3, l3);
    uint2 uh, ul;
    uh.x = pk2h(h0, h1); uh.y = pk2h(h2, h3);
    ul.x = pk2h(l0, l1); ul.y = pk2h(l2, l3);
    *(uint2*)(oh + i4 * 4) = uh;
    *(uint2*)(ol + i4 * 4) = ul;
}

// ---------------- transpose -> fp16 single (down^T) ----------------
__global__ void transpose_f16(const float* __restrict__ in, uint16_t* __restrict__ ot,
                              int R, int Cc) {
    __shared__ float s[64][33];
    int t = threadIdx.x;
    int c0 = blockIdx.x * 32, r0 = blockIdx.y * 64;
    size_t zb = (size_t)blockIdx.z * R * Cc;
    {
        int r = t >> 2, cl = (t & 3) * 8;
        const float* src = in + zb + (size_t)(r0 + r) * Cc + c0 + cl;
        float4 a = *(const float4*)src;
        float4 b = *(const float4*)(src + 4);
        s[r][cl + 0] = a.x; s[r][cl + 1] = a.y; s[r][cl + 2] = a.z; s[r][cl + 3] = a.w;
        s[r][cl + 4] = b.x; s[r][cl + 5] = b.y; s[r][cl + 6] = b.z; s[r][cl + 7] = b.w;
    }
    __syncthreads();
    int c = t >> 3, rl = (t & 7) * 8;
    size_t o = zb + (size_t)(c0 + c) * R + r0 + rl;
    uint4 u;
    u.x = pk2h(__float2half(s[rl + 0][c]), __float2half(s[rl + 1][c]));
    u.y = pk2h(__float2half(s[rl + 2][c]), __float2half(s[rl + 3][c]));
    u.z = pk2h(__float2half(s[rl + 4][c]), __float2half(s[rl + 5][c]));
    u.w = pk2h(__float2half(s[rl + 6][c]), __float2half(s[rl + 7][c]));
    *(uint4*)(ot + o) = u;
}

// ---------------- transpose + fp16 split (FFN weights) ----------------
__global__ void transpose_split_f16(const float* __restrict__ in,
                                    uint16_t* __restrict__ oh, uint16_t* __restrict__ ol,
                                    int R, int Cc) {
    __shared__ float s[64][33];
    int t = threadIdx.x;
    int c0 = blockIdx.x * 32, r0 = blockIdx.y * 64;
    {
        int r = t >> 2, cl = (t & 3) * 8;
        const float* src = in + (size_t)(r0 + r) * Cc + c0 + cl;
        float4 a = *(const float4*)src;
        float4 b = *(const float4*)(src + 4);
        s[r][cl + 0] = a.x; s[r][cl + 1] = a.y; s[r][cl + 2] = a.z; s[r][cl + 3] = a.w;
        s[r][cl + 4] = b.x; s[r][cl + 5] = b.y; s[r][cl + 6] = b.z; s[r][cl + 7] = b.w;
    }
    __syncthreads();
    int c = t >> 3, rl = (t & 7) * 8;
    __half hh[8], ll[8];
    #pragma unroll
    for (int i = 0; i < 8; i++) split1h(s[rl + i][c], hh[i], ll[i]);
    size_t o = (size_t)(c0 + c) * R + r0 + rl;
    uint4 uh, ul;
    uh.x = pk2h(hh[0], hh[1]); uh.y = pk2h(hh[2], hh[3]); uh.z = pk2h(hh[4], hh[5]); uh.w = pk2h(hh[6], hh[7]);
    ul.x = pk2h(ll[0], ll[1]); ul.y = pk2h(ll[2], ll[3]); ul.z = pk2h(ll[4], ll[5]); ul.w = pk2h(ll[6], ll[7]);
    *(uint4*)(oh + o) = uh;
    *(uint4*)(ol + o) = ul;
}

// ---------------- reductions ----------------
__device__ __forceinline__ float block_sum(float v, float* red) {
    int tid = threadIdx.x;
    red[tid] = v; __syncthreads();
    #pragma unroll
    for (int s = 128; s > 0; s >>= 1) { if (tid < s) red[tid] += red[tid + s]; __syncthreads(); }
    float r = red[0]; __syncthreads();
    return r;
}
__device__ __forceinline__ float block_max(float v, float* red) {
    int tid = threadIdx.x;
    red[tid] = v; __syncthreads();
    #pragma unroll
    for (int s = 128; s > 0; s >>= 1) { if (tid < s) red[tid] = fmaxf(red[tid], red[tid + s]); __syncthreads(); }
    float r = red[0]; __syncthreads();
    return r;
}

// ---------------- softmax with analytic rel-pos bias -> fp16 split ----------------
__global__ void softmax_bias_split(const float* __restrict__ qk, const float* __restrict__ rel,
                                   uint16_t* __restrict__ oh, uint16_t* __restrict__ ol) {
    __shared__ float red[256];
    int row = blockIdx.x;
    int b = row / E_;
    int i = row - b * E_;
    int ci = i / HW, wi = i - ci * HW;
    const float* rp = qk + (size_t)row * E_;
    int tid = threadIdx.x;
    float v[9];
    float mx = -3.4e38f;
    #pragma unroll
    for (int r = 0; r < 9; r++) {
        int j = r * 256 + tid;
        int cj = j / HW, wj = j - cj * HW;
        int idx = (ci - cj + HW - 1) * (2 * HW - 1) + (wi - wj + HW - 1);
        v[r] = rp[j] * (1.0f / 48.0f) + rel[idx * NH_ + b];
        mx = fmaxf(mx, v[r]);
    }
    mx = block_max(mx, red);
    float s = 0.f;
    #pragma unroll
    for (int r = 0; r < 9; r++) { v[r] = __expf(v[r] - mx); s += v[r]; }
    s = block_sum(s, red);
    float inv = 1.f / s;
    #pragma unroll
    for (int r = 0; r < 9; r++) {
        int j = r * 256 + tid;
        __half h, l;
        split1h(v[r] * inv, h, l);
        oh[(size_t)row * E_ + j] = *(uint16_t*)&h;
        ol[(size_t)row * E_ + j] = *(uint16_t*)&l;
    }
}

// ---------------- shuffle + residual + LN1 -> fp32 + fp16 single ----------------
__global__ void add_shuffle_ln(const float* __restrict__ ao, const float* __restrict__ down,
                               const float* __restrict__ g, const float* __restrict__ be,
                               float* __restrict__ h1, uint16_t* __restrict__ of16) {
    __shared__ float red[256];
    int m = blockIdx.x;
    int e = m >> 2, bs = m & 3;
    const float* ar = ao + ((size_t)bs * E_ + e) * N_;
    const float* dr = down + (size_t)m * N_;
    int tid = threadIdx.x;
    float v[9]; float s = 0.f;
    #pragma unroll
    for (int r = 0; r < 9; r++) { int j = r * 256 + tid; v[r] = ar[j] + dr[j]; s += v[r]; }
    float mean = block_sum(s, red) * (1.f / N_);
    float s2 = 0.f;
    #pragma unroll
    for (int r = 0; r < 9; r++) { float d = v[r] - mean; s2 += d * d; }
    float var = block_sum(s2, red) * (1.f / N_);
    float rstd = rsqrtf(var + 1e-5f);
    #pragma unroll
    for (int r = 0; r < 9; r++) {
        int j = r * 256 + tid;
        float o = (v[r] - mean) * rstd * g[j] + be[j];
        h1[(size_t)m * N_ + j] = o;
        __half hf = __float2half(o);
        of16[(size_t)m * N_ + j] = *(uint16_t*)&hf;
    }
}

// ---------------- residual + LN2 ----------------
__global__ void add_ln(const float* __restrict__ f, const float* __restrict__ h1,
                       const float* __restrict__ g, const float* __restrict__ be,
                       float* __restrict__ out) {
    __shared__ float red[256];
    int m = blockIdx.x;
    const float* fr = f + (size_t)m * N_;
    const float* hr = h1 + (size_t)m * N_;
    int tid = threadIdx.x;
    float v[9]; float s = 0.f;
    #pragma unroll
    for (int r = 0; r < 9; r++) { int j = r * 256 + tid; v[r] = fr[j] + hr[j]; s += v[r]; }
    float mean = block_sum(s, red) * (1.f / N_);
    float s2 = 0.f;
    #pragma unroll
    for (int r = 0; r < 9; r++) { float d = v[r] - mean; s2 += d * d; }
    float var = block_sum(s2, red) * (1.f / N_);
    float rstd = rsqrtf(var + 1e-5f);
    #pragma unroll
    for (int r = 0; r < 9; r++) {
        int j = r * 256 + tid;
        out[(size_t)m * N_ + j] = (v[r] - mean) * rstd * g[j] + be[j];
    }
}

// ---------------- maxpool 2x2 ----------------
__global__ void maxpool_k(const float* __restrict__ out, float* __restrict__ p) {
    int idx = blockIdx.x * 256 + threadIdx.x;
    int bc = idx / (24 * 24);
    int r = idx - bc * 576;
    int y = r / 24, x = r - y * 24;
    const float* o = out + (size_t)bc * N_ + (2 * y) * HW + 2 * x;
    p[idx] = fmaxf(fmaxf(o[0], o[1]), fmaxf(o[HW], o[HW + 1]));
}

// ---------------- launcher ----------------
extern "C" void kernel_launch(void* const* d_in, const int* in_sizes, int n_in,
                              void* d_out, int out_size) {
    const float* x    = (const float*)d_in[0];
    const float* c1w  = (const float*)d_in[1];
    const float* c1b  = (const float*)d_in[2];
    const float* c2w  = (const float*)d_in[3];
    const float* c2b  = (const float*)d_in[4];
    const float* idw  = (const float*)d_in[5];
    const float* idb  = (const float*)d_in[6];
    const float* qw   = (const float*)d_in[7];
    const float* qb   = (const float*)d_in[8];
    const float* kw   = (const float*)d_in[9];
    const float* kb   = (const float*)d_in[10];
    const float* vw   = (const float*)d_in[11];
    const float* vb   = (const float*)d_in[12];
    const float* rel  = (const float*)d_in[13];
    const float* ln1g = (const float*)d_in[14];
    const float* ln1b = (const float*)d_in[15];
    const float* ln2g = (const float*)d_in[16];
    const float* ln2b = (const float*)d_in[17];
    const float* fw1  = (const float*)d_in[18];
    const float* fb1  = (const float*)d_in[19];
    const float* fw2  = (const float*)d_in[20];
    const float* fb2  = (const float*)d_in[21];

    float* outp = (float*)d_out;
    float* pool = outp + (size_t)B_ * C_ * N_;

    float* F; uint16_t* Hh;
    cudaGetSymbolAddress((void**)&F, g_f32);
    cudaGetSymbolAddress((void**)&Hh, g_b16);

    float* hp = F + F_HP;   float* down = F + F_DOWN;
    float* qk = F + F_QK;   float* ao   = F + F_AO;
    float* h1 = F + F_H1;   float* ff   = F + F_FF;

    const int SM3 = NSTAGE * 3 * TILE_BYTES;    // all GEMMs are 2-term now
    cudaFuncSetAttribute(mm_gemm<1,1,4,0>, cudaFuncAttributeMaxDynamicSharedMemorySize, SM3);
    cudaFuncSetAttribute(mm_gemm<1,1,1,3>, cudaFuncAttributeMaxDynamicSharedMemorySize, SM3);
    cudaFuncSetAttribute(mm_gemm<1,1,1,2>, cudaFuncAttributeMaxDynamicSharedMemorySize, SM3);
    cudaFuncSetAttribute(mm_gemm<2,1,3,2>, cudaFuncAttributeMaxDynamicSharedMemorySize, SM3);
    cudaFuncSetAttribute(mm_gemm<1,1,0,0>, cudaFuncAttributeMaxDynamicSharedMemorySize, SM3);
    cudaFuncSetAttribute(mm_gemm<2,1,2,2>, cudaFuncAttributeMaxDynamicSharedMemorySize, SM3);
    cudaFuncSetAttribute(mm_gemm<2,1,3,0>, cudaFuncAttributeMaxDynamicSharedMemorySize, SM3);

    const long long EN = (long long)E_ * N_;
    const long long NK2 = (long long)N_ * K2;

    // weight prep
    reorder_split_w2<<<23328, 256>>>(c2w, Hh + H_W2H, Hh + H_W2L);
    split_plain_f16<<<5184, 256>>>(qw, Hh + H_QWH, Hh + H_QWL);
    split_plain_f16<<<5184, 256>>>(kw, Hh + H_KWH, Hh + H_KWL);
    split_plain_f16<<<5184, 256>>>(vw, Hh + H_VWH, Hh + H_VWL);
    transpose_split_f16<<<dim3(144, 36, 1), 256>>>(fw1, Hh + H_W1TH, Hh + H_W1TL, E_, E2);
    transpose_split_f16<<<dim3(72, 72, 1), 256>>>(fw2, Hh + H_W2TH, Hh + H_W2TL, E2, E_);

    // conv block (2-term fp16: W2 split, im2col single)
    conv1_relu_pad<<<90000, 256>>>(x, c1w, c1b, hp);
    im2col_f16<<<dim3(36, 72, 36), 256>>>(hp, Hh + H_IM);
    mm_gemm<1,1,4,0><<<dim3(324, 1, 4), 256, SM3>>>(
        Hh + H_W2H, Hh + H_W2L, Hh + H_IM, nullptr, down, nullptr, nullptr,
        c2b, idb, idw, x, C_, N_, K2, 18, 18, 0, NK2, EN);

    // qkv (2-term fp16: weight split, down^T single)
    transpose_f16<<<dim3(72, 36, 4), 256>>>(down, Hh + H_DT, C_, N_);
    mm_gemm<1,1,1,3><<<dim3(324, 1, 4), 256, SM3>>>(
        Hh + H_QWH, Hh + H_QWL, Hh + H_DT, nullptr, nullptr, Hh + H_QH, Hh + H_QL,
        qb, nullptr, nullptr, nullptr, E_, N_, C_, 18, 18, 0, EN, EN);
    mm_gemm<1,1,1,2><<<dim3(324, 1, 4), 256, SM3>>>(
        Hh + H_KWH, Hh + H_KWL, Hh + H_DT, nullptr, nullptr, Hh + H_K, nullptr,
        kb, nullptr, nullptr, nullptr, E_, N_, C_, 18, 18, 0, EN, EN);
    mm_gemm<2,1,3,2><<<dim3(324, 1, 4), 256, SM3>>>(
        Hh + H_DT, nullptr, Hh + H_VWH, Hh + H_VWL, nullptr, Hh + H_VT, nullptr,
        vb, nullptr, nullptr, nullptr, N_, E_, C_, 18, 18, EN, 0, EN);

    // attention (2-term fp16: q split / attn split, k / v^T single)
    mm_gemm<1,1,0,0><<<dim3(324, 1, 4), 256, SM3>>>(
        Hh + H_QH, Hh + H_QL, Hh + H_K, nullptr, qk, nullptr, nullptr,
        nullptr, nullptr, nullptr, nullptr, E_, E_, N_, 18, 18, EN, EN, EN);
    softmax_bias_split<<<B_ * E_, 256>>>(qk, rel, Hh + H_ATH, Hh + H_ATL);
    mm_gemm<1,1,0,0><<<dim3(324, 1, 4), 256, SM3>>>(
        Hh + H_ATH, Hh + H_ATL, Hh + H_VT, nullptr, ao, nullptr, nullptr,
        nullptr, nullptr, nullptr, nullptr, E_, N_, E_, 18, 18, EN, EN, EN);
    add_shuffle_ln<<<B_ * C_, 256>>>(ao, down, ln1g, ln1b, h1, Hh + H_H1F);

    // FFN (2-term fp16)
    mm_gemm<2,1,2,2><<<dim3(2592, 1, 1), 256, SM3>>>(
        Hh + H_H1F, nullptr, Hh + H_W1TH, Hh + H_W1TL, nullptr, Hh + H_MID, nullptr,
        fb1, nullptr, nullptr, nullptr, B_ * N_, E2, E_, 72, 36, 0, 0, 0);
    mm_gemm<2,1,3,0><<<dim3(1296, 1, 1), 256, SM3>>>(
        Hh + H_MID, nullptr, Hh + H_W2TH, Hh + H_W2TL, ff, nullptr, nullptr,
        fb2, nullptr, nullptr, nullptr, B_ * N_, E_, E2, 72, 18, 0, 0, 0);
    add_ln<<<B_ * C_, 256>>>(ff, h1, ln2g, ln2b, outp);
    maxpool_k<<<20736, 256>>>(outp, pool);
}

// round 14
// speedup vs baseline: 2.0561x; 1.2704x over previous
#include <cuda_runtime.h>
#include <cuda_bf16.h>
#include <cuda_fp16.h>
#include <cstdint>

#define B_  4
#define C_  2304
#define N_  2304
#define E_  2304
#define HW  48
#define PW  50
#define NH_ 4
#define K2  20736
#define E2  4608

// GEMM tiling: CTA 128x128x32, 8 warps (2m x 4n), warp tile 64x32
#define BM 128
#define BN 128
#define BK 32
#define TSTRIDE 40
#define TILE_BYTES (BM * TSTRIDE * 2)   // 10240
#define NSTAGE 3

// ---------------- PTX helpers ----------------
__device__ __forceinline__ uint32_t smem_u32(const void* p) {
    uint32_t a;
    asm("{ .reg .u64 t; cvta.to.shared.u64 t, %1; cvt.u32.u64 %0, t; }" : "=r"(a) : "l"(p));
    return a;
}
__device__ __forceinline__ void cp16(uint32_t dst, const void* src) {
    asm volatile("cp.async.cg.shared.global [%0], [%1], 16;" :: "r"(dst), "l"(src));
}
__device__ __forceinline__ void cp_commit() { asm volatile("cp.async.commit_group;"); }
template<int NN>
__device__ __forceinline__ void cp_wait() { asm volatile("cp.async.wait_group %0;" :: "n"(NN)); }

__device__ __forceinline__ void ldm4(uint32_t& r0, uint32_t& r1, uint32_t& r2, uint32_t& r3, uint32_t a) {
    asm volatile("ldmatrix.sync.aligned.m8n8.x4.shared.b16 {%0,%1,%2,%3}, [%4];"
                 : "=r"(r0), "=r"(r1), "=r"(r2), "=r"(r3) : "r"(a));
}
__device__ __forceinline__ void mma_bf16(float* d, uint32_t a0, uint32_t a1, uint32_t a2, uint32_t a3,
                                         uint32_t b0, uint32_t b1) {
    asm volatile("mma.sync.aligned.m16n8k16.row.col.f32.bf16.bf16.f32 "
                 "{%0,%1,%2,%3}, {%4,%5,%6,%7}, {%8,%9}, {%0,%1,%2,%3};"
                 : "+f"(d[0]), "+f"(d[1]), "+f"(d[2]), "+f"(d[3])
                 : "r"(a0), "r"(a1), "r"(a2), "r"(a3), "r"(b0), "r"(b1));
}
__device__ __forceinline__ void mma_f16(float* d, uint32_t a0, uint32_t a1, uint32_t a2, uint32_t a3,
                                        uint32_t b0, uint32_t b1) {
    asm volatile("mma.sync.aligned.m16n8k16.row.col.f32.f16.f16.f32 "
                 "{%0,%1,%2,%3}, {%4,%5,%6,%7}, {%8,%9}, {%0,%1,%2,%3};"
                 : "+f"(d[0]), "+f"(d[1]), "+f"(d[2]), "+f"(d[3])
                 : "r"(a0), "r"(a1), "r"(a2), "r"(a3), "r"(b0), "r"(b1));
}
template<int DT>
__device__ __forceinline__ void mma_any(float* d, uint32_t a0, uint32_t a1, uint32_t a2, uint32_t a3,
                                        uint32_t b0, uint32_t b1) {
    if (DT == 0) mma_bf16(d, a0, a1, a2, a3, b0, b1);
    else         mma_f16 (d, a0, a1, a2, a3, b0, b1);
}

__device__ __forceinline__ void split1h(float v, __half& h, __half& l) {
    h = __float2half(v);
    l = __float2half(v - __half2float(h));
}
__device__ __forceinline__ uint32_t pk2h(__half a, __half b) {
    __half2 t(a, b);
    return *reinterpret_cast<uint32_t*>(&t);
}

// ---------------- scratch arenas (uint16 units) ----------------
constexpr size_t SZ_EN = (size_t)B_ * E_ * N_;
constexpr size_t SZ_W  = (size_t)E_ * E_;
constexpr size_t F_HP = 0, F_DOWN = 23040000;
constexpr size_t F_QK = F_DOWN + SZ_EN, F_AO = F_QK + SZ_EN, F_H1 = F_AO + SZ_EN;
constexpr size_t F_FF = F_H1 + SZ_EN;
constexpr size_t F_TOT = F_FF + SZ_EN;

constexpr size_t H_IM  = 0;                                  // fp16 single im2col
constexpr size_t H_W2  = H_IM + (size_t)B_ * N_ * K2;        // fp16 single W2 (reordered)
constexpr size_t H_QWH = H_W2 + (size_t)C_ * K2, H_QWL = H_QWH + SZ_W;
constexpr size_t H_KWH = H_QWL + SZ_W, H_KWL = H_KWH + SZ_W;
constexpr size_t H_VWH = H_KWL + SZ_W, H_VWL = H_VWH + SZ_W;
constexpr size_t H_W1TH = H_VWL + SZ_W, H_W1TL = H_W1TH + 2 * SZ_W;
constexpr size_t H_W2TH = H_W1TL + 2 * SZ_W, H_W2TL = H_W2TH + 2 * SZ_W;
constexpr size_t H_DT  = H_W2TL + 2 * SZ_W;                  // fp16 single down^T
constexpr size_t H_VT  = H_DT + SZ_EN;                       // fp16 single v^T
constexpr size_t H_Q   = H_VT + SZ_EN;                       // fp16 single q
constexpr size_t H_K   = H_Q + SZ_EN;                        // fp16 single k
constexpr size_t H_AT  = H_K + SZ_EN;                        // fp16 single attn
constexpr size_t H_H1F = H_AT + SZ_EN;                       // fp16 single h1
constexpr size_t H_MID = H_H1F + SZ_EN;                      // fp16 single mid
constexpr size_t H_TOT = H_MID + 2 * SZ_EN;

__device__ __align__(256) float    g_f32[F_TOT];
__device__ __align__(256) uint16_t g_b16[H_TOT];

// ---------------- GEMM: D[m][n] = sum_k A[m,k]*B[n,k] ----------------
// MODE: 1 = A-split/B-single (2 MMA); 2 = A-single/B-split (2 MMA); 3 = both single (1 MMA)
// DT: 0 bf16, 1 f16
// EPI: 0 none, 1 +b1[row], 2 +b1[col]+relu, 3 +b1[col], 4 conv(+b1[r]+b2[r]+b3[r]*b4[z*N_+n], relu)
// OUTB: 0 fp32 C; 2 fp16 single (Oh)
template<int MODE, int DT, int EPI, int OUTB>
__global__ void __launch_bounds__(256, 1) mm_gemm(
    const uint16_t* __restrict__ Ah, const uint16_t* __restrict__ Al,
    const uint16_t* __restrict__ Bh, const uint16_t* __restrict__ Bl,
    float* __restrict__ C,
    uint16_t* __restrict__ Oh,
    const float* __restrict__ b1, const float* __restrict__ b2,
    const float* __restrict__ b3, const float* __restrict__ b4,
    int M, int N, int K, int tilesM, int tilesN,
    long long sA, long long sB, long long sC)
{
    constexpr int NA = (MODE == 1) ? 2 : 1;
    constexpr int NB = (MODE == 2) ? 2 : 1;
    constexpr int STB = (NA + NB) * TILE_BYTES;

    extern __shared__ char smem[];
    const uint32_t sb = smem_u32(smem);
    const int tid = threadIdx.x;
    const int wid = tid >> 5, lane = tid & 31;
    const int wm = wid >> 2, wn = wid & 3;
    const int z = blockIdx.z;

    int bid = blockIdx.x;
    const int GROUP = 8;
    int npg = GROUP * tilesN;
    int grp = bid / npg, rem = bid - grp * npg;
    int gs = tilesM - grp * GROUP; if (gs > GROUP) gs = GROUP;
    int mt = grp * GROUP + rem % gs;
    int nt = rem / gs;
    const int row0 = mt * BM, col0 = nt * BN;

    Ah += (size_t)z * sA; if (NA == 2) Al += (size_t)z * sA;
    Bh += (size_t)z * sB; if (NB == 2) Bl += (size_t)z * sB;

    const int crow = tid >> 1;
    const int cbyte = (tid & 1) * 32;
    const uint32_t dst_off = (uint32_t)crow * (TSTRIDE * 2) + cbyte;

    auto prefetch = [&](int slab, int st) {
        const int k0 = slab * BK;
        uint32_t base = sb + st * STB + dst_off;
        const char* a0 = (const char*)(Ah + (size_t)(row0 + crow) * K + k0) + cbyte;
        cp16(base, a0); cp16(base + 16, a0 + 16);
        if (NA == 2) {
            const char* a1 = (const char*)(Al + (size_t)(row0 + crow) * K + k0) + cbyte;
            cp16(base + TILE_BYTES, a1); cp16(base + TILE_BYTES + 16, a1 + 16);
        }
        uint32_t bb = base + NA * TILE_BYTES;
        const char* b0 = (const char*)(Bh + (size_t)(col0 + crow) * K + k0) + cbyte;
        cp16(bb, b0); cp16(bb + 16, b0 + 16);
        if (NB == 2) {
            const char* b1p = (const char*)(Bl + (size_t)(col0 + crow) * K + k0) + cbyte;
            cp16(bb + TILE_BYTES, b1p); cp16(bb + TILE_BYTES + 16, b1p + 16);
        }
        cp_commit();
    };

    float acc[4][4][4];
    #pragma unroll
    for (int a = 0; a < 4; a++)
        #pragma unroll
        for (int b = 0; b < 4; b++)
            #pragma unroll
            for (int c = 0; c < 4; c++) acc[a][b][c] = 0.f;

    const int S = K / BK;
    prefetch(0, 0);
    prefetch(1, 1);
    cp_wait<1>();
    __syncthreads();

    const uint32_t a_row = (uint32_t)(wm * 64 + (lane & 15));
    const uint32_t a_kh  = (uint32_t)(lane >> 4) * 16;
    const uint32_t b_row = (uint32_t)(wn * 32 + (lane & 7) + ((lane >> 4) & 1) * 8);
    const uint32_t b_kh  = (uint32_t)((lane >> 3) & 1) * 16;

    for (int i = 0; i < S; i++) {
        const uint32_t st = sb + (i % NSTAGE) * STB;
        const uint32_t aH = st + a_row * (TSTRIDE * 2) + a_kh;
        const uint32_t bH = st + NA * TILE_BYTES + b_row * (TSTRIDE * 2) + b_kh;

        #pragma unroll
        for (int ks = 0; ks < 2; ks++) {
            const uint32_t ko = ks * 32;
            uint32_t ah[4][4], al[4][4], bh2[2][4], bl2[2][4];
            #pragma unroll
            for (int mf = 0; mf < 4; mf++) {
                uint32_t adr = aH + ko + (uint32_t)mf * 16 * (TSTRIDE * 2);
                ldm4(ah[mf][0], ah[mf][1], ah[mf][2], ah[mf][3], adr);
                if (NA == 2) ldm4(al[mf][0], al[mf][1], al[mf][2], al[mf][3], adr + TILE_BYTES);
            }
            #pragma unroll
            for (int p = 0; p < 2; p++) {
                uint32_t adr = bH + ko + (uint32_t)p * 16 * (TSTRIDE * 2);
                ldm4(bh2[p][0], bh2[p][1], bh2[p][2], bh2[p][3], adr);
                if (NB == 2) ldm4(bl2[p][0], bl2[p][1], bl2[p][2], bl2[p][3], adr + TILE_BYTES);
            }
            #pragma unroll
            for (int mf = 0; mf < 4; mf++)
                #pragma unroll
                for (int nf = 0; nf < 4; nf++) {
                    const int p = nf >> 1, q = (nf & 1) * 2;
                    uint32_t h0 = bh2[p][q], h1 = bh2[p][q + 1];
                    mma_any<DT>(acc[mf][nf], ah[mf][0], ah[mf][1], ah[mf][2], ah[mf][3], h0, h1);
                    if (MODE == 1) {
                        mma_any<DT>(acc[mf][nf], al[mf][0], al[mf][1], al[mf][2], al[mf][3], h0, h1);
                    } else if (MODE == 2) {
                        uint32_t l0 = bl2[p][q], l1 = bl2[p][q + 1];
                        mma_any<DT>(acc[mf][nf], ah[mf][0], ah[mf][1], ah[mf][2], ah[mf][3], l0, l1);
                    }
                }
        }
        if (i + 2 < S) prefetch(i + 2, (i + 2) % NSTAGE);
        if (i + 1 < S) cp_wait<1>(); else cp_wait<0>();
        __syncthreads();
    }

    // epilogue
    #pragma unroll
    for (int mf = 0; mf < 4; mf++) {
        #pragma unroll
        for (int h = 0; h < 2; h++) {
            const int r = row0 + wm * 64 + mf * 16 + (lane >> 2) + h * 8;
            float rbias = 0.f, iw = 0.f;
            if (EPI == 1) rbias = b1[r];
            if (EPI == 4) { rbias = b1[r] + b2[r]; iw = b3[r]; }
            const float* xrow = (EPI == 4) ? (b4 + (size_t)z * N_) : nullptr;
            #pragma unroll
            for (int nf = 0; nf < 4; nf++) {
                const int cidx = col0 + wn * 32 + nf * 8 + (lane & 3) * 2;
                float2 o;
                o.x = acc[mf][nf][h * 2 + 0];
                o.y = acc[mf][nf][h * 2 + 1];
                if (EPI == 1) { o.x += rbias; o.y += rbias; }
                if (EPI == 2 || EPI == 3) {
                    float2 bc = *(const float2*)(b1 + cidx);
                    o.x += bc.x; o.y += bc.y;
                }
                if (EPI == 4) {
                    float2 xv = *(const float2*)(xrow + cidx);
                    o.x += rbias + iw * xv.x; o.y += rbias + iw * xv.y;
                }
                if (EPI == 2 || EPI == 4) { o.x = fmaxf(o.x, 0.f); o.y = fmaxf(o.y, 0.f); }
                size_t off = (size_t)z * sC + (size_t)r * N + cidx;
                if (OUTB == 0) {
                    *(float2*)(C + off) = o;
                } else {
                    *(uint32_t*)(Oh + off) = pk2h(__float2half(o.x), __float2half(o.y));
                }
            }
        }
    }
}

// ---------------- conv1 (3x3, 1->C) + ReLU, zero-padded ----------------
__global__ void conv1_relu_pad(const float* __restrict__ x, const float* __restrict__ w,
                               const float* __restrict__ bia, float* __restrict__ hp) {
    int idx = blockIdx.x * 256 + threadIdx.x;
    int b = idx / (C_ * PW * PW);
    int rem = idx - b * (C_ * PW * PW);
    int c = rem / (PW * PW);
    int p = rem - c * (PW * PW);
    int yy = p / PW, xx = p - yy * PW;
    float out = 0.f;
    if (yy >= 1 && yy <= HW && xx >= 1 && xx <= HW) {
        int y = yy - 1, x0 = xx - 1;
        float acc = bia[c];
        const float* xb = x + b * HW * HW;
        #pragma unroll
        for (int ky = 0; ky < 3; ky++) {
            int iy = y + ky - 1;
            if (iy < 0 || iy >= HW) continue;
            #pragma unroll
            for (int kx = 0; kx < 3; kx++) {
                int ix = x0 + kx - 1;
                if (ix < 0 || ix >= HW) continue;
                acc += w[c * 9 + ky * 3 + kx] * xb[iy * HW + ix];
            }
        }
        out = fmaxf(acc, 0.f);
    }
    hp[idx] = out;
}

// ---------------- im2col^T, fp16 single ----------------
__global__ void im2col_f16(const float* __restrict__ hp, uint16_t* __restrict__ bb) {
    __shared__ float s[64][33];
    int t = threadIdx.x;
    int ic0 = blockIdx.x * 64, n0 = blockIdx.y * 32;
    int zo = blockIdx.z, z = zo / 9, off = zo - z * 9;
    int ky = off / 3, kx = off - ky * 3;
    const float* hpz = hp + (size_t)z * C_ * (PW * PW);
    #pragma unroll
    for (int p = 0; p < 2; p++) {
        int icl = p * 32 + (t >> 3);
        int nl = (t & 7) * 4;
        const float* base = hpz + (size_t)(ic0 + icl) * (PW * PW) + ky * PW + kx;
        #pragma unroll
        for (int i = 0; i < 4; i++) {
            int n = n0 + nl + i;
            int y = n / HW, xx = n - y * HW;
            s[icl][nl + i] = base[y * PW + xx];
        }
    }
    __syncthreads();
    int n = t >> 3, icc = (t & 7) * 8;
    size_t o = (size_t)z * ((size_t)N_ * K2) + (size_t)(n0 + n) * K2 + (size_t)off * C_ + ic0 + icc;
    uint4 u;
    u.x = pk2h(__float2half(s[icc + 0][n]), __float2half(s[icc + 1][n]));
    u.y = pk2h(__float2half(s[icc + 2][n]), __float2half(s[icc + 3][n]));
    u.z = pk2h(__float2half(s[icc + 4][n]), __float2half(s[icc + 5][n]));
    u.w = pk2h(__float2half(s[icc + 6][n]), __float2half(s[icc + 7][n]));
    *(uint4*)(bb + o) = u;
}

// ---------------- W2 reorder -> fp16 single ----------------
__global__ void reorder_w2_f16(const float* __restrict__ w2, uint16_t* __restrict__ ow) {
    int id = blockIdx.x * 256 + threadIdx.x;
    int c = id / (9 * 288);
    int rem = id - c * (9 * 288);
    int off = rem / 288, icb = rem - off * 288;
    const float* src = w2 + (size_t)c * K2 + (size_t)icb * 72 + off;
    size_t o = (size_t)c * K2 + (size_t)off * C_ + (size_t)icb * 8;
    uint4 u;
    u.x = pk2h(__float2half(src[0]),  __float2half(src[9]));
    u.y = pk2h(__float2half(src[18]), __float2half(src[27]));
    u.z = pk2h(__float2half(src[36]), __float2half(src[45]));
    u.w = pk2h(__float2half(src[54]), __float2half(src[63]));
    *(uint4*)(ow + o) = u;
}

// ---------------- plain fp16 split (qkv weights) ----------------
__global__ void split_plain_f16(const float* __restrict__ src,
                                uint16_t* __restrict__ oh, uint16_t* __restrict__ ol) {
    size_t i4 = (size_t)blockIdx.x * 256 + threadIdx.x;
    float4 v = *(const float4*)(src + i4 * 4);
    __half h0, h1, h2, h3, l0, l1, l2, l3;
    split1h(v.x, h0, l0); split1h(v.y, h1, l1); split1h(v.z, h2, l2); split1h(v.w, h3, l3);
    uint2 uh, ul;
    uh.x = pk2h(h0, h1); uh.y = pk2h(h2, h3);
    ul.x = pk2h(l0, l1); ul.y = pk2h(l2, l3);
    *(uint2*)(oh + i4 * 4) = uh;
    *(uint2*)(ol + i4 * 4) = ul;
}

// ---------------- transpose -> fp16 single (down^T) ----------------
__global__ void transpose_f16(const float* __restrict__ in, uint16_t* __restrict__ ot,
                              int R, int Cc) {
    __shared__ float s[64][33];
    int t = threadIdx.x;
    int c0 = blockIdx.x * 32, r0 = blockIdx.y * 64;
    size_t zb = (size_t)blockIdx.z * R * Cc;
    {
        int r = t >> 2, cl = (t & 3) * 8;
        const float* src = in + zb + (size_t)(r0 + r) * Cc + c0 + cl;
        float4 a = *(const float4*)src;
        float4 b = *(const float4*)(src + 4);
        s[r][cl + 0] = a.x; s[r][cl + 1] = a.y; s[r][cl + 2] = a.z; s[r][cl + 3] = a.w;
        s[r][cl + 4] = b.x; s[r][cl + 5] = b.y; s[r][cl + 6] = b.z; s[r][cl + 7] = b.w;
    }
    __syncthreads();
    int c = t >> 3, rl = (t & 7) * 8;
    size_t o = zb + (size_t)(c0 + c) * R + r0 + rl;
    uint4 u;
    u.x = pk2h(__float2half(s[rl + 0][c]), __float2half(s[rl + 1][c]));
    u.y = pk2h(__float2half(s[rl + 2][c]), __float2half(s[rl + 3][c]));
    u.z = pk2h(__float2half(s[rl + 4][c]), __float2half(s[rl + 5][c]));
    u.w = pk2h(__float2half(s[rl + 6][c]), __float2half(s[rl + 7][c]));
    *(uint4*)(ot + o) = u;
}

// ---------------- transpose + fp16 split (FFN weights) ----------------
__global__ void transpose_split_f16(const float* __restrict__ in,
                                    uint16_t* __restrict__ oh, uint16_t* __restrict__ ol,
                                    int R, int Cc) {
    __shared__ float s[64][33];
    int t = threadIdx.x;
    int c0 = blockIdx.x * 32, r0 = blockIdx.y * 64;
    {
        int r = t >> 2, cl = (t & 3) * 8;
        const float* src = in + (size_t)(r0 + r) * Cc + c0 + cl;
        float4 a = *(const float4*)src;
        float4 b = *(const float4*)(src + 4);
        s[r][cl + 0] = a.x; s[r][cl + 1] = a.y; s[r][cl + 2] = a.z; s[r][cl + 3] = a.w;
        s[r][cl + 4] = b.x; s[r][cl + 5] = b.y; s[r][cl + 6] = b.z; s[r][cl + 7] = b.w;
    }
    __syncthreads();
    int c = t >> 3, rl = (t & 7) * 8;
    __half hh[8], ll[8];
    #pragma unroll
    for (int i = 0; i < 8; i++) split1h(s[rl + i][c], hh[i], ll[i]);
    size_t o = (size_t)(c0 + c) * R + r0 + rl;
    uint4 uh, ul;
    uh.x = pk2h(hh[0], hh[1]); uh.y = pk2h(hh[2], hh[3]); uh.z = pk2h(hh[4], hh[5]); uh.w = pk2h(hh[6], hh[7]);
    ul.x = pk2h(ll[0], ll[1]); ul.y = pk2h(ll[2], ll[3]); ul.z = pk2h(ll[4], ll[5]); ul.w = pk2h(ll[6], ll[7]);
    *(uint4*)(oh + o) = uh;
    *(uint4*)(ol + o) = ul;
}

// ---------------- reductions ----------------
__device__ __forceinline__ float block_sum(float v, float* red) {
    int tid = threadIdx.x;
    red[tid] = v; __syncthreads();
    #pragma unroll
    for (int s = 128; s > 0; s >>= 1) { if (tid < s) red[tid] += red[tid + s]; __syncthreads(); }
    float r = red[0]; __syncthreads();
    return r;
}
__device__ __forceinline__ float block_max(float v, float* red) {
    int tid = threadIdx.x;
    red[tid] = v; __syncthreads();
    #pragma unroll
    for (int s = 128; s > 0; s >>= 1) { if (tid < s) red[tid] = fmaxf(red[tid], red[tid + s]); __syncthreads(); }
    float r = red[0]; __syncthreads();
    return r;
}

// ---------------- softmax with analytic rel-pos bias -> fp16 single ----------------
__global__ void softmax_bias_f16(const float* __restrict__ qk, const float* __restrict__ rel,
                                 uint16_t* __restrict__ oh) {
    __shared__ float red[256];
    int row = blockIdx.x;
    int b = row / E_;
    int i = row - b * E_;
    int ci = i / HW, wi = i - ci * HW;
    const float* rp = qk + (size_t)row * E_;
    int tid = threadIdx.x;
    float v[9];
    float mx = -3.4e38f;
    #pragma unroll
    for (int r = 0; r < 9; r++) {
        int j = r * 256 + tid;
        int cj = j / HW, wj = j - cj * HW;
        int idx = (ci - cj + HW - 1) * (2 * HW - 1) + (wi - wj + HW - 1);
        v[r] = rp[j] * (1.0f / 48.0f) + rel[idx * NH_ + b];
        mx = fmaxf(mx, v[r]);
    }
    mx = block_max(mx, red);
    float s = 0.f;
    #pragma unroll
    for (int r = 0; r < 9; r++) { v[r] = __expf(v[r] - mx); s += v[r]; }
    s = block_sum(s, red);
    float inv = 1.f / s;
    #pragma unroll
    for (int r = 0; r < 9; r++) {
        int j = r * 256 + tid;
        __half h = __float2half(v[r] * inv);
        oh[(size_t)row * E_ + j] = *(uint16_t*)&h;
    }
}

// ---------------- shuffle + residual + LN1 -> fp32 + fp16 single ----------------
__global__ void add_shuffle_ln(const float* __restrict__ ao, const float* __restrict__ down,
                               const float* __restrict__ g, const float* __restrict__ be,
                               float* __restrict__ h1, uint16_t* __restrict__ of16) {
    __shared__ float red[256];
    int m = blockIdx.x;
    int e = m >> 2, bs = m & 3;
    const float* ar = ao + ((size_t)bs * E_ + e) * N_;
    const float* dr = down + (size_t)m * N_;
    int tid = threadIdx.x;
    float v[9]; float s = 0.f;
    #pragma unroll
    for (int r = 0; r < 9; r++) { int j = r * 256 + tid; v[r] = ar[j] + dr[j]; s += v[r]; }
    float mean = block_sum(s, red) * (1.f / N_);
    float s2 = 0.f;
    #pragma unroll
    for (int r = 0; r < 9; r++) { float d = v[r] - mean; s2 += d * d; }
    float var = block_sum(s2, red) * (1.f / N_);
    float rstd = rsqrtf(var + 1e-5f);
    #pragma unroll
    for (int r = 0; r < 9; r++) {
        int j = r * 256 + tid;
        float o = (v[r] - mean) * rstd * g[j] + be[j];
        h1[(size_t)m * N_ + j] = o;
        __half hf = __float2half(o);
        of16[(size_t)m * N_ + j] = *(uint16_t*)&hf;
    }
}

// ---------------- residual + LN2 ----------------
__global__ void add_ln(const float* __restrict__ f, const float* __restrict__ h1,
                       const float* __restrict__ g, const float* __restrict__ be,
                       float* __restrict__ out) {
    __shared__ float red[256];
    int m = blockIdx.x;
    const float* fr = f + (size_t)m * N_;
    const float* hr = h1 + (size_t)m * N_;
    int tid = threadIdx.x;
    float v[9]; float s = 0.f;
    #pragma unroll
    for (int r = 0; r < 9; r++) { int j = r * 256 + tid; v[r] = fr[j] + hr[j]; s += v[r]; }
    float mean = block_sum(s, red) * (1.f / N_);
    float s2 = 0.f;
    #pragma unroll
    for (int r = 0; r < 9; r++) { float d = v[r] - mean; s2 += d * d; }
    float var = block_sum(s2, red) * (1.f / N_);
    float rstd = rsqrtf(var + 1e-5f);
    #pragma unroll
    for (int r = 0; r < 9; r++) {
        int j = r * 256 + tid;
        out[(size_t)m * N_ + j] = (v[r] - mean) * rstd * g[j] + be[j];
    }
}

// ---------------- maxpool 2x2 ----------------
__global__ void maxpool_k(const float* __restrict__ out, float* __restrict__ p) {
    int idx = blockIdx.x * 256 + threadIdx.x;
    int bc = idx / (24 * 24);
    int r = idx - bc * 576;
    int y = r / 24, x = r - y * 24;
    const float* o = out + (size_t)bc * N_ + (2 * y) * HW + 2 * x;
    p[idx] = fmaxf(fmaxf(o[0], o[1]), fmaxf(o[HW], o[HW + 1]));
}

// ---------------- launcher ----------------
extern "C" void kernel_launch(void* const* d_in, const int* in_sizes, int n_in,
                              void* d_out, int out_size) {
    const float* x    = (const float*)d_in[0];
    const float* c1w  = (const float*)d_in[1];
    const float* c1b  = (const float*)d_in[2];
    const float* c2w  = (const float*)d_in[3];
    const float* c2b  = (const float*)d_in[4];
    const float* idw  = (const float*)d_in[5];
    const float* idb  = (const float*)d_in[6];
    const float* qw   = (const float*)d_in[7];
    const float* qb   = (const float*)d_in[8];
    const float* kw   = (const float*)d_in[9];
    const float* kb   = (const float*)d_in[10];
    const float* vw   = (const float*)d_in[11];
    const float* vb   = (const float*)d_in[12];
    const float* rel  = (const float*)d_in[13];
    const float* ln1g = (const float*)d_in[14];
    const float* ln1b = (const float*)d_in[15];
    const float* ln2g = (const float*)d_in[16];
    const float* ln2b = (const float*)d_in[17];
    const float* fw1  = (const float*)d_in[18];
    const float* fb1  = (const float*)d_in[19];
    const float* fw2  = (const float*)d_in[20];
    const float* fb2  = (const float*)d_in[21];

    float* outp = (float*)d_out;
    float* pool = outp + (size_t)B_ * C_ * N_;

    float* F; uint16_t* Hh;
    cudaGetSymbolAddress((void**)&F, g_f32);
    cudaGetSymbolAddress((void**)&Hh, g_b16);

    float* hp = F + F_HP;   float* down = F + F_DOWN;
    float* qk = F + F_QK;   float* ao   = F + F_AO;
    float* h1 = F + F_H1;   float* ff   = F + F_FF;

    const int SM3 = NSTAGE * 3 * TILE_BYTES;   // 2-term stages (92160)
    const int SM2 = NSTAGE * 2 * TILE_BYTES;   // 1-term stages (61440)
    cudaFuncSetAttribute(mm_gemm<3,1,4,0>, cudaFuncAttributeMaxDynamicSharedMemorySize, SM2);
    cudaFuncSetAttribute(mm_gemm<1,1,1,2>, cudaFuncAttributeMaxDynamicSharedMemorySize, SM3);
    cudaFuncSetAttribute(mm_gemm<2,1,3,2>, cudaFuncAttributeMaxDynamicSharedMemorySize, SM3);
    cudaFuncSetAttribute(mm_gemm<3,1,0,0>, cudaFuncAttributeMaxDynamicSharedMemorySize, SM2);
    cudaFuncSetAttribute(mm_gemm<2,1,2,2>, cudaFuncAttributeMaxDynamicSharedMemorySize, SM3);
    cudaFuncSetAttribute(mm_gemm<2,1,3,0>, cudaFuncAttributeMaxDynamicSharedMemorySize, SM3);

    const long long EN = (long long)E_ * N_;
    const long long NK2 = (long long)N_ * K2;

    // weight prep
    reorder_w2_f16<<<23328, 256>>>(c2w, Hh + H_W2);
    split_plain_f16<<<5184, 256>>>(qw, Hh + H_QWH, Hh + H_QWL);
    split_plain_f16<<<5184, 256>>>(kw, Hh + H_KWH, Hh + H_KWL);
    split_plain_f16<<<5184, 256>>>(vw, Hh + H_VWH, Hh + H_VWL);
    transpose_split_f16<<<dim3(144, 36, 1), 256>>>(fw1, Hh + H_W1TH, Hh + H_W1TL, E_, E2);
    transpose_split_f16<<<dim3(72, 72, 1), 256>>>(fw2, Hh + H_W2TH, Hh + H_W2TL, E2, E_);

    // conv block (1-term fp16: W2 single, im2col single)
    conv1_relu_pad<<<90000, 256>>>(x, c1w, c1b, hp);
    im2col_f16<<<dim3(36, 72, 36), 256>>>(hp, Hh + H_IM);
    mm_gemm<3,1,4,0><<<dim3(324, 1, 4), 256, SM2>>>(
        Hh + H_W2, nullptr, Hh + H_IM, nullptr, down, nullptr,
        c2b, idb, idw, x, C_, N_, K2, 18, 18, 0, NK2, EN);

    // qkv (2-term fp16: weight split, down^T single; outputs single fp16)
    transpose_f16<<<dim3(72, 36, 4), 256>>>(down, Hh + H_DT, C_, N_);
    mm_gemm<1,1,1,2><<<dim3(324, 1, 4), 256, SM3>>>(
        Hh + H_QWH, Hh + H_QWL, Hh + H_DT, nullptr, nullptr, Hh + H_Q,
        qb, nullptr, nullptr, nullptr, E_, N_, C_, 18, 18, 0, EN, EN);
    mm_gemm<1,1,1,2><<<dim3(324, 1, 4), 256, SM3>>>(
        Hh + H_KWH, Hh + H_KWL, Hh + H_DT, nullptr, nullptr, Hh + H_K,
        kb, nullptr, nullptr, nullptr, E_, N_, C_, 18, 18, 0, EN, EN);
    mm_gemm<2,1,3,2><<<dim3(324, 1, 4), 256, SM3>>>(
        Hh + H_DT, nullptr, Hh + H_VWH, Hh + H_VWL, nullptr, Hh + H_VT,
        vb, nullptr, nullptr, nullptr, N_, E_, C_, 18, 18, EN, 0, EN);

    // attention (1-term fp16)
    mm_gemm<3,1,0,0><<<dim3(324, 1, 4), 256, SM2>>>(
        Hh + H_Q, nullptr, Hh + H_K, nullptr, qk, nullptr,
        nullptr, nullptr, nullptr, nullptr, E_, E_, N_, 18, 18, EN, EN, EN);
    softmax_bias_f16<<<B_ * E_, 256>>>(qk, rel, Hh + H_AT);
    mm_gemm<3,1,0,0><<<dim3(324, 1, 4), 256, SM2>>>(
        Hh + H_AT, nullptr, Hh + H_VT, nullptr, ao, nullptr,
        nullptr, nullptr, nullptr, nullptr, E_, N_, E_, 18, 18, EN, EN, EN);
    add_shuffle_ln<<<B_ * C_, 256>>>(ao, down, ln1g, ln1b, h1, Hh + H_H1F);

    // FFN (2-term fp16: weights split, activations single)
    mm_gemm<2,1,2,2><<<dim3(2592, 1, 1), 256, SM3>>>(
        Hh + H_H1F, nullptr, Hh + H_W1TH, Hh + H_W1TL, nullptr, Hh + H_MID,
        fb1, nullptr, nullptr, nullptr, B_ * N_, E2, E_, 72, 36, 0, 0, 0);
    mm_gemm<2,1,3,0><<<dim3(1296, 1, 1), 256, SM3>>>(
        Hh + H_MID, nullptr, Hh + H_W2TH, Hh + H_W2TL, ff, nullptr,
        fb2, nullptr, nullptr, nullptr, B_ * N_, E_, E2, 72, 18, 0, 0, 0);
    add_ln<<<B_ * C_, 256>>>(ff, h1, ln2g, ln2b, outp);
    maxpool_k<<<20736, 256>>>(outp, pool);
}

// round 15
// speedup vs baseline: 2.4350x; 1.1843x over previous
#include <cuda_runtime.h>
#include <cuda_bf16.h>
#include <cuda_fp16.h>
#include <cstdint>

#define B_  4
#define C_  2304
#define N_  2304
#define E_  2304
#define HW  48
#define PW  50
#define NH_ 4
#define K2  20736
#define E2  4608

// GEMM tiling: CTA 128x128x32, 8 warps (2m x 4n), warp tile 64x32
#define BM 128
#define BN 128
#define BK 32
#define TSTRIDE 40
#define TILE_BYTES (BM * TSTRIDE * 2)   // 10240
#define NSTAGE 3

// ---------------- PTX helpers ----------------
__device__ __forceinline__ uint32_t smem_u32(const void* p) {
    uint32_t a;
    asm("{ .reg .u64 t; cvta.to.shared.u64 t, %1; cvt.u32.u64 %0, t; }" : "=r"(a) : "l"(p));
    return a;
}
__device__ __forceinline__ void cp16(uint32_t dst, const void* src) {
    asm volatile("cp.async.cg.shared.global [%0], [%1], 16;" :: "r"(dst), "l"(src));
}
__device__ __forceinline__ void cp_commit() { asm volatile("cp.async.commit_group;"); }
template<int NN>
__device__ __forceinline__ void cp_wait() { asm volatile("cp.async.wait_group %0;" :: "n"(NN)); }

__device__ __forceinline__ void ldm4(uint32_t& r0, uint32_t& r1, uint32_t& r2, uint32_t& r3, uint32_t a) {
    asm volatile("ldmatrix.sync.aligned.m8n8.x4.shared.b16 {%0,%1,%2,%3}, [%4];"
                 : "=r"(r0), "=r"(r1), "=r"(r2), "=r"(r3) : "r"(a));
}
__device__ __forceinline__ void mma_f16(float* d, uint32_t a0, uint32_t a1, uint32_t a2, uint32_t a3,
                                        uint32_t b0, uint32_t b1) {
    asm volatile("mma.sync.aligned.m16n8k16.row.col.f32.f16.f16.f32 "
                 "{%0,%1,%2,%3}, {%4,%5,%6,%7}, {%8,%9}, {%0,%1,%2,%3};"
                 : "+f"(d[0]), "+f"(d[1]), "+f"(d[2]), "+f"(d[3])
                 : "r"(a0), "r"(a1), "r"(a2), "r"(a3), "r"(b0), "r"(b1));
}

__device__ __forceinline__ uint32_t pk2h(__half a, __half b) {
    __half2 t(a, b);
    return *reinterpret_cast<uint32_t*>(&t);
}

// ---------------- scratch arenas (uint16 units) ----------------
constexpr size_t SZ_EN = (size_t)B_ * E_ * N_;
constexpr size_t SZ_W  = (size_t)E_ * E_;
constexpr size_t F_HP = 0, F_DOWN = 23040000;
constexpr size_t F_QK = F_DOWN + SZ_EN, F_AO = F_QK + SZ_EN, F_H1 = F_AO + SZ_EN;
constexpr size_t F_FF = F_H1 + SZ_EN;
constexpr size_t F_TOT = F_FF + SZ_EN;

constexpr size_t H_IM  = 0;                                  // fp16 im2col
constexpr size_t H_W2  = H_IM + (size_t)B_ * N_ * K2;        // fp16 W2 (reordered)
constexpr size_t H_QW  = H_W2 + (size_t)C_ * K2;
constexpr size_t H_KW  = H_QW + SZ_W;
constexpr size_t H_VW  = H_KW + SZ_W;
constexpr size_t H_W1T = H_VW + SZ_W;
constexpr size_t H_W2T = H_W1T + 2 * SZ_W;
constexpr size_t H_DT  = H_W2T + 2 * SZ_W;                   // fp16 down^T
constexpr size_t H_VT  = H_DT + SZ_EN;                       // fp16 v^T
constexpr size_t H_Q   = H_VT + SZ_EN;                       // fp16 q
constexpr size_t H_K   = H_Q + SZ_EN;                        // fp16 k
constexpr size_t H_AT  = H_K + SZ_EN;                        // fp16 attn
constexpr size_t H_H1F = H_AT + SZ_EN;                       // fp16 h1
constexpr size_t H_MID = H_H1F + SZ_EN;                      // fp16 mid
constexpr size_t H_TOT = H_MID + 2 * SZ_EN;

__device__ __align__(256) float    g_f32[F_TOT];
__device__ __align__(256) uint16_t g_b16[H_TOT];

// ---------------- GEMM (1-term fp16): D[m][n] = sum_k A[m,k]*B[n,k] ----------------
// EPI: 0 none, 1 +b1[row], 2 +b1[col]+relu, 3 +b1[col], 4 conv(+b1[r]+b2[r]+b3[r]*b4[z*N_+n], relu)
// OUTB: 0 fp32 C; 2 fp16 single (Oh)
template<int EPI, int OUTB>
__global__ void __launch_bounds__(256, 1) mm_gemm(
    const uint16_t* __restrict__ Ah,
    const uint16_t* __restrict__ Bh,
    float* __restrict__ C,
    uint16_t* __restrict__ Oh,
    const float* __restrict__ b1, const float* __restrict__ b2,
    const float* __restrict__ b3, const float* __restrict__ b4,
    int M, int N, int K, int tilesM, int tilesN,
    long long sA, long long sB, long long sC)
{
    constexpr int STB = 2 * TILE_BYTES;

    extern __shared__ char smem[];
    const uint32_t sb = smem_u32(smem);
    const int tid = threadIdx.x;
    const int wid = tid >> 5, lane = tid & 31;
    const int wm = wid >> 2, wn = wid & 3;
    const int z = blockIdx.z;

    int bid = blockIdx.x;
    const int GROUP = 8;
    int npg = GROUP * tilesN;
    int grp = bid / npg, rem = bid - grp * npg;
    int gs = tilesM - grp * GROUP; if (gs > GROUP) gs = GROUP;
    int mt = grp * GROUP + rem % gs;
    int nt = rem / gs;
    const int row0 = mt * BM, col0 = nt * BN;

    Ah += (size_t)z * sA;
    Bh += (size_t)z * sB;

    const int crow = tid >> 1;
    const int cbyte = (tid & 1) * 32;
    const uint32_t dst_off = (uint32_t)crow * (TSTRIDE * 2) + cbyte;

    auto prefetch = [&](int slab, int st) {
        const int k0 = slab * BK;
        uint32_t base = sb + st * STB + dst_off;
        const char* a0 = (const char*)(Ah + (size_t)(row0 + crow) * K + k0) + cbyte;
        cp16(base, a0); cp16(base + 16, a0 + 16);
        const char* b0 = (const char*)(Bh + (size_t)(col0 + crow) * K + k0) + cbyte;
        cp16(base + TILE_BYTES, b0); cp16(base + TILE_BYTES + 16, b0 + 16);
        cp_commit();
    };

    float acc[4][4][4];
    #pragma unroll
    for (int a = 0; a < 4; a++)
        #pragma unroll
        for (int b = 0; b < 4; b++)
            #pragma unroll
            for (int c = 0; c < 4; c++) acc[a][b][c] = 0.f;

    const int S = K / BK;
    prefetch(0, 0);
    prefetch(1, 1);
    cp_wait<1>();
    __syncthreads();

    const uint32_t a_row = (uint32_t)(wm * 64 + (lane & 15));
    const uint32_t a_kh  = (uint32_t)(lane >> 4) * 16;
    const uint32_t b_row = (uint32_t)(wn * 32 + (lane & 7) + ((lane >> 4) & 1) * 8);
    const uint32_t b_kh  = (uint32_t)((lane >> 3) & 1) * 16;

    for (int i = 0; i < S; i++) {
        const uint32_t st = sb + (i % NSTAGE) * STB;
        const uint32_t aH = st + a_row * (TSTRIDE * 2) + a_kh;
        const uint32_t bH = st + TILE_BYTES + b_row * (TSTRIDE * 2) + b_kh;

        #pragma unroll
        for (int ks = 0; ks < 2; ks++) {
            const uint32_t ko = ks * 32;
            uint32_t ah[4][4], bh2[2][4];
            #pragma unroll
            for (int mf = 0; mf < 4; mf++) {
                uint32_t adr = aH + ko + (uint32_t)mf * 16 * (TSTRIDE * 2);
                ldm4(ah[mf][0], ah[mf][1], ah[mf][2], ah[mf][3], adr);
            }
            #pragma unroll
            for (int p = 0; p < 2; p++) {
                uint32_t adr = bH + ko + (uint32_t)p * 16 * (TSTRIDE * 2);
                ldm4(bh2[p][0], bh2[p][1], bh2[p][2], bh2[p][3], adr);
            }
            #pragma unroll
            for (int mf = 0; mf < 4; mf++)
                #pragma unroll
                for (int nf = 0; nf < 4; nf++) {
                    const int p = nf >> 1, q = (nf & 1) * 2;
                    mma_f16(acc[mf][nf], ah[mf][0], ah[mf][1], ah[mf][2], ah[mf][3],
                            bh2[p][q], bh2[p][q + 1]);
                }
        }
        if (i + 2 < S) prefetch(i + 2, (i + 2) % NSTAGE);
        if (i + 1 < S) cp_wait<1>(); else cp_wait<0>();
        __syncthreads();
    }

    // epilogue
    #pragma unroll
    for (int mf = 0; mf < 4; mf++) {
        #pragma unroll
        for (int h = 0; h < 2; h++) {
            const int r = row0 + wm * 64 + mf * 16 + (lane >> 2) + h * 8;
            float rbias = 0.f, iw = 0.f;
            if (EPI == 1) rbias = b1[r];
            if (EPI == 4) { rbias = b1[r] + b2[r]; iw = b3[r]; }
            const float* xrow = (EPI == 4) ? (b4 + (size_t)z * N_) : nullptr;
            #pragma unroll
            for (int nf = 0; nf < 4; nf++) {
                const int cidx = col0 + wn * 32 + nf * 8 + (lane & 3) * 2;
                float2 o;
                o.x = acc[mf][nf][h * 2 + 0];
                o.y = acc[mf][nf][h * 2 + 1];
                if (EPI == 1) { o.x += rbias; o.y += rbias; }
                if (EPI == 2 || EPI == 3) {
                    float2 bc = *(const float2*)(b1 + cidx);
                    o.x += bc.x; o.y += bc.y;
                }
                if (EPI == 4) {
                    float2 xv = *(const float2*)(xrow + cidx);
                    o.x += rbias + iw * xv.x; o.y += rbias + iw * xv.y;
                }
                if (EPI == 2 || EPI == 4) { o.x = fmaxf(o.x, 0.f); o.y = fmaxf(o.y, 0.f); }
                size_t off = (size_t)z * sC + (size_t)r * N + cidx;
                if (OUTB == 0) {
                    *(float2*)(C + off) = o;
                } else {
                    *(uint32_t*)(Oh + off) = pk2h(__float2half(o.x), __float2half(o.y));
                }
            }
        }
    }
}

// ---------------- conv1 (3x3, 1->C) + ReLU, zero-padded ----------------
__global__ void conv1_relu_pad(const float* __restrict__ x, const float* __restrict__ w,
                               const float* __restrict__ bia, float* __restrict__ hp) {
    int idx = blockIdx.x * 256 + threadIdx.x;
    int b = idx / (C_ * PW * PW);
    int rem = idx - b * (C_ * PW * PW);
    int c = rem / (PW * PW);
    int p = rem - c * (PW * PW);
    int yy = p / PW, xx = p - yy * PW;
    float out = 0.f;
    if (yy >= 1 && yy <= HW && xx >= 1 && xx <= HW) {
        int y = yy - 1, x0 = xx - 1;
        float acc = bia[c];
        const float* xb = x + b * HW * HW;
        #pragma unroll
        for (int ky = 0; ky < 3; ky++) {
            int iy = y + ky - 1;
            if (iy < 0 || iy >= HW) continue;
            #pragma unroll
            for (int kx = 0; kx < 3; kx++) {
                int ix = x0 + kx - 1;
                if (ix < 0 || ix >= HW) continue;
                acc += w[c * 9 + ky * 3 + kx] * xb[iy * HW + ix];
            }
        }
        out = fmaxf(acc, 0.f);
    }
    hp[idx] = out;
}

// ---------------- im2col^T, fp16 ----------------
__global__ void im2col_f16(const float* __restrict__ hp, uint16_t* __restrict__ bb) {
    __shared__ float s[64][33];
    int t = threadIdx.x;
    int ic0 = blockIdx.x * 64, n0 = blockIdx.y * 32;
    int zo = blockIdx.z, z = zo / 9, off = zo - z * 9;
    int ky = off / 3, kx = off - ky * 3;
    const float* hpz = hp + (size_t)z * C_ * (PW * PW);
    #pragma unroll
    for (int p = 0; p < 2; p++) {
        int icl = p * 32 + (t >> 3);
        int nl = (t & 7) * 4;
        const float* base = hpz + (size_t)(ic0 + icl) * (PW * PW) + ky * PW + kx;
        #pragma unroll
        for (int i = 0; i < 4; i++) {
            int n = n0 + nl + i;
            int y = n / HW, xx = n - y * HW;
            s[icl][nl + i] = base[y * PW + xx];
        }
    }
    __syncthreads();
    int n = t >> 3, icc = (t & 7) * 8;
    size_t o = (size_t)z * ((size_t)N_ * K2) + (size_t)(n0 + n) * K2 + (size_t)off * C_ + ic0 + icc;
    uint4 u;
    u.x = pk2h(__float2half(s[icc + 0][n]), __float2half(s[icc + 1][n]));
    u.y = pk2h(__float2half(s[icc + 2][n]), __float2half(s[icc + 3][n]));
    u.z = pk2h(__float2half(s[icc + 4][n]), __float2half(s[icc + 5][n]));
    u.w = pk2h(__float2half(s[icc + 6][n]), __float2half(s[icc + 7][n]));
    *(uint4*)(bb + o) = u;
}

// ---------------- W2 reorder -> fp16 ----------------
__global__ void reorder_w2_f16(const float* __restrict__ w2, uint16_t* __restrict__ ow) {
    int id = blockIdx.x * 256 + threadIdx.x;
    int c = id / (9 * 288);
    int rem = id - c * (9 * 288);
    int off = rem / 288, icb = rem - off * 288;
    const float* src = w2 + (size_t)c * K2 + (size_t)icb * 72 + off;
    size_t o = (size_t)c * K2 + (size_t)off * C_ + (size_t)icb * 8;
    uint4 u;
    u.x = pk2h(__float2half(src[0]),  __float2half(src[9]));
    u.y = pk2h(__float2half(src[18]), __float2half(src[27]));
    u.z = pk2h(__float2half(src[36]), __float2half(src[45]));
    u.w = pk2h(__float2half(src[54]), __float2half(src[63]));
    *(uint4*)(ow + o) = u;
}

// ---------------- plain fp32 -> fp16 convert ----------------
__global__ void conv_plain_f16(const float* __restrict__ src, uint16_t* __restrict__ ow) {
    size_t i4 = (size_t)blockIdx.x * 256 + threadIdx.x;
    float4 v = *(const float4*)(src + i4 * 4);
    uint2 u;
    u.x = pk2h(__float2half(v.x), __float2half(v.y));
    u.y = pk2h(__float2half(v.z), __float2half(v.w));
    *(uint2*)(ow + i4 * 4) = u;
}

// ---------------- transpose -> fp16 ----------------
__global__ void transpose_f16(const float* __restrict__ in, uint16_t* __restrict__ ot,
                              int R, int Cc) {
    __shared__ float s[64][33];
    int t = threadIdx.x;
    int c0 = blockIdx.x * 32, r0 = blockIdx.y * 64;
    size_t zb = (size_t)blockIdx.z * R * Cc;
    {
        int r = t >> 2, cl = (t & 3) * 8;
        const float* src = in + zb + (size_t)(r0 + r) * Cc + c0 + cl;
        float4 a = *(const float4*)src;
        float4 b = *(const float4*)(src + 4);
        s[r][cl + 0] = a.x; s[r][cl + 1] = a.y; s[r][cl + 2] = a.z; s[r][cl + 3] = a.w;
        s[r][cl + 4] = b.x; s[r][cl + 5] = b.y; s[r][cl + 6] = b.z; s[r][cl + 7] = b.w;
    }
    __syncthreads();
    int c = t >> 3, rl = (t & 7) * 8;
    size_t o = zb + (size_t)(c0 + c) * R + r0 + rl;
    uint4 u;
    u.x = pk2h(__float2half(s[rl + 0][c]), __float2half(s[rl + 1][c]));
    u.y = pk2h(__float2half(s[rl + 2][c]), __float2half(s[rl + 3][c]));
    u.z = pk2h(__float2half(s[rl + 4][c]), __float2half(s[rl + 5][c]));
    u.w = pk2h(__float2half(s[rl + 6][c]), __float2half(s[rl + 7][c]));
    *(uint4*)(ot + o) = u;
}

// ---------------- reductions ----------------
__device__ __forceinline__ float block_sum(float v, float* red) {
    int tid = threadIdx.x;
    red[tid] = v; __syncthreads();
    #pragma unroll
    for (int s = 128; s > 0; s >>= 1) { if (tid < s) red[tid] += red[tid + s]; __syncthreads(); }
    float r = red[0]; __syncthreads();
    return r;
}
__device__ __forceinline__ float block_max(float v, float* red) {
    int tid = threadIdx.x;
    red[tid] = v; __syncthreads();
    #pragma unroll
    for (int s = 128; s > 0; s >>= 1) { if (tid < s) red[tid] = fmaxf(red[tid], red[tid + s]); __syncthreads(); }
    float r = red[0]; __syncthreads();
    return r;
}

// ---------------- softmax with analytic rel-pos bias -> fp16 ----------------
__global__ void softmax_bias_f16(const float* __restrict__ qk, const float* __restrict__ rel,
                                 uint16_t* __restrict__ oh) {
    __shared__ float red[256];
    int row = blockIdx.x;
    int b = row / E_;
    int i = row - b * E_;
    int ci = i / HW, wi = i - ci * HW;
    const float* rp = qk + (size_t)row * E_;
    int tid = threadIdx.x;
    float v[9];
    float mx = -3.4e38f;
    #pragma unroll
    for (int r = 0; r < 9; r++) {
        int j = r * 256 + tid;
        int cj = j / HW, wj = j - cj * HW;
        int idx = (ci - cj + HW - 1) * (2 * HW - 1) + (wi - wj + HW - 1);
        v[r] = rp[j] * (1.0f / 48.0f) + rel[idx * NH_ + b];
        mx = fmaxf(mx, v[r]);
    }
    mx = block_max(mx, red);
    float s = 0.f;
    #pragma unroll
    for (int r = 0; r < 9; r++) { v[r] = __expf(v[r] - mx); s += v[r]; }
    s = block_sum(s, red);
    float inv = 1.f / s;
    #pragma unroll
    for (int r = 0; r < 9; r++) {
        int j = r * 256 + tid;
        __half h = __float2half(v[r] * inv);
        oh[(size_t)row * E_ + j] = *(uint16_t*)&h;
    }
}

// ---------------- shuffle + residual + LN1 -> fp32 + fp16 ----------------
__global__ void add_shuffle_ln(const float* __restrict__ ao, const float* __restrict__ down,
                               const float* __restrict__ g, const float* __restrict__ be,
                               float* __restrict__ h1, uint16_t* __restrict__ of16) {
    __shared__ float red[256];
    int m = blockIdx.x;
    int e = m >> 2, bs = m & 3;
    const float* ar = ao + ((size_t)bs * E_ + e) * N_;
    const float* dr = down + (size_t)m * N_;
    int tid = threadIdx.x;
    float v[9]; float s = 0.f;
    #pragma unroll
    for (int r = 0; r < 9; r++) { int j = r * 256 + tid; v[r] = ar[j] + dr[j]; s += v[r]; }
    float mean = block_sum(s, red) * (1.f / N_);
    float s2 = 0.f;
    #pragma unroll
    for (int r = 0; r < 9; r++) { float d = v[r] - mean; s2 += d * d; }
    float var = block_sum(s2, red) * (1.f / N_);
    float rstd = rsqrtf(var + 1e-5f);
    #pragma unroll
    for (int r = 0; r < 9; r++) {
        int j = r * 256 + tid;
        float o = (v[r] - mean) * rstd * g[j] + be[j];
        h1[(size_t)m * N_ + j] = o;
        __half hf = __float2half(o);
        of16[(size_t)m * N_ + j] = *(uint16_t*)&hf;
    }
}

// ---------------- residual + LN2 ----------------
__global__ void add_ln(const float* __restrict__ f, const float* __restrict__ h1,
                       const float* __restrict__ g, const float* __restrict__ be,
                       float* __restrict__ out) {
    __shared__ float red[256];
    int m = blockIdx.x;
    const float* fr = f + (size_t)m * N_;
    const float* hr = h1 + (size_t)m * N_;
    int tid = threadIdx.x;
    float v[9]; float s = 0.f;
    #pragma unroll
    for (int r = 0; r < 9; r++) { int j = r * 256 + tid; v[r] = fr[j] + hr[j]; s += v[r]; }
    float mean = block_sum(s, red) * (1.f / N_);
    float s2 = 0.f;
    #pragma unroll
    for (int r = 0; r < 9; r++) { float d = v[r] - mean; s2 += d * d; }
    float var = block_sum(s2, red) * (1.f / N_);
    float rstd = rsqrtf(var + 1e-5f);
    #pragma unroll
    for (int r = 0; r < 9; r++) {
        int j = r * 256 + tid;
        out[(size_t)m * N_ + j] = (v[r] - mean) * rstd * g[j] + be[j];
    }
}

// ---------------- maxpool 2x2 ----------------
__global__ void maxpool_k(const float* __restrict__ out, float* __restrict__ p) {
    int idx = blockIdx.x * 256 + threadIdx.x;
    int bc = idx / (24 * 24);
    int r = idx - bc * 576;
    int y = r / 24, x = r - y * 24;
    const float* o = out + (size_t)bc * N_ + (2 * y) * HW + 2 * x;
    p[idx] = fmaxf(fmaxf(o[0], o[1]), fmaxf(o[HW], o[HW + 1]));
}

// ---------------- launcher ----------------
extern "C" void kernel_launch(void* const* d_in, const int* in_sizes, int n_in,
                              void* d_out, int out_size) {
    const float* x    = (const float*)d_in[0];
    const float* c1w  = (const float*)d_in[1];
    const float* c1b  = (const float*)d_in[2];
    const float* c2w  = (const float*)d_in[3];
    const float* c2b  = (const float*)d_in[4];
    const float* idw  = (const float*)d_in[5];
    const float* idb  = (const float*)d_in[6];
    const float* qw   = (const float*)d_in[7];
    const float* qb   = (const float*)d_in[8];
    const float* kw   = (const float*)d_in[9];
    const float* kb   = (const float*)d_in[10];
    const float* vw   = (const float*)d_in[11];
    const float* vb   = (const float*)d_in[12];
    const float* rel  = (const float*)d_in[13];
    const float* ln1g = (const float*)d_in[14];
    const float* ln1b = (const float*)d_in[15];
    const float* ln2g = (const float*)d_in[16];
    const float* ln2b = (const float*)d_in[17];
    const float* fw1  = (const float*)d_in[18];
    const float* fb1  = (const float*)d_in[19];
    const float* fw2  = (const float*)d_in[20];
    const float* fb2  = (const float*)d_in[21];

    float* outp = (float*)d_out;
    float* pool = outp + (size_t)B_ * C_ * N_;

    float* F; uint16_t* Hh;
    cudaGetSymbolAddress((void**)&F, g_f32);
    cudaGetSymbolAddress((void**)&Hh, g_b16);

    float* hp = F + F_HP;   float* down = F + F_DOWN;
    float* qk = F + F_QK;   float* ao   = F + F_AO;
    float* h1 = F + F_H1;   float* ff   = F + F_FF;

    const int SM2 = NSTAGE * 2 * TILE_BYTES;   // 61440
    cudaFuncSetAttribute(mm_gemm<4,0>, cudaFuncAttributeMaxDynamicSharedMemorySize, SM2);
    cudaFuncSetAttribute(mm_gemm<1,2>, cudaFuncAttributeMaxDynamicSharedMemorySize, SM2);
    cudaFuncSetAttribute(mm_gemm<3,2>, cudaFuncAttributeMaxDynamicSharedMemorySize, SM2);
    cudaFuncSetAttribute(mm_gemm<0,0>, cudaFuncAttributeMaxDynamicSharedMemorySize, SM2);
    cudaFuncSetAttribute(mm_gemm<2,2>, cudaFuncAttributeMaxDynamicSharedMemorySize, SM2);
    cudaFuncSetAttribute(mm_gemm<3,0>, cudaFuncAttributeMaxDynamicSharedMemorySize, SM2);

    const long long EN = (long long)E_ * N_;
    const long long NK2 = (long long)N_ * K2;

    // weight prep (all single fp16)
    reorder_w2_f16<<<23328, 256>>>(c2w, Hh + H_W2);
    conv_plain_f16<<<5184, 256>>>(qw, Hh + H_QW);
    conv_plain_f16<<<5184, 256>>>(kw, Hh + H_KW);
    conv_plain_f16<<<5184, 256>>>(vw, Hh + H_VW);
    transpose_f16<<<dim3(144, 36, 1), 256>>>(fw1, Hh + H_W1T, E_, E2);
    transpose_f16<<<dim3(72, 72, 1), 256>>>(fw2, Hh + H_W2T, E2, E_);

    // conv block
    conv1_relu_pad<<<90000, 256>>>(x, c1w, c1b, hp);
    im2col_f16<<<dim3(36, 72, 36), 256>>>(hp, Hh + H_IM);
    mm_gemm<4,0><<<dim3(324, 1, 4), 256, SM2>>>(
        Hh + H_W2, Hh + H_IM, down, nullptr,
        c2b, idb, idw, x, C_, N_, K2, 18, 18, 0, NK2, EN);

    // qkv
    transpose_f16<<<dim3(72, 36, 4), 256>>>(down, Hh + H_DT, C_, N_);
    mm_gemm<1,2><<<dim3(324, 1, 4), 256, SM2>>>(
        Hh + H_QW, Hh + H_DT, nullptr, Hh + H_Q,
        qb, nullptr, nullptr, nullptr, E_, N_, C_, 18, 18, 0, EN, EN);
    mm_gemm<1,2><<<dim3(324, 1, 4), 256, SM2>>>(
        Hh + H_KW, Hh + H_DT, nullptr, Hh + H_K,
        kb, nullptr, nullptr, nullptr, E_, N_, C_, 18, 18, 0, EN, EN);
    mm_gemm<3,2><<<dim3(324, 1, 4), 256, SM2>>>(
        Hh + H_DT, Hh + H_VW, nullptr, Hh + H_VT,
        vb, nullptr, nullptr, nullptr, N_, E_, C_, 18, 18, EN, 0, EN);

    // attention
    mm_gemm<0,0><<<dim3(324, 1, 4), 256, SM2>>>(
        Hh + H_Q, Hh + H_K, qk, nullptr,
        nullptr, nullptr, nullptr, nullptr, E_, E_, N_, 18, 18, EN, EN, EN);
    softmax_bias_f16<<<B_ * E_, 256>>>(qk, rel, Hh + H_AT);
    mm_gemm<0,0><<<dim3(324, 1, 4), 256, SM2>>>(
        Hh + H_AT, Hh + H_VT, ao, nullptr,
        nullptr, nullptr, nullptr, nullptr, E_, N_, E_, 18, 18, EN, EN, EN);
    add_shuffle_ln<<<B_ * C_, 256>>>(ao, down, ln1g, ln1b, h1, Hh + H_H1F);

    // FFN
    mm_gemm<2,2><<<dim3(2592, 1, 1), 256, SM2>>>(
        Hh + H_H1F, Hh + H_W1T, nullptr, Hh + H_MID,
        fb1, nullptr, nullptr, nullptr, B_ * N_, E2, E_, 72, 36, 0, 0, 0);
    mm_gemm<3,0><<<dim3(1296, 1, 1), 256, SM2>>>(
        Hh + H_MID, Hh + H_W2T, ff, nullptr,
        fb2, nullptr, nullptr, nullptr, B_ * N_, E_, E2, 72, 18, 0, 0, 0);
    add_ln<<<B_ * C_, 256>>>(ff, h1, ln2g, ln2b, outp);
    maxpool_k<<<20736, 256>>>(outp, pool);
}